// round 12
// baseline (speedup 1.0000x reference)
#include <cuda_runtime.h>
#include <cuda_fp16.h>
#include <math.h>
#include <stdint.h>

// ---------------- problem constants ----------------
#define Bn   4
#define Sn   2048
#define Dn   2048
#define Hn   16
#define DHn  128
#define WINn 128
#define nWn  16
#define Mn   64
#define Cn   256
#define FFn  8192
#define EPSn 1e-6f
#define SCALEn 0.08838834764831843f   // 1/sqrt(128)

#define ROWS (Bn*Sn)                  // 8192
#define OUT_ELEMS  ((size_t)Bn*Sn*Dn)
#define MEM_ELEMS  ((size_t)Bn*Mn*Dn)
#define GM_ELEMS   ((size_t)Bn*Mn*Dn)
#define NCH  8                        // matt key chunks

// ---------------- fp32 scratch ----------------
__device__ float g_h1   [ROWS*Dn];
__device__ float g_lcp  [ROWS*Dn];
__device__ float g_h2   [ROWS*Dn];
__device__ float g_gate [ROWS*Dn];
__device__ float g_gmg  [ROWS*Dn];
__device__ float g_pool [Bn*Dn];
__device__ float g_state[Bn*Cn];
__device__ float g_sp   [Bn*Dn];
__device__ float g_bias [Bn*Dn];
__device__ float g_fused[ROWS*Dn];
__device__ float g_h    [ROWS*Dn];
__device__ float g_h4   [ROWS*Dn];
// matt split-K partials
__device__ float g_pm   [Bn*Hn*NCH*Mn];
__device__ float g_pl   [Bn*Hn*NCH*Mn];
__device__ float g_pacc [(size_t)Bn*Hn*NCH*Mn*DHn];

// ---------------- fp16 scratch ----------------
#define AD __device__ __align__(256)
AD __half c_h1  [(size_t)ROWS*Dn];
AD __half c_h2  [(size_t)ROWS*Dn];
AD __half c_gm  [GM_ELEMS];
AD __half c_qkv [(size_t)ROWS*3*Dn];
AD __half c_atto[(size_t)ROWS*Dn];
AD __half c_qg  [(size_t)ROWS*Dn];
AD __half c_kvq [3*GM_ELEMS];            // kg | vg | qm
AD __half c_km  [(size_t)ROWS*Dn];
AD __half c_vm  [(size_t)ROWS*Dn];
AD __half c_rd  [(size_t)ROWS*Dn];
AD __half c_f01 [(size_t)ROWS*2*Dn];     // [lcp | gmg] fp16, ld 4096
AD __half c_h4  [(size_t)ROWS*Dn];
AD __half c_ffa [(size_t)ROWS*FFn];
AD __half c_wr  [GM_ELEMS];
// transposed weights [N][K]
AD __half t_qkv [2][(size_t)3*Dn*Dn];    // hi/lo
AD __half t_qgmk[2][(size_t)2*Dn*Dn];    // [gq | mk] along N, hi/lo
AD __half t_lo  [(size_t)Dn*Dn];
AD __half t_gtmv[(size_t)2*Dn*Dn];       // [gate | mv] along N
AD __half t_go  [(size_t)Dn*Dn];
AD __half t_f01 [(size_t)Dn*2*Dn];       // [2048][4096]: fuse0 | fuse1 along K
AD __half t_gm3 [(size_t)3*Dn*Dn];       // gk | gv | mq
AD __half t_mo  [(size_t)Dn*Dn];
AD __half t_ff1 [(size_t)FFn*Dn];
AD __half t_ff2 [(size_t)Dn*FFn];

// ---------------- helpers ----------------
__device__ __forceinline__ float warpMax(float v){
    #pragma unroll
    for (int o=16;o;o>>=1) v = fmaxf(v, __shfl_xor_sync(0xffffffffu, v, o));
    return v;
}
__device__ __forceinline__ float warpSum(float v){
    #pragma unroll
    for (int o=16;o;o>>=1) v += __shfl_xor_sync(0xffffffffu, v, o);
    return v;
}
__device__ __forceinline__ float gelu_tanh(float v){
    const float c0 = 0.7978845608028654f;
    float t = tanhf(c0 * (v + 0.044715f * v * v * v));
    return 0.5f * v * (1.0f + t);
}
__device__ __forceinline__ uint32_t smem_u32(const void* p){
    uint32_t a;
    asm("{ .reg .u64 t; cvta.to.shared.u64 t, %1; cvt.u32.u64 %0, t; }" : "=r"(a) : "l"(p));
    return a;
}
__device__ __forceinline__ void cpa16(uint32_t d, const void* g){
    asm volatile("cp.async.cg.shared.global [%0], [%1], 16;" :: "r"(d), "l"(g));
}
__device__ __forceinline__ void cpa_commit(){ asm volatile("cp.async.commit_group;" ::: "memory"); }
template<int NN> __device__ __forceinline__ void cpa_wait(){
    asm volatile("cp.async.wait_group %0;" :: "n"(NN) : "memory");
}
__device__ __forceinline__ void ldm4(uint32_t* r, uint32_t addr){
    asm volatile("ldmatrix.sync.aligned.m8n8.x4.shared.b16 {%0,%1,%2,%3}, [%4];"
        : "=r"(r[0]),"=r"(r[1]),"=r"(r[2]),"=r"(r[3]) : "r"(addr));
}
__device__ __forceinline__ void mma_f16(float* c, const uint32_t* a, uint32_t b0, uint32_t b1){
    asm volatile("mma.sync.aligned.m16n8k16.row.col.f32.f16.f16.f32 "
        "{%0,%1,%2,%3}, {%4,%5,%6,%7}, {%8,%9}, {%0,%1,%2,%3};"
        : "+f"(c[0]),"+f"(c[1]),"+f"(c[2]),"+f"(c[3])
        : "r"(a[0]),"r"(a[1]),"r"(a[2]),"r"(a[3]), "r"(b0),"r"(b1));
}

// ---------------- tensor GEMM via mma.sync (BK=64; TM rows x 128 cols) ----------------
// seg: 0 normal | 1 kvq 3-way split | 2 dual-dest by 2048-col segment (epi / epiB)
#define TG_B_ARR 18432                  // 128 rows * 72 halfs * 2B
template<int P, int TM>
__global__ void __launch_bounds__(256, 2)
tgemm_kernel(const __half* __restrict__ Ahi,
             const __half* __restrict__ Bhi, const __half* __restrict__ Blo,
             float* __restrict__ C, int ldC, int K,
             int epi, const float* __restrict__ R1, const float* __restrict__ R2,
             __half* __restrict__ Hout, int seg,
             float* __restrict__ C2, __half* __restrict__ Hout2, int epiB, int ldH)
{
    constexpr int NARR = (P == 2) ? 3 : 2;
    constexpr int A_SZ = TM * 144;
    constexpr int STG  = A_SZ + (NARR - 1) * TG_B_ARR;
    constexpr int MT   = TM / 32;       // m16 tiles per warp
    extern __shared__ char smem[];
    uint32_t sb = smem_u32(smem);
    const int tid = threadIdx.x, lane = tid & 31, wid = tid >> 5;
    const int warpM = wid >> 2, warpN = wid & 3;
    const int rowBase = blockIdx.y * TM, colBase = blockIdx.x * 128;

    const __half* srcA = Ahi + (size_t)rowBase * K;
    const __half* srcB = Bhi + (size_t)colBase * K;
    const __half* srcL = (P == 2) ? Blo + (size_t)colBase * K : nullptr;

    auto prefetch = [&](int c, int s){
        size_t koff = (size_t)c * 64;
        uint32_t sbase = sb + s*STG;
        const __half* ga = srcA + koff;
        #pragma unroll
        for (int q = 0; q < TM/32; q++){
            int i = tid + q*256;
            int r = i >> 3, sg = i & 7;
            cpa16(sbase + r*144 + sg*16, ga + (size_t)r*K + sg*8);
        }
        const __half* gb = srcB + koff;
        #pragma unroll
        for (int q = 0; q < 4; q++){
            int i = tid + q*256;
            int r = i >> 3, sg = i & 7;
            cpa16(sbase + A_SZ + r*144 + sg*16, gb + (size_t)r*K + sg*8);
        }
        if (P == 2){
            const __half* gl = srcL + koff;
            #pragma unroll
            for (int q = 0; q < 4; q++){
                int i = tid + q*256;
                int r = i >> 3, sg = i & 7;
                cpa16(sbase + A_SZ + TG_B_ARR + r*144 + sg*16, gl + (size_t)r*K + sg*8);
            }
        }
    };

    const int lrow = lane & 15, lhalf = (lane >> 4) << 3;
    uint32_t aoff[MT], boff[2];
    #pragma unroll
    for (int mt = 0; mt < MT; mt++) aoff[mt] = (warpM*(TM/2) + mt*16 + lrow)*144 + lhalf*2;
    #pragma unroll
    for (int np = 0; np < 2; np++) boff[np] = A_SZ + (warpN*32 + np*16 + lrow)*144 + lhalf*2;

    float acc[MT][4][4];
    #pragma unroll
    for (int a=0;a<MT;a++)
        #pragma unroll
        for (int b=0;b<4;b++)
            #pragma unroll
            for (int q=0;q<4;q++) acc[a][b][q] = 0.f;

    auto compute = [&](uint32_t sA){
        #pragma unroll
        for (int ks = 0; ks < 4; ks++){
            const uint32_t kadd = ks * 32;
            uint32_t bh[2][4], bl[2][4];
            #pragma unroll
            for (int np = 0; np < 2; np++){
                uint32_t a = sA + boff[np] + kadd;
                ldm4(bh[np], a);
                if (P == 2) ldm4(bl[np], a + TG_B_ARR);
            }
            #pragma unroll
            for (int mg = 0; mg < MT/2; mg++){
                uint32_t ah[2][4];
                #pragma unroll
                for (int mt = 0; mt < 2; mt++)
                    ldm4(ah[mt], sA + aoff[mg*2+mt] + kadd);
                #pragma unroll
                for (int mt = 0; mt < 2; mt++)
                    #pragma unroll
                    for (int nt = 0; nt < 4; nt++){
                        int np = nt >> 1, hh = nt & 1;
                        mma_f16(acc[mg*2+mt][nt], ah[mt], bh[np][hh], bh[np][2+hh]);
                    }
                if (P == 2){
                    #pragma unroll
                    for (int mt = 0; mt < 2; mt++)
                        #pragma unroll
                        for (int nt = 0; nt < 4; nt++){
                            int np = nt >> 1, hh = nt & 1;
                            mma_f16(acc[mg*2+mt][nt], ah[mt], bl[np][hh], bl[np][2+hh]);
                        }
                }
            }
        }
    };

    const int nCh = K >> 6;
    if (P == 1){
        prefetch(0, 0); cpa_commit();
        prefetch(1, 1); cpa_commit();
        uint32_t sA = sb;
        int s2 = 2;
        for (int c = 0; c < nCh; c++){
            if (c + 1 < nCh) cpa_wait<1>(); else cpa_wait<0>();
            __syncthreads();
            if (c + 2 < nCh){ prefetch(c+2, s2); cpa_commit(); s2 = (s2 == 2) ? 0 : s2 + 1; }
            compute(sA);
            sA += STG;
            if (sA == sb + 3*STG) sA = sb;
        }
    } else {
        prefetch(0, 0); cpa_commit();
        for (int c = 0; c < nCh; c++){
            if (c + 1 < nCh){ prefetch(c+1, (c+1)&1); cpa_commit(); cpa_wait<1>(); }
            else            { cpa_wait<0>(); }
            __syncthreads();
            compute(sb + (c&1)*STG);
            __syncthreads();
        }
    }

    // epilogue
    #pragma unroll
    for (int mt = 0; mt < MT; mt++){
        #pragma unroll
        for (int nt = 0; nt < 4; nt++){
            int r0 = rowBase + warpM*(TM/2) + mt*16 + (lane >> 2);
            int col = colBase + warpN*32 + nt*8 + (lane & 3)*2;
            #pragma unroll
            for (int hh = 0; hh < 2; hh++){
                int row = r0 + hh*8;
                int cs = col >> 11, col2 = col & 2047;
                float v0 = acc[mt][nt][hh*2+0];
                float v1 = acc[mt][nt][hh*2+1];
                int e = epi;
                float* Cd = C; __half* Hd = Hout;
                size_t idx, hidx;
                if (seg == 0){
                    idx = (size_t)row * ldC + col;
                    hidx = (size_t)row * ldH + col;
                } else if (seg == 1){
                    idx = hidx = (size_t)cs * GM_ELEMS + (size_t)row * Dn + col2;
                } else {
                    idx = hidx = (size_t)row * 2048 + col2;
                    if (cs){ e = epiB; Cd = C2; Hd = Hout2; }
                }
                if      (e == 1){ v0 += R1[idx]; v1 += R1[idx+1]; }
                else if (e == 2){ v0 = 1.f/(1.f+expf(-v0)); v1 = 1.f/(1.f+expf(-v1)); }
                else if (e == 3){ v0 = R1[idx] + R2[idx]*v0; v1 = R1[idx+1] + R2[idx+1]*v1; }
                else if (e == 4){ v0 = gelu_tanh(v0); v1 = gelu_tanh(v1); }
                else if (e == 6){
                    size_t bidx = (size_t)(row >> 11) * ldC + col;
                    v0 += R1[bidx]; v1 += R1[bidx+1];
                }
                if (Cd) *(float2*)(Cd + idx) = make_float2(v0, v1);
                if (Hd) *(__half2*)(Hd + hidx) = __halves2half2(__float2half_rn(v0), __float2half_rn(v1));
            }
        }
    }
}

// ---------------- convert: fp32 -> fp16 ----------------
__global__ __launch_bounds__(256)
void conv_kernel(const float* __restrict__ in, __half* __restrict__ hi, size_t n)
{
    size_t i = ((size_t)blockIdx.x * 256 + threadIdx.x) * 4;
    if (i >= n) return;
    float4 v = *(const float4*)(in + i);
    __half2* ph = (__half2*)(hi + i);
    ph[0] = __halves2half2(__float2half_rn(v.x), __float2half_rn(v.y));
    ph[1] = __halves2half2(__float2half_rn(v.z), __float2half_rn(v.w));
}

// ---------------- weight transpose-convert (output stride ldo) ----------------
__global__ __launch_bounds__(256)
void wconv_kernel(const float* __restrict__ W, __half* __restrict__ hi,
                  __half* __restrict__ lo, int K, int N, int ldo)
{
    __shared__ float t[32][33];
    int n0 = blockIdx.x * 32, k0 = blockIdx.y * 32;
    int tx = threadIdx.x & 31, ty = threadIdx.x >> 5;
    #pragma unroll
    for (int r = ty; r < 32; r += 8)
        t[r][tx] = W[(size_t)(k0 + r) * N + n0 + tx];
    __syncthreads();
    #pragma unroll
    for (int r = ty; r < 32; r += 8){
        float v = t[tx][r];
        size_t o = (size_t)(n0 + r) * ldo + k0 + tx;
        __half h = __float2half_rn(v);
        hi[o] = h;
        if (lo) lo[o] = __float2half_rn(v - __half2float(h));
    }
}

// ---------------- rmsnorm ----------------
__global__ __launch_bounds__(256)
void rmsnorm_kernel(const float* __restrict__ in, const float* __restrict__ g,
                    float* __restrict__ out, __half* __restrict__ hi, int mode)
{
    __shared__ float red[256];
    int row = blockIdx.x, tid = threadIdx.x;
    const float* xr = in + (size_t)row * Dn;
    float4 xa = *(const float4*)(xr + tid*4);
    float4 xb = *(const float4*)(xr + 1024 + tid*4);
    float ss = xa.x*xa.x + xa.y*xa.y + xa.z*xa.z + xa.w*xa.w
             + xb.x*xb.x + xb.y*xb.y + xb.z*xb.z + xb.w*xb.w;
    red[tid] = ss; __syncthreads();
    for (int o=128;o;o>>=1){ if (tid < o) red[tid] += red[tid+o]; __syncthreads(); }
    float inv = rsqrtf(red[0] * (1.0f/Dn) + EPSn);
    float* orow = out + (size_t)row * Dn;
    #pragma unroll
    for (int half_ = 0; half_ < 2; half_++){
        float4 xv = half_ ? xb : xa;
        int d = half_*1024 + tid*4;
        float4 gv = *(const float4*)(g + d);
        float4 ov;
        ov.x = xv.x*inv*gv.x; ov.y = xv.y*inv*gv.y;
        ov.z = xv.z*inv*gv.z; ov.w = xv.w*inv*gv.w;
        if (mode){ ov.x += xv.x; ov.y += xv.y; ov.z += xv.z; ov.w += xv.w; }
        *(float4*)(orow + d) = ov;
        if (hi){
            __half2* ph = (__half2*)(hi + (size_t)row*Dn + d);
            ph[0] = __halves2half2(__float2half_rn(ov.x), __float2half_rn(ov.y));
            ph[1] = __halves2half2(__float2half_rn(ov.z), __float2half_rn(ov.w));
        }
    }
}

// ---------------- local window attention (fp16 smem, V transposed) ----------------
__global__ __launch_bounds__(256)
void latt_kernel(const __half* __restrict__ qkv, __half* __restrict__ out)
{
    extern __shared__ char smraw[];
    __half* Qh = (__half*)smraw;
    __half* Kh = Qh + 128*130;
    __half* VT = Kh + 128*130;
    float*  Ps = (float*)(VT + 128*130);
    __half2* Q2 = (__half2*)Qh;
    __half2* K2 = (__half2*)Kh;
    __half2* V2 = (__half2*)VT;

    int bid = blockIdx.x;
    int h = bid % Hn;
    int w = (bid / Hn) % nWn;
    int b = bid / (Hn * nWn);
    int tid = threadIdx.x, lane = tid & 31, wp = tid >> 5;

    size_t base = ((size_t)(b*Sn + w*WINn)) * (3*Dn) + (size_t)h * DHn;
    for (int i = tid; i < 128*64; i += 256){
        int r = i >> 6, dc = i & 63, d2 = dc*2;
        size_t gidx = base + (size_t)r * (3*Dn) + d2;
        __half2 q2 = *(const __half2*)(qkv + gidx);
        __half2 k2 = *(const __half2*)(qkv + gidx + Dn);
        __half2 v2 = *(const __half2*)(qkv + gidx + 2*Dn);
        Q2[r*65 + dc] = q2;
        K2[r*65 + dc] = k2;
        VT[d2*130 + r]     = __low2half(v2);
        VT[(d2+1)*130 + r] = __high2half(v2);
    }
    __syncthreads();

    for (int row = wp; row < 128; row += 8){
        float sc[4] = {0,0,0,0};
        for (int dd = 0; dd < 64; dd++){
            float2 q2 = __half22float2(Q2[row*65 + dd]);
            #pragma unroll
            for (int j=0;j<4;j++){
                float2 k2 = __half22float2(K2[(j*32+lane)*65 + dd]);
                sc[j] = fmaf(q2.x, k2.x, sc[j]);
                sc[j] = fmaf(q2.y, k2.y, sc[j]);
            }
        }
        #pragma unroll
        for (int j=0;j<4;j++) sc[j] *= SCALEn;
        float m = fmaxf(fmaxf(sc[0],sc[1]), fmaxf(sc[2],sc[3]));
        m = warpMax(m);
        float l = 0.f;
        #pragma unroll
        for (int j=0;j<4;j++){ sc[j] = expf(sc[j]-m); l += sc[j]; }
        l = warpSum(l);
        float inv = 1.f / l;
        #pragma unroll
        for (int j=0;j<4;j++) Ps[wp*128 + j*32 + lane] = sc[j]*inv;
        __syncwarp();
        float accv[4] = {0,0,0,0};
        for (int kk=0;kk<64;kk++){
            float p0 = Ps[wp*128 + 2*kk], p1 = Ps[wp*128 + 2*kk + 1];
            #pragma unroll
            for (int j=0;j<4;j++){
                float2 v2 = __half22float2(V2[(j*32+lane)*65 + kk]);
                accv[j] = fmaf(p0, v2.x, accv[j]);
                accv[j] = fmaf(p1, v2.y, accv[j]);
            }
        }
        size_t orow = ((size_t)(b*Sn + w*WINn + row)) * Dn + (size_t)h*DHn;
        #pragma unroll
        for (int j=0;j<4;j++) out[orow + j*32 + lane] = __float2half_rn(accv[j]);
        __syncwarp();
    }
}

// ---------------- global-memory read attention (fp16 smem, V transposed) ----------------
__global__ __launch_bounds__(256)
void gatt_kernel(const __half* __restrict__ qg, const __half* __restrict__ kg,
                 const __half* __restrict__ vg, __half* __restrict__ rd)
{
    extern __shared__ char smraw[];
    __half* Qh = (__half*)smraw;
    __half* Kh = Qh + 64*130;
    __half* VT = Kh + 64*130;
    float*  Ps = (float*)(VT + 128*66);
    __half2* Q2 = (__half2*)Qh;
    __half2* K2 = (__half2*)Kh;
    __half2* V2 = (__half2*)VT;

    int bid = blockIdx.x;
    int qt = bid % (Sn/64);
    int h  = (bid / (Sn/64)) % Hn;
    int b  = bid / ((Sn/64) * Hn);
    int tid = threadIdx.x, lane = tid & 31, wp = tid >> 5;
    int s0 = qt * 64;

    for (int i = tid; i < 64*64; i += 256){
        int r = i >> 6, dc = i & 63, d2 = dc*2;
        __half2 q2 = *(const __half2*)(qg + ((size_t)(b*Sn + s0 + r))*Dn + h*DHn + d2);
        size_t gidx = ((size_t)(b*Mn + r))*Dn + h*DHn + d2;
        __half2 k2 = *(const __half2*)(kg + gidx);
        __half2 v2 = *(const __half2*)(vg + gidx);
        Q2[r*65 + dc] = q2;
        K2[r*65 + dc] = k2;
        VT[d2*66 + r]     = __low2half(v2);
        VT[(d2+1)*66 + r] = __high2half(v2);
    }
    __syncthreads();

    for (int row = wp; row < 64; row += 8){
        float sc[2] = {0,0};
        for (int dd = 0; dd < 64; dd++){
            float2 q2 = __half22float2(Q2[row*65 + dd]);
            #pragma unroll
            for (int j=0;j<2;j++){
                float2 k2 = __half22float2(K2[(j*32+lane)*65 + dd]);
                sc[j] = fmaf(q2.x, k2.x, sc[j]);
                sc[j] = fmaf(q2.y, k2.y, sc[j]);
            }
        }
        sc[0] *= SCALEn; sc[1] *= SCALEn;
        float m = warpMax(fmaxf(sc[0], sc[1]));
        float l = 0.f;
        #pragma unroll
        for (int j=0;j<2;j++){ sc[j] = expf(sc[j]-m); l += sc[j]; }
        l = warpSum(l);
        float inv = 1.f/l;
        #pragma unroll
        for (int j=0;j<2;j++) Ps[wp*64 + j*32 + lane] = sc[j]*inv;
        __syncwarp();
        float accv[4] = {0,0,0,0};
        for (int kk=0;kk<32;kk++){
            float p0 = Ps[wp*64 + 2*kk], p1 = Ps[wp*64 + 2*kk + 1];
            #pragma unroll
            for (int j=0;j<4;j++){
                float2 v2 = __half22float2(V2[(j*32+lane)*33 + kk]);
                accv[j] = fmaf(p0, v2.x, accv[j]);
                accv[j] = fmaf(p1, v2.y, accv[j]);
            }
        }
        size_t orow = ((size_t)(b*Sn + s0 + row))*Dn + (size_t)h*DHn;
        #pragma unroll
        for (int j=0;j<4;j++) rd[orow + j*32 + lane] = __float2half_rn(accv[j]);
        __syncwarp();
    }
}

// ---------------- memory-write attention: split-K partials ----------------
__global__ __launch_bounds__(256)
void matt_part_kernel(const __half* __restrict__ qm, const __half* __restrict__ km,
                      const __half* __restrict__ vm,
                      float* __restrict__ pm, float* __restrict__ pl,
                      float* __restrict__ pacc)
{
    extern __shared__ char smraw[];
    __half* Qm = (__half*)smraw;
    __half* Kc = Qm + 64*130;
    __half* VT = Kc + 128*130;
    float*  Ps = (float*)(VT + 128*130);
    __half2* Q2 = (__half2*)Qm;
    __half2* K2 = (__half2*)Kc;
    __half2* V2 = (__half2*)VT;

    int bid = blockIdx.x;
    int ch = bid & (NCH-1);
    int hb = bid >> 3;
    int h = hb % Hn, b = hb / Hn;
    int tid = threadIdx.x, lane = tid & 31, wp = tid >> 5;

    for (int i = tid; i < 64*64; i += 256){
        int r = i >> 6, dc = i & 63;
        Q2[r*65 + dc] = *(const __half2*)(qm + ((size_t)(b*Mn + r))*Dn + h*DHn + dc*2);
    }

    float mrun[8], lrun[8], accv[8][4];
    #pragma unroll
    for (int rr=0;rr<8;rr++){
        mrun[rr] = -1e30f; lrun[rr] = 0.f;
        #pragma unroll
        for (int j=0;j<4;j++) accv[rr][j] = 0.f;
    }

    int cBeg = ch * (Sn / NCH);
    for (int c0 = cBeg; c0 < cBeg + Sn/NCH; c0 += 128){
        __syncthreads();
        for (int i = tid; i < 128*64; i += 256){
            int r = i >> 6, dc = i & 63, d2 = dc*2;
            size_t gidx = ((size_t)(b*Sn + c0 + r))*Dn + h*DHn + d2;
            __half2 k2 = *(const __half2*)(km + gidx);
            __half2 v2 = *(const __half2*)(vm + gidx);
            K2[r*65 + dc] = k2;
            VT[d2*130 + r]     = __low2half(v2);
            VT[(d2+1)*130 + r] = __high2half(v2);
        }
        __syncthreads();

        #pragma unroll 1
        for (int rr=0;rr<8;rr++){
            int row = wp*8 + rr;
            float sc[4] = {0,0,0,0};
            for (int dd = 0; dd < 64; dd++){
                float2 q2 = __half22float2(Q2[row*65 + dd]);
                #pragma unroll
                for (int j=0;j<4;j++){
                    float2 k2 = __half22float2(K2[(j*32+lane)*65 + dd]);
                    sc[j] = fmaf(q2.x, k2.x, sc[j]);
                    sc[j] = fmaf(q2.y, k2.y, sc[j]);
                }
            }
            #pragma unroll
            for (int j=0;j<4;j++) sc[j] *= SCALEn;
            float cm = fmaxf(fmaxf(sc[0],sc[1]), fmaxf(sc[2],sc[3]));
            cm = warpMax(cm);
            float mn = fmaxf(mrun[rr], cm);
            float corr = expf(mrun[rr] - mn);
            float ls = 0.f;
            #pragma unroll
            for (int j=0;j<4;j++){ sc[j] = expf(sc[j]-mn); ls += sc[j]; }
            ls = warpSum(ls);
            lrun[rr] = lrun[rr]*corr + ls;
            mrun[rr] = mn;
            #pragma unroll
            for (int j=0;j<4;j++) accv[rr][j] *= corr;
            #pragma unroll
            for (int j=0;j<4;j++) Ps[wp*128 + j*32 + lane] = sc[j];
            __syncwarp();
            for (int kk=0;kk<64;kk++){
                float p0 = Ps[wp*128 + 2*kk], p1 = Ps[wp*128 + 2*kk + 1];
                #pragma unroll
                for (int j=0;j<4;j++){
                    float2 v2 = __half22float2(V2[(j*32+lane)*65 + kk]);
                    accv[rr][j] = fmaf(p0, v2.x, accv[rr][j]);
                    accv[rr][j] = fmaf(p1, v2.y, accv[rr][j]);
                }
            }
            __syncwarp();
        }
    }

    #pragma unroll
    for (int rr=0;rr<8;rr++){
        int row = wp*8 + rr;
        size_t p = ((size_t)(b*Hn + h)*NCH + ch)*Mn + row;
        if (lane == 0){ pm[p] = mrun[rr]; pl[p] = lrun[rr]; }
        #pragma unroll
        for (int j=0;j<4;j++)
            pacc[p*DHn + j*32 + lane] = accv[rr][j];
    }
}

// ---------------- matt merge ----------------
__global__ __launch_bounds__(256)
void matt_merge_kernel(const float* __restrict__ pm, const float* __restrict__ pl,
                       const float* __restrict__ pacc, __half* __restrict__ wr)
{
    int b = blockIdx.x / Hn, h = blockIdx.x % Hn;
    int tid = threadIdx.x, lane = tid & 31, wp = tid >> 5;
    size_t pb = (size_t)(b*Hn + h)*NCH;

    #pragma unroll 1
    for (int rr=0;rr<8;rr++){
        int row = wp*8 + rr;
        float M = -1e30f;
        float mv[NCH], lv[NCH];
        #pragma unroll
        for (int ccc=0; ccc<NCH; ccc++){
            mv[ccc] = pm[(pb + ccc)*Mn + row];
            lv[ccc] = pl[(pb + ccc)*Mn + row];
            M = fmaxf(M, mv[ccc]);
        }
        float L = 0.f, w[NCH];
        #pragma unroll
        for (int ccc=0; ccc<NCH; ccc++){
            w[ccc] = expf(mv[ccc] - M);
            L += w[ccc]*lv[ccc];
        }
        float invL = 1.f/L;
        #pragma unroll
        for (int j=0;j<4;j++){
            int d = j*32 + lane;
            float s = 0.f;
            #pragma unroll
            for (int ccc=0; ccc<NCH; ccc++)
                s += w[ccc]*pacc[((pb + ccc)*Mn + row)*DHn + d];
            wr[((size_t)(b*Mn + row))*Dn + h*DHn + d] = __float2half_rn(s*invL);
        }
    }
}

// ---------------- small elementwise / reductions ----------------
__global__ __launch_bounds__(256)
void pooled_kernel(const float* __restrict__ gmg, float* __restrict__ pooled)
{
    int d = blockIdx.x*256 + threadIdx.x;
    int b = blockIdx.y;
    const float* p = gmg + (size_t)b*Sn*Dn + d;
    float s = 0.f;
    for (int i=0;i<Sn;i++) s += p[(size_t)i*Dn];
    pooled[b*Dn + d] = s * (1.0f/Sn);
}

__global__ __launch_bounds__(256)
void state_kernel(const float* __restrict__ pooled, const float* __restrict__ w_cz,
                  const float* __restrict__ w_cg, const float* __restrict__ cs,
                  float* __restrict__ state, float* __restrict__ out_state)
{
    int b = blockIdx.x, c = threadIdx.x;
    const float* pr = pooled + (size_t)b*Dn;
    float z = 0.f, gs = 0.f;
    for (int k=0;k<Dn;k++){
        float p = pr[k];
        z  = fmaf(p, w_cz[(size_t)k*Cn + c], z);
        gs = fmaf(p, w_cg[(size_t)k*Cn + c], gs);
    }
    float zt = tanhf(z);
    float gc = 1.f / (1.f + expf(-gs));
    float ns = gc * cs[b*Cn + c] + (1.f - gc) * zt;
    state[b*Cn + c] = ns;
    out_state[b*Cn + c] = ns;
}

__global__ __launch_bounds__(256)
void sp_kernel(const float* __restrict__ state, const float* __restrict__ w_sp,
               float* __restrict__ sp)
{
    int d = blockIdx.x*256 + threadIdx.x;
    int b = blockIdx.y;
    float s = 0.f;
    for (int c=0;c<Cn;c++) s = fmaf(state[b*Cn+c], w_sp[(size_t)c*Dn + d], s);
    sp[b*Dn + d] = s;
}

__global__ __launch_bounds__(256)
void spbias_kernel(const float* __restrict__ sp, const float* __restrict__ wf2,
                   float* __restrict__ bias)
{
    int n = blockIdx.x*256 + threadIdx.x;
    int b = blockIdx.y;
    const float* sr = sp + (size_t)b*Dn;
    float s = 0.f;
    for (int k=0;k<Dn;k++) s = fmaf(sr[k], wf2[(size_t)k*Dn + n], s);
    bias[b*Dn + n] = s;
}

// ---------------- host orchestration ----------------
#define TG1_128_SMEM (3*(128*144 + TG_B_ARR))      // 110592
#define TG1_64_SMEM  (3*(64*144 + TG_B_ARR))       // 82944
#define TG2_128_SMEM (2*(128*144 + 2*TG_B_ARR))    // 110592

struct GArgs {
    float* C = nullptr; const float* R1 = nullptr; const float* R2 = nullptr;
    __half* Hout = nullptr; int seg = 0;
    float* C2 = nullptr; __half* Hout2 = nullptr; int epiB = 0; int ldH = 0;
};

static void tg1_128(const __half* A, const __half* W, int Mr, int Nc, int ldC, int K, int epi, GArgs a){
    if (!a.ldH) a.ldH = ldC;
    tgemm_kernel<1,128><<<dim3(Nc/128, Mr/128), 256, TG1_128_SMEM>>>(A, W, nullptr, a.C, ldC, K, epi, a.R1, a.R2, a.Hout, a.seg, a.C2, a.Hout2, a.epiB, a.ldH);
}
static void tg1_64(const __half* A, const __half* W, int Mr, int Nc, int ldC, int K, int epi, GArgs a){
    if (!a.ldH) a.ldH = ldC;
    tgemm_kernel<1,64><<<dim3(Nc/128, Mr/64), 256, TG1_64_SMEM>>>(A, W, nullptr, a.C, ldC, K, epi, a.R1, a.R2, a.Hout, a.seg, a.C2, a.Hout2, a.epiB, a.ldH);
}
static void tg2_128(const __half* A, const __half* Wh, const __half* Wl, int Mr, int Nc, int ldC, int K, int epi, GArgs a){
    if (!a.ldH) a.ldH = ldC;
    tgemm_kernel<2,128><<<dim3(Nc/128, Mr/128), 256, TG2_128_SMEM>>>(A, Wh, Wl, a.C, ldC, K, epi, a.R1, a.R2, a.Hout, a.seg, a.C2, a.Hout2, a.epiB, a.ldH);
}
static void conv(const float* in, __half* hi, size_t n){
    conv_kernel<<<(unsigned)((n+1023)/1024), 256>>>(in, hi, n);
}
static void wconv(const float* W, __half* hi, __half* lo, int K, int N, int ldo = 0){
    if (!ldo) ldo = K;
    wconv_kernel<<<dim3(N/32, K/32), 256>>>(W, hi, lo, K, N, ldo);
}

template <typename T>
static T* sym(const void* symbol){ void* p; cudaGetSymbolAddress(&p, symbol); return (T*)p; }

extern "C" void kernel_launch(void* const* d_in, const int* in_sizes, int n_in,
                              void* d_out, int out_size)
{
    (void)in_sizes; (void)n_in; (void)out_size;
    const float* x      = (const float*)d_in[0];
    const float* gmem   = (const float*)d_in[1];
    const float* cstate = (const float*)d_in[2];
    const float* g1     = (const float*)d_in[3];
    const float* g2     = (const float*)d_in[4];
    const float* g3     = (const float*)d_in[5];
    const float* g4     = (const float*)d_in[6];
    const float* w_qkv  = (const float*)d_in[7];
    const float* w_lo   = (const float*)d_in[8];
    const float* w_gq   = (const float*)d_in[9];
    const float* w_gk   = (const float*)d_in[10];
    const float* w_gv   = (const float*)d_in[11];
    const float* w_go   = (const float*)d_in[12];
    const float* w_gate = (const float*)d_in[13];
    const float* w_mq   = (const float*)d_in[14];
    const float* w_mk   = (const float*)d_in[15];
    const float* w_mv   = (const float*)d_in[16];
    const float* w_mo   = (const float*)d_in[17];
    const float* w_cz   = (const float*)d_in[18];
    const float* w_cg   = (const float*)d_in[19];
    const float* w_sp   = (const float*)d_in[20];
    const float* w_fuse = (const float*)d_in[21];
    const float* w_ff1  = (const float*)d_in[22];
    const float* w_ff2  = (const float*)d_in[23];
    float* out = (float*)d_out;

    float* h1    = sym<float>(g_h1);
    float* lcp   = sym<float>(g_lcp);
    float* h2    = sym<float>(g_h2);
    float* gate  = sym<float>(g_gate);
    float* gmgv  = sym<float>(g_gmg);
    float* pool  = sym<float>(g_pool);
    float* state = sym<float>(g_state);
    float* sp    = sym<float>(g_sp);
    float* bias  = sym<float>(g_bias);
    float* fused = sym<float>(g_fused);
    float* hv    = sym<float>(g_h);
    float* h4    = sym<float>(g_h4);
    float* pm    = sym<float>(g_pm);
    float* pl    = sym<float>(g_pl);
    float* pacc  = sym<float>(g_pacc);

    __half* ch1  = sym<__half>(c_h1);
    __half* ch2  = sym<__half>(c_h2);
    __half* cgm  = sym<__half>(c_gm);
    __half* cqkv = sym<__half>(c_qkv);
    __half* cat  = sym<__half>(c_atto);
    __half* cqg  = sym<__half>(c_qg);
    __half* ckvq = sym<__half>(c_kvq);
    __half* ckm  = sym<__half>(c_km);
    __half* cvm  = sym<__half>(c_vm);
    __half* crd  = sym<__half>(c_rd);
    __half* cf01 = sym<__half>(c_f01);
    __half* ch4  = sym<__half>(c_h4);
    __half* cffa = sym<__half>(c_ffa);
    __half* cwr  = sym<__half>(c_wr);
    __half* tqkv = sym<__half>(t_qkv);
    __half* tqm  = sym<__half>(t_qgmk);
    __half* tlo  = sym<__half>(t_lo);
    __half* tgv2 = sym<__half>(t_gtmv);
    __half* tgo  = sym<__half>(t_go);
    __half* tf01 = sym<__half>(t_f01);
    __half* tgm3 = sym<__half>(t_gm3);
    __half* tmo  = sym<__half>(t_mo);
    __half* tff1 = sym<__half>(t_ff1);
    __half* tff2 = sym<__half>(t_ff2);

    const size_t W1 = (size_t)Dn*Dn;
    const size_t WQ = (size_t)3*Dn*Dn;
    const size_t W2 = (size_t)2*Dn*Dn;

    const int LATT_SMEM = 3*128*130*2 + 8*128*4;
    const int GATT_SMEM = 2*64*130*2 + 128*66*2 + 8*64*4;
    const int MATT_SMEM = 64*130*2 + 2*128*130*2 + 8*128*4;
    cudaFuncSetAttribute(latt_kernel, cudaFuncAttributeMaxDynamicSharedMemorySize, LATT_SMEM);
    cudaFuncSetAttribute(gatt_kernel, cudaFuncAttributeMaxDynamicSharedMemorySize, GATT_SMEM);
    cudaFuncSetAttribute(matt_part_kernel, cudaFuncAttributeMaxDynamicSharedMemorySize, MATT_SMEM);
    cudaFuncSetAttribute(tgemm_kernel<1,128>, cudaFuncAttributeMaxDynamicSharedMemorySize, TG1_128_SMEM);
    cudaFuncSetAttribute(tgemm_kernel<1,64>,  cudaFuncAttributeMaxDynamicSharedMemorySize, TG1_64_SMEM);
    cudaFuncSetAttribute(tgemm_kernel<2,128>, cudaFuncAttributeMaxDynamicSharedMemorySize, TG2_128_SMEM);

    // ---- front: qkv path (launch #5 = TM=64 P1 tgemm) ----
    wconv(w_qkv, tqkv, tqkv + WQ, Dn, 3*Dn);                        // 0
    rmsnorm_kernel<<<ROWS, 256>>>(x, g1, h1, ch1, 0);               // 1
    wconv(w_lo,  tlo,  nullptr, Dn, Dn);                            // 2
    { GArgs a; a.Hout = cqkv; a.ldH = 3*Dn;
      tg2_128(ch1, tqkv, tqkv + WQ, ROWS, 3*Dn, 3*Dn, Dn, 0, a); }  // 3
    latt_kernel<<<Bn*nWn*Hn, 256, LATT_SMEM>>>(cqkv, cat);          // 4
    { GArgs a; a.C = lcp; a.R1 = x; a.Hout = cf01; a.ldH = 2*Dn;
      tg1_64(cat, tlo, ROWS, Dn, Dn, Dn, 1, a); }                   // 5 <- profiled

    // ---- remaining weight converts ----
    wconv(w_gq, tqm,      tqm + W2,      Dn, Dn);
    wconv(w_mk, tqm + W1, tqm + W2 + W1, Dn, Dn);
    wconv(w_gate, tgv2,      nullptr, Dn, Dn);
    wconv(w_mv,   tgv2 + W1, nullptr, Dn, Dn);
    wconv(w_go,   tgo,  nullptr, Dn, Dn);
    wconv(w_fuse,      tf01,      nullptr, Dn, Dn, 2*Dn);
    wconv(w_fuse + W1, tf01 + Dn, nullptr, Dn, Dn, 2*Dn);
    wconv(w_gk,   tgm3,          nullptr, Dn, Dn);
    wconv(w_gv,   tgm3 + W1,     nullptr, Dn, Dn);
    wconv(w_mq,   tgm3 + 2*W1,   nullptr, Dn, Dn);
    wconv(w_mo,   tmo,  nullptr, Dn, Dn);
    wconv(w_ff1,  tff1, nullptr, Dn, FFn);
    wconv(w_ff2,  tff2, nullptr, FFn, Dn);
    conv(gmem, cgm, GM_ELEMS);

    // 5) h2 = rmsnorm(lcp, g2)
    rmsnorm_kernel<<<ROWS, 256>>>(lcp, g2, h2, ch2, 0);
    // 6) qg+mk fused (P2, N=4096, dual fp16 dest) ; batched kg|vg|qm
    { GArgs a; a.seg = 2; a.Hout = cqg; a.Hout2 = ckm;
      tg2_128(ch2, tqm, tqm + W2, ROWS, 2*Dn, Dn, Dn, 0, a); }
    { GArgs a; a.seg = 1; a.Hout = ckvq;
      tg1_128(cgm, tgm3, Bn*Mn, 3*Dn, Dn, Dn, 0, a); }
    // 7) read attention
    gatt_kernel<<<Bn*Hn*(Sn/64), 256, GATT_SMEM>>>(cqg, ckvq, ckvq + GM_ELEMS, crd);
    // 8) gate+mv fused (P1, N=4096: sigmoid->fp32 gate | plain->fp16 cvm)
    { GArgs a; a.seg = 2; a.C = gate; a.Hout2 = cvm; a.epiB = 0;
      tg1_128(ch2, tgv2, ROWS, 2*Dn, Dn, Dn, 2, a); }
    // gmg = h2 + gate*(read@w_go)  (fp32 gmgv + fp16 into cf01 cols 2048..)
    { GArgs a; a.C = gmgv; a.R1 = h2; a.R2 = gate; a.Hout = cf01 + Dn; a.ldH = 2*Dn;
      tg1_64(crd, tgo, ROWS, Dn, Dn, Dn, 3, a); }
    // 10) memory-write attention: split-K + merge
    matt_part_kernel<<<Bn*Hn*NCH, 256, MATT_SMEM>>>(ckvq + 2*GM_ELEMS, ckm, cvm, pm, pl, pacc);
    matt_merge_kernel<<<Bn*Hn, 256>>>(pm, pl, pacc, cwr);
    // 11) new_memory
    { GArgs a; a.C = out + OUT_ELEMS; a.R1 = gmem;
      tg1_64(cwr, tmo, Bn*Mn, Dn, Dn, Dn, 1, a); }
    // 12) pooled / state / sp / bias
    pooled_kernel<<<dim3(Dn/256, Bn), 256>>>(gmgv, pool);
    state_kernel<<<Bn, Cn>>>(pool, w_cz, w_cg, cstate, state, out + OUT_ELEMS + MEM_ELEMS);
    sp_kernel<<<dim3(Dn/256, Bn), 256>>>(state, w_sp, sp);
    spbias_kernel<<<dim3(Dn/256, Bn), 256>>>(sp, w_fuse + (size_t)2*Dn*Dn, bias);
    // 13) fused = [lcp|gmg] @ [Wf0;Wf1] + bias  (single K=4096 GEMM)
    { GArgs a; a.C = fused; a.R1 = bias;
      tg1_64(cf01, tf01, ROWS, Dn, Dn, 2*Dn, 6, a); }
    // 14) h / h4
    rmsnorm_kernel<<<ROWS, 256>>>(fused, g3, hv, nullptr, 1);
    rmsnorm_kernel<<<ROWS, 256>>>(hv, g4, h4, ch4, 0);
    // 15) FFN
    { GArgs a; a.Hout = cffa; a.ldH = FFn;
      tg1_128(ch4, tff1, ROWS, FFn, FFn, Dn, 4, a); }
    { GArgs a; a.C = out; a.R1 = hv;
      tg1_64(cffa, tff2, ROWS, Dn, Dn, FFn, 1, a); }
}

// round 13
// speedup vs baseline: 1.0408x; 1.0408x over previous
#include <cuda_runtime.h>
#include <cuda_fp16.h>
#include <math.h>
#include <stdint.h>

// ---------------- problem constants ----------------
#define Bn   4
#define Sn   2048
#define Dn   2048
#define Hn   16
#define DHn  128
#define WINn 128
#define nWn  16
#define Mn   64
#define Cn   256
#define FFn  8192
#define EPSn 1e-6f
#define SCALEn 0.08838834764831843f   // 1/sqrt(128)

#define ROWS (Bn*Sn)                  // 8192
#define OUT_ELEMS  ((size_t)Bn*Sn*Dn)
#define MEM_ELEMS  ((size_t)Bn*Mn*Dn)
#define GM_ELEMS   ((size_t)Bn*Mn*Dn)
#define NCH  8                        // matt key chunks

// ---------------- fp32 scratch ----------------
__device__ float g_h1   [ROWS*Dn];
__device__ float g_lcp  [ROWS*Dn];
__device__ float g_h2   [ROWS*Dn];
__device__ float g_gate [ROWS*Dn];
__device__ float g_gmg  [ROWS*Dn];
__device__ float g_pool [Bn*Dn];
__device__ float g_state[Bn*Cn];
__device__ float g_sp   [Bn*Dn];
__device__ float g_bias [Bn*Dn];
__device__ float g_fused[ROWS*Dn];
__device__ float g_h    [ROWS*Dn];
__device__ float g_h4   [ROWS*Dn];
// matt split-K partials
__device__ float g_pm   [Bn*Hn*NCH*Mn];
__device__ float g_pl   [Bn*Hn*NCH*Mn];
__device__ float g_pacc [(size_t)Bn*Hn*NCH*Mn*DHn];

// ---------------- fp16 scratch ----------------
#define AD __device__ __align__(256)
AD __half c_h1  [(size_t)ROWS*Dn];
AD __half c_h2  [(size_t)ROWS*Dn];
AD __half c_gm  [GM_ELEMS];
AD __half c_qkv [(size_t)ROWS*3*Dn];
AD __half c_atto[(size_t)ROWS*Dn];
AD __half c_qg  [(size_t)ROWS*Dn];
AD __half c_kvq [3*GM_ELEMS];            // kg | vg | qm
AD __half c_km  [(size_t)ROWS*Dn];
AD __half c_vm  [(size_t)ROWS*Dn];
AD __half c_rd  [(size_t)ROWS*Dn];
AD __half c_f01 [(size_t)ROWS*2*Dn];     // [lcp | gmg] fp16, ld 4096
AD __half c_h4  [(size_t)ROWS*Dn];
AD __half c_ffa [(size_t)ROWS*FFn];
AD __half c_wr  [GM_ELEMS];
// transposed weights [N][K]
AD __half t_qkv [2][(size_t)3*Dn*Dn];    // hi/lo
AD __half t_qgmk[2][(size_t)2*Dn*Dn];    // [gq | mk] along N, hi/lo
AD __half t_lo  [(size_t)Dn*Dn];
AD __half t_gtmv[(size_t)2*Dn*Dn];       // [gate | mv] along N
AD __half t_go  [(size_t)Dn*Dn];
AD __half t_f01 [(size_t)Dn*2*Dn];       // [2048][4096]: fuse0 | fuse1 along K
AD __half t_gm3 [(size_t)3*Dn*Dn];       // gk | gv | mq
AD __half t_mo  [(size_t)Dn*Dn];
AD __half t_ff1 [(size_t)FFn*Dn];
AD __half t_ff2 [(size_t)Dn*FFn];

// ---------------- helpers ----------------
__device__ __forceinline__ float warpMax(float v){
    #pragma unroll
    for (int o=16;o;o>>=1) v = fmaxf(v, __shfl_xor_sync(0xffffffffu, v, o));
    return v;
}
__device__ __forceinline__ float warpSum(float v){
    #pragma unroll
    for (int o=16;o;o>>=1) v += __shfl_xor_sync(0xffffffffu, v, o);
    return v;
}
__device__ __forceinline__ float gelu_tanh(float v){
    const float c0 = 0.7978845608028654f;
    float t = tanhf(c0 * (v + 0.044715f * v * v * v));
    return 0.5f * v * (1.0f + t);
}
__device__ __forceinline__ uint32_t smem_u32(const void* p){
    uint32_t a;
    asm("{ .reg .u64 t; cvta.to.shared.u64 t, %1; cvt.u32.u64 %0, t; }" : "=r"(a) : "l"(p));
    return a;
}
__device__ __forceinline__ void cpa16(uint32_t d, const void* g){
    asm volatile("cp.async.cg.shared.global [%0], [%1], 16;" :: "r"(d), "l"(g));
}
__device__ __forceinline__ void cpa_commit(){ asm volatile("cp.async.commit_group;" ::: "memory"); }
template<int NN> __device__ __forceinline__ void cpa_wait(){
    asm volatile("cp.async.wait_group %0;" :: "n"(NN) : "memory");
}
__device__ __forceinline__ void ldm4(uint32_t* r, uint32_t addr){
    asm volatile("ldmatrix.sync.aligned.m8n8.x4.shared.b16 {%0,%1,%2,%3}, [%4];"
        : "=r"(r[0]),"=r"(r[1]),"=r"(r[2]),"=r"(r[3]) : "r"(addr));
}
__device__ __forceinline__ void mma_f16(float* c, const uint32_t* a, uint32_t b0, uint32_t b1){
    asm volatile("mma.sync.aligned.m16n8k16.row.col.f32.f16.f16.f32 "
        "{%0,%1,%2,%3}, {%4,%5,%6,%7}, {%8,%9}, {%0,%1,%2,%3};"
        : "+f"(c[0]),"+f"(c[1]),"+f"(c[2]),"+f"(c[3])
        : "r"(a[0]),"r"(a[1]),"r"(a[2]),"r"(a[3]), "r"(b0),"r"(b1));
}

// ---------------- tensor GEMM via mma.sync (BK=64; 128x128 tile) ----------------
// seg: 0 normal | 1 kvq 3-way split | 2 dual-dest by 2048-col segment (epi / epiB)
#define TG_B_ARR 18432                  // 128 rows * 72 halfs * 2B
template<int P>
__global__ void __launch_bounds__(256, 2)
tgemm_kernel(const __half* __restrict__ Ahi,
             const __half* __restrict__ Bhi, const __half* __restrict__ Blo,
             float* __restrict__ C, int ldC, int K,
             int epi, const float* __restrict__ R1, const float* __restrict__ R2,
             __half* __restrict__ Hout, int seg,
             float* __restrict__ C2, __half* __restrict__ Hout2, int epiB, int ldH)
{
    constexpr int NARR = (P == 2) ? 3 : 2;
    constexpr int STG  = NARR * TG_B_ARR;
    extern __shared__ char smem[];
    uint32_t sb = smem_u32(smem);
    const int tid = threadIdx.x, lane = tid & 31, wid = tid >> 5;
    const int warpM = wid >> 2, warpN = wid & 3;
    const int rowBase = blockIdx.y * 128, colBase = blockIdx.x * 128;

    const __half* src[NARR];
    src[0] = Ahi + (size_t)rowBase * K;
    src[1] = Bhi + (size_t)colBase * K;
    if (P == 2) src[2] = Blo + (size_t)colBase * K;

    auto prefetch = [&](int c, int s){
        size_t koff = (size_t)c * 64;
        #pragma unroll
        for (int t = 0; t < NARR; t++){
            const __half* gb = src[t] + koff;
            uint32_t sdst = sb + s*STG + t*TG_B_ARR;
            #pragma unroll
            for (int q = 0; q < 4; q++){
                int i = tid + q*256;
                int r = i >> 3, sg = i & 7;
                cpa16(sdst + r*144 + sg*16, gb + (size_t)r*K + sg*8);
            }
        }
    };

    const int lrow = lane & 15, lhalf = (lane >> 4) << 3;
    uint32_t aoff[4], boff[2];
    #pragma unroll
    for (int mt = 0; mt < 4; mt++) aoff[mt] = (warpM*64 + mt*16 + lrow)*144 + lhalf*2;
    #pragma unroll
    for (int np = 0; np < 2; np++) boff[np] = TG_B_ARR + (warpN*32 + np*16 + lrow)*144 + lhalf*2;

    float acc[4][4][4];
    #pragma unroll
    for (int a=0;a<4;a++)
        #pragma unroll
        for (int b=0;b<4;b++)
            #pragma unroll
            for (int q=0;q<4;q++) acc[a][b][q] = 0.f;

    auto compute = [&](uint32_t sA){
        #pragma unroll
        for (int ks = 0; ks < 4; ks++){
            const uint32_t kadd = ks * 32;
            uint32_t bh[2][4], bl[2][4];
            #pragma unroll
            for (int np = 0; np < 2; np++){
                uint32_t a = sA + boff[np] + kadd;
                ldm4(bh[np], a);
                if (P == 2) ldm4(bl[np], a + TG_B_ARR);
            }
            #pragma unroll
            for (int mh = 0; mh < 2; mh++){
                uint32_t ah[2][4];
                #pragma unroll
                for (int mt = 0; mt < 2; mt++)
                    ldm4(ah[mt], sA + aoff[mh*2+mt] + kadd);
                #pragma unroll
                for (int mt = 0; mt < 2; mt++)
                    #pragma unroll
                    for (int nt = 0; nt < 4; nt++){
                        int np = nt >> 1, hh = nt & 1;
                        mma_f16(acc[mh*2+mt][nt], ah[mt], bh[np][hh], bh[np][2+hh]);
                    }
                if (P == 2){
                    #pragma unroll
                    for (int mt = 0; mt < 2; mt++)
                        #pragma unroll
                        for (int nt = 0; nt < 4; nt++){
                            int np = nt >> 1, hh = nt & 1;
                            mma_f16(acc[mh*2+mt][nt], ah[mt], bl[np][hh], bl[np][2+hh]);
                        }
                }
            }
        }
    };

    const int nCh = K >> 6;
    if (P == 1){
        prefetch(0, 0); cpa_commit();
        prefetch(1, 1); cpa_commit();
        uint32_t sA = sb;
        int s2 = 2;
        for (int c = 0; c < nCh; c++){
            if (c + 1 < nCh) cpa_wait<1>(); else cpa_wait<0>();
            __syncthreads();
            if (c + 2 < nCh){ prefetch(c+2, s2); cpa_commit(); s2 = (s2 == 2) ? 0 : s2 + 1; }
            compute(sA);
            sA += STG;
            if (sA == sb + 3*STG) sA = sb;
        }
    } else {
        prefetch(0, 0); cpa_commit();
        for (int c = 0; c < nCh; c++){
            if (c + 1 < nCh){ prefetch(c+1, (c+1)&1); cpa_commit(); cpa_wait<1>(); }
            else            { cpa_wait<0>(); }
            __syncthreads();
            compute(sb + (c&1)*STG);
            __syncthreads();
        }
    }

    // epilogue
    #pragma unroll
    for (int mt = 0; mt < 4; mt++){
        #pragma unroll
        for (int nt = 0; nt < 4; nt++){
            int r0 = rowBase + warpM*64 + mt*16 + (lane >> 2);
            int col = colBase + warpN*32 + nt*8 + (lane & 3)*2;
            #pragma unroll
            for (int hh = 0; hh < 2; hh++){
                int row = r0 + hh*8;
                int cs = col >> 11, col2 = col & 2047;
                float v0 = acc[mt][nt][hh*2+0];
                float v1 = acc[mt][nt][hh*2+1];
                int e = epi;
                float* Cd = C; __half* Hd = Hout;
                size_t idx, hidx;
                if (seg == 0){
                    idx = (size_t)row * ldC + col;
                    hidx = (size_t)row * ldH + col;
                } else if (seg == 1){
                    idx = hidx = (size_t)cs * GM_ELEMS + (size_t)row * Dn + col2;
                } else {
                    idx = hidx = (size_t)row * 2048 + col2;
                    if (cs){ e = epiB; Cd = C2; Hd = Hout2; }
                }
                if      (e == 1){ v0 += R1[idx]; v1 += R1[idx+1]; }
                else if (e == 2){ v0 = 1.f/(1.f+expf(-v0)); v1 = 1.f/(1.f+expf(-v1)); }
                else if (e == 3){ v0 = R1[idx] + R2[idx]*v0; v1 = R1[idx+1] + R2[idx+1]*v1; }
                else if (e == 4){ v0 = gelu_tanh(v0); v1 = gelu_tanh(v1); }
                else if (e == 6){
                    size_t bidx = (size_t)(row >> 11) * ldC + col;
                    v0 += R1[bidx]; v1 += R1[bidx+1];
                }
                if (Cd) *(float2*)(Cd + idx) = make_float2(v0, v1);
                if (Hd) *(__half2*)(Hd + hidx) = __halves2half2(__float2half_rn(v0), __float2half_rn(v1));
            }
        }
    }
}

// ---------------- convert: fp32 -> fp16 ----------------
__global__ __launch_bounds__(256)
void conv_kernel(const float* __restrict__ in, __half* __restrict__ hi, size_t n)
{
    size_t i = ((size_t)blockIdx.x * 256 + threadIdx.x) * 4;
    if (i >= n) return;
    float4 v = *(const float4*)(in + i);
    __half2* ph = (__half2*)(hi + i);
    ph[0] = __halves2half2(__float2half_rn(v.x), __float2half_rn(v.y));
    ph[1] = __halves2half2(__float2half_rn(v.z), __float2half_rn(v.w));
}

// ---------------- weight transpose-convert (output stride ldo) ----------------
__global__ __launch_bounds__(256)
void wconv_kernel(const float* __restrict__ W, __half* __restrict__ hi,
                  __half* __restrict__ lo, int K, int N, int ldo)
{
    __shared__ float t[32][33];
    int n0 = blockIdx.x * 32, k0 = blockIdx.y * 32;
    int tx = threadIdx.x & 31, ty = threadIdx.x >> 5;
    #pragma unroll
    for (int r = ty; r < 32; r += 8)
        t[r][tx] = W[(size_t)(k0 + r) * N + n0 + tx];
    __syncthreads();
    #pragma unroll
    for (int r = ty; r < 32; r += 8){
        float v = t[tx][r];
        size_t o = (size_t)(n0 + r) * ldo + k0 + tx;
        __half h = __float2half_rn(v);
        hi[o] = h;
        if (lo) lo[o] = __float2half_rn(v - __half2float(h));
    }
}

// ---------------- rmsnorm ----------------
__global__ __launch_bounds__(256)
void rmsnorm_kernel(const float* __restrict__ in, const float* __restrict__ g,
                    float* __restrict__ out, __half* __restrict__ hi, int mode)
{
    __shared__ float red[256];
    int row = blockIdx.x, tid = threadIdx.x;
    const float* xr = in + (size_t)row * Dn;
    float4 xa = *(const float4*)(xr + tid*4);
    float4 xb = *(const float4*)(xr + 1024 + tid*4);
    float ss = xa.x*xa.x + xa.y*xa.y + xa.z*xa.z + xa.w*xa.w
             + xb.x*xb.x + xb.y*xb.y + xb.z*xb.z + xb.w*xb.w;
    red[tid] = ss; __syncthreads();
    for (int o=128;o;o>>=1){ if (tid < o) red[tid] += red[tid+o]; __syncthreads(); }
    float inv = rsqrtf(red[0] * (1.0f/Dn) + EPSn);
    float* orow = out + (size_t)row * Dn;
    #pragma unroll
    for (int half_ = 0; half_ < 2; half_++){
        float4 xv = half_ ? xb : xa;
        int d = half_*1024 + tid*4;
        float4 gv = *(const float4*)(g + d);
        float4 ov;
        ov.x = xv.x*inv*gv.x; ov.y = xv.y*inv*gv.y;
        ov.z = xv.z*inv*gv.z; ov.w = xv.w*inv*gv.w;
        if (mode){ ov.x += xv.x; ov.y += xv.y; ov.z += xv.z; ov.w += xv.w; }
        *(float4*)(orow + d) = ov;
        if (hi){
            __half2* ph = (__half2*)(hi + (size_t)row*Dn + d);
            ph[0] = __halves2half2(__float2half_rn(ov.x), __float2half_rn(ov.y));
            ph[1] = __halves2half2(__float2half_rn(ov.z), __float2half_rn(ov.w));
        }
    }
}

// ---------------- local window attention (fp16 smem, V transposed) ----------------
__global__ __launch_bounds__(256)
void latt_kernel(const __half* __restrict__ qkv, __half* __restrict__ out)
{
    extern __shared__ char smraw[];
    __half* Qh = (__half*)smraw;
    __half* Kh = Qh + 128*130;
    __half* VT = Kh + 128*130;
    float*  Ps = (float*)(VT + 128*130);
    __half2* Q2 = (__half2*)Qh;
    __half2* K2 = (__half2*)Kh;
    __half2* V2 = (__half2*)VT;

    int bid = blockIdx.x;
    int h = bid % Hn;
    int w = (bid / Hn) % nWn;
    int b = bid / (Hn * nWn);
    int tid = threadIdx.x, lane = tid & 31, wp = tid >> 5;

    size_t base = ((size_t)(b*Sn + w*WINn)) * (3*Dn) + (size_t)h * DHn;
    for (int i = tid; i < 128*64; i += 256){
        int r = i >> 6, dc = i & 63, d2 = dc*2;
        size_t gidx = base + (size_t)r * (3*Dn) + d2;
        __half2 q2 = *(const __half2*)(qkv + gidx);
        __half2 k2 = *(const __half2*)(qkv + gidx + Dn);
        __half2 v2 = *(const __half2*)(qkv + gidx + 2*Dn);
        Q2[r*65 + dc] = q2;
        K2[r*65 + dc] = k2;
        VT[d2*130 + r]     = __low2half(v2);
        VT[(d2+1)*130 + r] = __high2half(v2);
    }
    __syncthreads();

    for (int row = wp; row < 128; row += 8){
        float sc[4] = {0,0,0,0};
        for (int dd = 0; dd < 64; dd++){
            float2 q2 = __half22float2(Q2[row*65 + dd]);
            #pragma unroll
            for (int j=0;j<4;j++){
                float2 k2 = __half22float2(K2[(j*32+lane)*65 + dd]);
                sc[j] = fmaf(q2.x, k2.x, sc[j]);
                sc[j] = fmaf(q2.y, k2.y, sc[j]);
            }
        }
        #pragma unroll
        for (int j=0;j<4;j++) sc[j] *= SCALEn;
        float m = fmaxf(fmaxf(sc[0],sc[1]), fmaxf(sc[2],sc[3]));
        m = warpMax(m);
        float l = 0.f;
        #pragma unroll
        for (int j=0;j<4;j++){ sc[j] = expf(sc[j]-m); l += sc[j]; }
        l = warpSum(l);
        float inv = 1.f / l;
        #pragma unroll
        for (int j=0;j<4;j++) Ps[wp*128 + j*32 + lane] = sc[j]*inv;
        __syncwarp();
        float accv[4] = {0,0,0,0};
        for (int kk=0;kk<64;kk++){
            float p0 = Ps[wp*128 + 2*kk], p1 = Ps[wp*128 + 2*kk + 1];
            #pragma unroll
            for (int j=0;j<4;j++){
                float2 v2 = __half22float2(V2[(j*32+lane)*65 + kk]);
                accv[j] = fmaf(p0, v2.x, accv[j]);
                accv[j] = fmaf(p1, v2.y, accv[j]);
            }
        }
        size_t orow = ((size_t)(b*Sn + w*WINn + row)) * Dn + (size_t)h*DHn;
        #pragma unroll
        for (int j=0;j<4;j++) out[orow + j*32 + lane] = __float2half_rn(accv[j]);
        __syncwarp();
    }
}

// ---------------- global-memory read attention (fp16 smem, V transposed) ----------------
__global__ __launch_bounds__(256)
void gatt_kernel(const __half* __restrict__ qg, const __half* __restrict__ kg,
                 const __half* __restrict__ vg, __half* __restrict__ rd)
{
    extern __shared__ char smraw[];
    __half* Qh = (__half*)smraw;
    __half* Kh = Qh + 64*130;
    __half* VT = Kh + 64*130;
    float*  Ps = (float*)(VT + 128*66);
    __half2* Q2 = (__half2*)Qh;
    __half2* K2 = (__half2*)Kh;
    __half2* V2 = (__half2*)VT;

    int bid = blockIdx.x;
    int qt = bid % (Sn/64);
    int h  = (bid / (Sn/64)) % Hn;
    int b  = bid / ((Sn/64) * Hn);
    int tid = threadIdx.x, lane = tid & 31, wp = tid >> 5;
    int s0 = qt * 64;

    for (int i = tid; i < 64*64; i += 256){
        int r = i >> 6, dc = i & 63, d2 = dc*2;
        __half2 q2 = *(const __half2*)(qg + ((size_t)(b*Sn + s0 + r))*Dn + h*DHn + d2);
        size_t gidx = ((size_t)(b*Mn + r))*Dn + h*DHn + d2;
        __half2 k2 = *(const __half2*)(kg + gidx);
        __half2 v2 = *(const __half2*)(vg + gidx);
        Q2[r*65 + dc] = q2;
        K2[r*65 + dc] = k2;
        VT[d2*66 + r]     = __low2half(v2);
        VT[(d2+1)*66 + r] = __high2half(v2);
    }
    __syncthreads();

    for (int row = wp; row < 64; row += 8){
        float sc[2] = {0,0};
        for (int dd = 0; dd < 64; dd++){
            float2 q2 = __half22float2(Q2[row*65 + dd]);
            #pragma unroll
            for (int j=0;j<2;j++){
                float2 k2 = __half22float2(K2[(j*32+lane)*65 + dd]);
                sc[j] = fmaf(q2.x, k2.x, sc[j]);
                sc[j] = fmaf(q2.y, k2.y, sc[j]);
            }
        }
        sc[0] *= SCALEn; sc[1] *= SCALEn;
        float m = warpMax(fmaxf(sc[0], sc[1]));
        float l = 0.f;
        #pragma unroll
        for (int j=0;j<2;j++){ sc[j] = expf(sc[j]-m); l += sc[j]; }
        l = warpSum(l);
        float inv = 1.f/l;
        #pragma unroll
        for (int j=0;j<2;j++) Ps[wp*64 + j*32 + lane] = sc[j]*inv;
        __syncwarp();
        float accv[4] = {0,0,0,0};
        for (int kk=0;kk<32;kk++){
            float p0 = Ps[wp*64 + 2*kk], p1 = Ps[wp*64 + 2*kk + 1];
            #pragma unroll
            for (int j=0;j<4;j++){
                float2 v2 = __half22float2(V2[(j*32+lane)*33 + kk]);
                accv[j] = fmaf(p0, v2.x, accv[j]);
                accv[j] = fmaf(p1, v2.y, accv[j]);
            }
        }
        size_t orow = ((size_t)(b*Sn + s0 + row))*Dn + (size_t)h*DHn;
        #pragma unroll
        for (int j=0;j<4;j++) rd[orow + j*32 + lane] = __float2half_rn(accv[j]);
        __syncwarp();
    }
}

// ---------------- memory-write attention: split-K partials ----------------
__global__ __launch_bounds__(256)
void matt_part_kernel(const __half* __restrict__ qm, const __half* __restrict__ km,
                      const __half* __restrict__ vm,
                      float* __restrict__ pm, float* __restrict__ pl,
                      float* __restrict__ pacc)
{
    extern __shared__ char smraw[];
    __half* Qm = (__half*)smraw;
    __half* Kc = Qm + 64*130;
    __half* VT = Kc + 128*130;
    float*  Ps = (float*)(VT + 128*130);
    __half2* Q2 = (__half2*)Qm;
    __half2* K2 = (__half2*)Kc;
    __half2* V2 = (__half2*)VT;

    int bid = blockIdx.x;
    int ch = bid & (NCH-1);
    int hb = bid >> 3;
    int h = hb % Hn, b = hb / Hn;
    int tid = threadIdx.x, lane = tid & 31, wp = tid >> 5;

    for (int i = tid; i < 64*64; i += 256){
        int r = i >> 6, dc = i & 63;
        Q2[r*65 + dc] = *(const __half2*)(qm + ((size_t)(b*Mn + r))*Dn + h*DHn + dc*2);
    }

    float mrun[8], lrun[8], accv[8][4];
    #pragma unroll
    for (int rr=0;rr<8;rr++){
        mrun[rr] = -1e30f; lrun[rr] = 0.f;
        #pragma unroll
        for (int j=0;j<4;j++) accv[rr][j] = 0.f;
    }

    int cBeg = ch * (Sn / NCH);
    for (int c0 = cBeg; c0 < cBeg + Sn/NCH; c0 += 128){
        __syncthreads();
        for (int i = tid; i < 128*64; i += 256){
            int r = i >> 6, dc = i & 63, d2 = dc*2;
            size_t gidx = ((size_t)(b*Sn + c0 + r))*Dn + h*DHn + d2;
            __half2 k2 = *(const __half2*)(km + gidx);
            __half2 v2 = *(const __half2*)(vm + gidx);
            K2[r*65 + dc] = k2;
            VT[d2*130 + r]     = __low2half(v2);
            VT[(d2+1)*130 + r] = __high2half(v2);
        }
        __syncthreads();

        #pragma unroll 1
        for (int rr=0;rr<8;rr++){
            int row = wp*8 + rr;
            float sc[4] = {0,0,0,0};
            for (int dd = 0; dd < 64; dd++){
                float2 q2 = __half22float2(Q2[row*65 + dd]);
                #pragma unroll
                for (int j=0;j<4;j++){
                    float2 k2 = __half22float2(K2[(j*32+lane)*65 + dd]);
                    sc[j] = fmaf(q2.x, k2.x, sc[j]);
                    sc[j] = fmaf(q2.y, k2.y, sc[j]);
                }
            }
            #pragma unroll
            for (int j=0;j<4;j++) sc[j] *= SCALEn;
            float cm = fmaxf(fmaxf(sc[0],sc[1]), fmaxf(sc[2],sc[3]));
            cm = warpMax(cm);
            float mn = fmaxf(mrun[rr], cm);
            float corr = expf(mrun[rr] - mn);
            float ls = 0.f;
            #pragma unroll
            for (int j=0;j<4;j++){ sc[j] = expf(sc[j]-mn); ls += sc[j]; }
            ls = warpSum(ls);
            lrun[rr] = lrun[rr]*corr + ls;
            mrun[rr] = mn;
            #pragma unroll
            for (int j=0;j<4;j++) accv[rr][j] *= corr;
            #pragma unroll
            for (int j=0;j<4;j++) Ps[wp*128 + j*32 + lane] = sc[j];
            __syncwarp();
            for (int kk=0;kk<64;kk++){
                float p0 = Ps[wp*128 + 2*kk], p1 = Ps[wp*128 + 2*kk + 1];
                #pragma unroll
                for (int j=0;j<4;j++){
                    float2 v2 = __half22float2(V2[(j*32+lane)*65 + kk]);
                    accv[rr][j] = fmaf(p0, v2.x, accv[rr][j]);
                    accv[rr][j] = fmaf(p1, v2.y, accv[rr][j]);
                }
            }
            __syncwarp();
        }
    }

    #pragma unroll
    for (int rr=0;rr<8;rr++){
        int row = wp*8 + rr;
        size_t p = ((size_t)(b*Hn + h)*NCH + ch)*Mn + row;
        if (lane == 0){ pm[p] = mrun[rr]; pl[p] = lrun[rr]; }
        #pragma unroll
        for (int j=0;j<4;j++)
            pacc[p*DHn + j*32 + lane] = accv[rr][j];
    }
}

// ---------------- matt merge ----------------
__global__ __launch_bounds__(256)
void matt_merge_kernel(const float* __restrict__ pm, const float* __restrict__ pl,
                       const float* __restrict__ pacc, __half* __restrict__ wr)
{
    int b = blockIdx.x / Hn, h = blockIdx.x % Hn;
    int tid = threadIdx.x, lane = tid & 31, wp = tid >> 5;
    size_t pb = (size_t)(b*Hn + h)*NCH;

    #pragma unroll 1
    for (int rr=0;rr<8;rr++){
        int row = wp*8 + rr;
        float M = -1e30f;
        float mv[NCH], lv[NCH];
        #pragma unroll
        for (int ccc=0; ccc<NCH; ccc++){
            mv[ccc] = pm[(pb + ccc)*Mn + row];
            lv[ccc] = pl[(pb + ccc)*Mn + row];
            M = fmaxf(M, mv[ccc]);
        }
        float L = 0.f, w[NCH];
        #pragma unroll
        for (int ccc=0; ccc<NCH; ccc++){
            w[ccc] = expf(mv[ccc] - M);
            L += w[ccc]*lv[ccc];
        }
        float invL = 1.f/L;
        #pragma unroll
        for (int j=0;j<4;j++){
            int d = j*32 + lane;
            float s = 0.f;
            #pragma unroll
            for (int ccc=0; ccc<NCH; ccc++)
                s += w[ccc]*pacc[((pb + ccc)*Mn + row)*DHn + d];
            wr[((size_t)(b*Mn + row))*Dn + h*DHn + d] = __float2half_rn(s*invL);
        }
    }
}

// ---------------- small elementwise / reductions ----------------
__global__ __launch_bounds__(256)
void pooled_kernel(const float* __restrict__ gmg, float* __restrict__ pooled)
{
    int d = blockIdx.x*256 + threadIdx.x;
    int b = blockIdx.y;
    const float* p = gmg + (size_t)b*Sn*Dn + d;
    float s = 0.f;
    for (int i=0;i<Sn;i++) s += p[(size_t)i*Dn];
    pooled[b*Dn + d] = s * (1.0f/Sn);
}

__global__ __launch_bounds__(256)
void state_kernel(const float* __restrict__ pooled, const float* __restrict__ w_cz,
                  const float* __restrict__ w_cg, const float* __restrict__ cs,
                  float* __restrict__ state, float* __restrict__ out_state)
{
    int b = blockIdx.x, c = threadIdx.x;
    const float* pr = pooled + (size_t)b*Dn;
    float z = 0.f, gs = 0.f;
    for (int k=0;k<Dn;k++){
        float p = pr[k];
        z  = fmaf(p, w_cz[(size_t)k*Cn + c], z);
        gs = fmaf(p, w_cg[(size_t)k*Cn + c], gs);
    }
    float zt = tanhf(z);
    float gc = 1.f / (1.f + expf(-gs));
    float ns = gc * cs[b*Cn + c] + (1.f - gc) * zt;
    state[b*Cn + c] = ns;
    out_state[b*Cn + c] = ns;
}

__global__ __launch_bounds__(256)
void sp_kernel(const float* __restrict__ state, const float* __restrict__ w_sp,
               float* __restrict__ sp)
{
    int d = blockIdx.x*256 + threadIdx.x;
    int b = blockIdx.y;
    float s = 0.f;
    for (int c=0;c<Cn;c++) s = fmaf(state[b*Cn+c], w_sp[(size_t)c*Dn + d], s);
    sp[b*Dn + d] = s;
}

__global__ __launch_bounds__(256)
void spbias_kernel(const float* __restrict__ sp, const float* __restrict__ wf2,
                   float* __restrict__ bias)
{
    int n = blockIdx.x*256 + threadIdx.x;
    int b = blockIdx.y;
    const float* sr = sp + (size_t)b*Dn;
    float s = 0.f;
    for (int k=0;k<Dn;k++) s = fmaf(sr[k], wf2[(size_t)k*Dn + n], s);
    bias[b*Dn + n] = s;
}

// ---------------- host orchestration ----------------
#define TG1_SMEM (3*2*TG_B_ARR)   // 110592
#define TG2_SMEM (2*3*TG_B_ARR)   // 110592

struct GArgs {
    float* C = nullptr; const float* R1 = nullptr; const float* R2 = nullptr;
    __half* Hout = nullptr; int seg = 0;
    float* C2 = nullptr; __half* Hout2 = nullptr; int epiB = 0; int ldH = 0;
};

static void tg1(const __half* A, const __half* W, int Mr, int Nc, int ldC, int K, int epi, GArgs a){
    if (!a.ldH) a.ldH = ldC;
    tgemm_kernel<1><<<dim3(Nc/128, Mr/128), 256, TG1_SMEM>>>(A, W, nullptr, a.C, ldC, K, epi, a.R1, a.R2, a.Hout, a.seg, a.C2, a.Hout2, a.epiB, a.ldH);
}
static void tg2(const __half* A, const __half* Wh, const __half* Wl, int Mr, int Nc, int ldC, int K, int epi, GArgs a){
    if (!a.ldH) a.ldH = ldC;
    tgemm_kernel<2><<<dim3(Nc/128, Mr/128), 256, TG2_SMEM>>>(A, Wh, Wl, a.C, ldC, K, epi, a.R1, a.R2, a.Hout, a.seg, a.C2, a.Hout2, a.epiB, a.ldH);
}
static void conv(const float* in, __half* hi, size_t n){
    conv_kernel<<<(unsigned)((n+1023)/1024), 256>>>(in, hi, n);
}
static void wconv(const float* W, __half* hi, __half* lo, int K, int N, int ldo = 0){
    if (!ldo) ldo = K;
    wconv_kernel<<<dim3(N/32, K/32), 256>>>(W, hi, lo, K, N, ldo);
}

template <typename T>
static T* sym(const void* symbol){ void* p; cudaGetSymbolAddress(&p, symbol); return (T*)p; }

extern "C" void kernel_launch(void* const* d_in, const int* in_sizes, int n_in,
                              void* d_out, int out_size)
{
    (void)in_sizes; (void)n_in; (void)out_size;
    const float* x      = (const float*)d_in[0];
    const float* gmem   = (const float*)d_in[1];
    const float* cstate = (const float*)d_in[2];
    const float* g1     = (const float*)d_in[3];
    const float* g2     = (const float*)d_in[4];
    const float* g3     = (const float*)d_in[5];
    const float* g4     = (const float*)d_in[6];
    const float* w_qkv  = (const float*)d_in[7];
    const float* w_lo   = (const float*)d_in[8];
    const float* w_gq   = (const float*)d_in[9];
    const float* w_gk   = (const float*)d_in[10];
    const float* w_gv   = (const float*)d_in[11];
    const float* w_go   = (const float*)d_in[12];
    const float* w_gate = (const float*)d_in[13];
    const float* w_mq   = (const float*)d_in[14];
    const float* w_mk   = (const float*)d_in[15];
    const float* w_mv   = (const float*)d_in[16];
    const float* w_mo   = (const float*)d_in[17];
    const float* w_cz   = (const float*)d_in[18];
    const float* w_cg   = (const float*)d_in[19];
    const float* w_sp   = (const float*)d_in[20];
    const float* w_fuse = (const float*)d_in[21];
    const float* w_ff1  = (const float*)d_in[22];
    const float* w_ff2  = (const float*)d_in[23];
    float* out = (float*)d_out;

    float* h1    = sym<float>(g_h1);
    float* lcp   = sym<float>(g_lcp);
    float* h2    = sym<float>(g_h2);
    float* gate  = sym<float>(g_gate);
    float* gmgv  = sym<float>(g_gmg);
    float* pool  = sym<float>(g_pool);
    float* state = sym<float>(g_state);
    float* sp    = sym<float>(g_sp);
    float* bias  = sym<float>(g_bias);
    float* fused = sym<float>(g_fused);
    float* hv    = sym<float>(g_h);
    float* h4    = sym<float>(g_h4);
    float* pm    = sym<float>(g_pm);
    float* pl    = sym<float>(g_pl);
    float* pacc  = sym<float>(g_pacc);

    __half* ch1  = sym<__half>(c_h1);
    __half* ch2  = sym<__half>(c_h2);
    __half* cgm  = sym<__half>(c_gm);
    __half* cqkv = sym<__half>(c_qkv);
    __half* cat  = sym<__half>(c_atto);
    __half* cqg  = sym<__half>(c_qg);
    __half* ckvq = sym<__half>(c_kvq);
    __half* ckm  = sym<__half>(c_km);
    __half* cvm  = sym<__half>(c_vm);
    __half* crd  = sym<__half>(c_rd);
    __half* cf01 = sym<__half>(c_f01);
    __half* ch4  = sym<__half>(c_h4);
    __half* cffa = sym<__half>(c_ffa);
    __half* cwr  = sym<__half>(c_wr);
    __half* tqkv = sym<__half>(t_qkv);
    __half* tqm  = sym<__half>(t_qgmk);
    __half* tlo  = sym<__half>(t_lo);
    __half* tgv2 = sym<__half>(t_gtmv);
    __half* tgo  = sym<__half>(t_go);
    __half* tf01 = sym<__half>(t_f01);
    __half* tgm3 = sym<__half>(t_gm3);
    __half* tmo  = sym<__half>(t_mo);
    __half* tff1 = sym<__half>(t_ff1);
    __half* tff2 = sym<__half>(t_ff2);

    const size_t W1 = (size_t)Dn*Dn;
    const size_t WQ = (size_t)3*Dn*Dn;
    const size_t W2 = (size_t)2*Dn*Dn;

    const int LATT_SMEM = 3*128*130*2 + 8*128*4;
    const int GATT_SMEM = 2*64*130*2 + 128*66*2 + 8*64*4;
    const int MATT_SMEM = 64*130*2 + 2*128*130*2 + 8*128*4;
    cudaFuncSetAttribute(latt_kernel, cudaFuncAttributeMaxDynamicSharedMemorySize, LATT_SMEM);
    cudaFuncSetAttribute(gatt_kernel, cudaFuncAttributeMaxDynamicSharedMemorySize, GATT_SMEM);
    cudaFuncSetAttribute(matt_part_kernel, cudaFuncAttributeMaxDynamicSharedMemorySize, MATT_SMEM);
    cudaFuncSetAttribute(tgemm_kernel<1>, cudaFuncAttributeMaxDynamicSharedMemorySize, TG1_SMEM);
    cudaFuncSetAttribute(tgemm_kernel<2>, cudaFuncAttributeMaxDynamicSharedMemorySize, TG2_SMEM);

    // ---- front: qkv path (launch #5 = P1 tgemm) ----
    wconv(w_qkv, tqkv, tqkv + WQ, Dn, 3*Dn);                        // 0
    rmsnorm_kernel<<<ROWS, 256>>>(x, g1, h1, ch1, 0);               // 1
    wconv(w_lo,  tlo,  nullptr, Dn, Dn);                            // 2
    { GArgs a; a.Hout = cqkv; a.ldH = 3*Dn;
      tg2(ch1, tqkv, tqkv + WQ, ROWS, 3*Dn, 3*Dn, Dn, 0, a); }      // 3
    latt_kernel<<<Bn*nWn*Hn, 256, LATT_SMEM>>>(cqkv, cat);          // 4
    { GArgs a; a.C = lcp; a.R1 = x; a.Hout = cf01; a.ldH = 2*Dn;
      tg1(cat, tlo, ROWS, Dn, Dn, Dn, 1, a); }                      // 5 <- profiled

    // ---- remaining weight converts ----
    wconv(w_gq, tqm,      tqm + W2,      Dn, Dn);
    wconv(w_mk, tqm + W1, tqm + W2 + W1, Dn, Dn);
    wconv(w_gate, tgv2,      nullptr, Dn, Dn);
    wconv(w_mv,   tgv2 + W1, nullptr, Dn, Dn);
    wconv(w_go,   tgo,  nullptr, Dn, Dn);
    wconv(w_fuse,      tf01,      nullptr, Dn, Dn, 2*Dn);
    wconv(w_fuse + W1, tf01 + Dn, nullptr, Dn, Dn, 2*Dn);
    wconv(w_gk,   tgm3,          nullptr, Dn, Dn);
    wconv(w_gv,   tgm3 + W1,     nullptr, Dn, Dn);
    wconv(w_mq,   tgm3 + 2*W1,   nullptr, Dn, Dn);
    wconv(w_mo,   tmo,  nullptr, Dn, Dn);
    wconv(w_ff1,  tff1, nullptr, Dn, FFn);
    wconv(w_ff2,  tff2, nullptr, FFn, Dn);
    conv(gmem, cgm, GM_ELEMS);

    // 5) h2 = rmsnorm(lcp, g2)
    rmsnorm_kernel<<<ROWS, 256>>>(lcp, g2, h2, ch2, 0);
    // 6) qg+mk fused (P2, N=4096, dual fp16 dest) ; batched kg|vg|qm
    { GArgs a; a.seg = 2; a.Hout = cqg; a.Hout2 = ckm;
      tg2(ch2, tqm, tqm + W2, ROWS, 2*Dn, Dn, Dn, 0, a); }
    { GArgs a; a.seg = 1; a.Hout = ckvq;
      tg1(cgm, tgm3, Bn*Mn, 3*Dn, Dn, Dn, 0, a); }
    // 7) read attention
    gatt_kernel<<<Bn*Hn*(Sn/64), 256, GATT_SMEM>>>(cqg, ckvq, ckvq + GM_ELEMS, crd);
    // 8) gate+mv fused (P1, N=4096: sigmoid->fp32 gate | plain->fp16 cvm)
    { GArgs a; a.seg = 2; a.C = gate; a.Hout2 = cvm; a.epiB = 0;
      tg1(ch2, tgv2, ROWS, 2*Dn, Dn, Dn, 2, a); }
    // gmg = h2 + gate*(read@w_go)  (fp32 gmgv + fp16 into cf01 cols 2048..)
    { GArgs a; a.C = gmgv; a.R1 = h2; a.R2 = gate; a.Hout = cf01 + Dn; a.ldH = 2*Dn;
      tg1(crd, tgo, ROWS, Dn, Dn, Dn, 3, a); }
    // 10) memory-write attention: split-K + merge
    matt_part_kernel<<<Bn*Hn*NCH, 256, MATT_SMEM>>>(ckvq + 2*GM_ELEMS, ckm, cvm, pm, pl, pacc);
    matt_merge_kernel<<<Bn*Hn, 256>>>(pm, pl, pacc, cwr);
    // 11) new_memory
    { GArgs a; a.C = out + OUT_ELEMS; a.R1 = gmem;
      tg1(cwr, tmo, Bn*Mn, Dn, Dn, Dn, 1, a); }
    // 12) pooled / state / sp / bias
    pooled_kernel<<<dim3(Dn/256, Bn), 256>>>(gmgv, pool);
    state_kernel<<<Bn, Cn>>>(pool, w_cz, w_cg, cstate, state, out + OUT_ELEMS + MEM_ELEMS);
    sp_kernel<<<dim3(Dn/256, Bn), 256>>>(state, w_sp, sp);
    spbias_kernel<<<dim3(Dn/256, Bn), 256>>>(sp, w_fuse + (size_t)2*Dn*Dn, bias);
    // 13) fused = [lcp|gmg] @ [Wf0;Wf1] + bias  (single K=4096 GEMM)
    { GArgs a; a.C = fused; a.R1 = bias;
      tg1(cf01, tf01, ROWS, Dn, Dn, 2*Dn, 6, a); }
    // 14) h / h4
    rmsnorm_kernel<<<ROWS, 256>>>(fused, g3, hv, nullptr, 1);
    rmsnorm_kernel<<<ROWS, 256>>>(hv, g4, h4, ch4, 0);
    // 15) FFN
    { GArgs a; a.Hout = cffa; a.ldH = FFn;
      tg1(ch4, tff1, ROWS, FFn, FFn, Dn, 4, a); }
    { GArgs a; a.C = out; a.R1 = hv;
      tg1(cffa, tff2, ROWS, Dn, Dn, FFn, 1, a); }
}

// round 14
// speedup vs baseline: 1.0653x; 1.0236x over previous
#include <cuda_runtime.h>
#include <cuda_fp16.h>
#include <math.h>
#include <stdint.h>

// ---------------- problem constants ----------------
#define Bn   4
#define Sn   2048
#define Dn   2048
#define Hn   16
#define DHn  128
#define WINn 128
#define nWn  16
#define Mn   64
#define Cn   256
#define FFn  8192
#define EPSn 1e-6f
#define SCALEn 0.08838834764831843f   // 1/sqrt(128)

#define ROWS (Bn*Sn)                  // 8192
#define OUT_ELEMS  ((size_t)Bn*Sn*Dn)
#define MEM_ELEMS  ((size_t)Bn*Mn*Dn)
#define GM_ELEMS   ((size_t)Bn*Mn*Dn)
#define NCH  8                        // matt key chunks

// ---------------- fp32 scratch ----------------
__device__ float g_h1   [ROWS*Dn];
__device__ float g_lcp  [ROWS*Dn];
__device__ float g_h2   [ROWS*Dn];
__device__ float g_gate [ROWS*Dn];
__device__ float g_gmg  [ROWS*Dn];
__device__ float g_pool [Bn*Dn];
__device__ float g_state[Bn*Cn];
__device__ float g_sp   [Bn*Dn];
__device__ float g_bias [Bn*Dn];
__device__ float g_fused[ROWS*Dn];
__device__ float g_h    [ROWS*Dn];
__device__ float g_h4   [ROWS*Dn];
// matt split-K partials
__device__ float g_pm   [Bn*Hn*NCH*Mn];
__device__ float g_pl   [Bn*Hn*NCH*Mn];
__device__ float g_pacc [(size_t)Bn*Hn*NCH*Mn*DHn];

// ---------------- fp16 scratch ----------------
#define AD __device__ __align__(256)
AD __half c_h1  [(size_t)ROWS*Dn];
AD __half c_h2  [(size_t)ROWS*Dn];
AD __half c_gm  [GM_ELEMS];
AD __half c_qkv [(size_t)ROWS*3*Dn];
AD __half c_atto[(size_t)ROWS*Dn];
AD __half c_qg  [(size_t)ROWS*Dn];
AD __half c_kvq [3*GM_ELEMS];            // kg | vg | qm
AD __half c_km  [(size_t)ROWS*Dn];
AD __half c_vm  [(size_t)ROWS*Dn];
AD __half c_rd  [(size_t)ROWS*Dn];
AD __half c_f01 [(size_t)ROWS*2*Dn];     // [lcp | gmg] fp16, ld 4096
AD __half c_h4  [(size_t)ROWS*Dn];
AD __half c_ffa [(size_t)ROWS*FFn];
AD __half c_wr  [GM_ELEMS];
// transposed weights [N][K]; [2] = hi/lo (lo only for qkv/gq/mk)
AD __half t_qkv [2][(size_t)3*Dn*Dn];
AD __half t_gq  [2][(size_t)Dn*Dn];
AD __half t_mk  [2][(size_t)Dn*Dn];
AD __half t_lo  [(size_t)Dn*Dn];
AD __half t_gate[(size_t)Dn*Dn];
AD __half t_go  [(size_t)Dn*Dn];
AD __half t_mv  [(size_t)Dn*Dn];
AD __half t_f01 [(size_t)Dn*2*Dn];       // [2048 N][4096 K]: fuse0 | fuse1 along K
AD __half t_gm3 [(size_t)3*Dn*Dn];       // gk | gv | mq
AD __half t_mo  [(size_t)Dn*Dn];
AD __half t_ff1 [(size_t)FFn*Dn];
AD __half t_ff2 [(size_t)Dn*FFn];

// ---------------- helpers ----------------
__device__ __forceinline__ float warpMax(float v){
    #pragma unroll
    for (int o=16;o;o>>=1) v = fmaxf(v, __shfl_xor_sync(0xffffffffu, v, o));
    return v;
}
__device__ __forceinline__ float warpSum(float v){
    #pragma unroll
    for (int o=16;o;o>>=1) v += __shfl_xor_sync(0xffffffffu, v, o);
    return v;
}
__device__ __forceinline__ float gelu_tanh(float v){
    const float c0 = 0.7978845608028654f;
    float t = tanhf(c0 * (v + 0.044715f * v * v * v));
    return 0.5f * v * (1.0f + t);
}
__device__ __forceinline__ uint32_t smem_u32(const void* p){
    uint32_t a;
    asm("{ .reg .u64 t; cvta.to.shared.u64 t, %1; cvt.u32.u64 %0, t; }" : "=r"(a) : "l"(p));
    return a;
}
__device__ __forceinline__ void cpa16(uint32_t d, const void* g){
    asm volatile("cp.async.cg.shared.global [%0], [%1], 16;" :: "r"(d), "l"(g));
}
__device__ __forceinline__ void cpa_commit(){ asm volatile("cp.async.commit_group;" ::: "memory"); }
template<int NN> __device__ __forceinline__ void cpa_wait(){
    asm volatile("cp.async.wait_group %0;" :: "n"(NN) : "memory");
}
__device__ __forceinline__ void ldm4(uint32_t* r, uint32_t addr){
    asm volatile("ldmatrix.sync.aligned.m8n8.x4.shared.b16 {%0,%1,%2,%3}, [%4];"
        : "=r"(r[0]),"=r"(r[1]),"=r"(r[2]),"=r"(r[3]) : "r"(addr));
}
__device__ __forceinline__ void mma_f16(float* c, const uint32_t* a, uint32_t b0, uint32_t b1){
    asm volatile("mma.sync.aligned.m16n8k16.row.col.f32.f16.f16.f32 "
        "{%0,%1,%2,%3}, {%4,%5,%6,%7}, {%8,%9}, {%0,%1,%2,%3};"
        : "+f"(c[0]),"+f"(c[1]),"+f"(c[2]),"+f"(c[3])
        : "r"(a[0]),"r"(a[1]),"r"(a[2]),"r"(a[3]), "r"(b0),"r"(b1));
}

// ---------------- tensor GEMM via mma.sync (BK=64; P1: 3-stage, P2: 2-stage) ----------------
#define TG_ARR    18432                 // 128 rows * 72 halfs * 2B
template<int P>
__global__ void __launch_bounds__(256, 2)
tgemm_kernel(const __half* __restrict__ Ahi,
             const __half* __restrict__ Bhi, const __half* __restrict__ Blo,
             float* __restrict__ C, int ldC, int K,
             int epi, const float* __restrict__ R1, const float* __restrict__ R2,
             __half* __restrict__ Hout, int seg, int ldH)
{
    constexpr int NARR = (P == 2) ? 3 : 2;
    constexpr int STG  = NARR * TG_ARR;
    extern __shared__ char smem[];
    uint32_t sb = smem_u32(smem);
    const int tid = threadIdx.x, lane = tid & 31, wid = tid >> 5;
    const int warpM = wid >> 2, warpN = wid & 3;
    const int rowBase = blockIdx.y * 128, colBase = blockIdx.x * 128;

    const __half* src[NARR];
    src[0] = Ahi + (size_t)rowBase * K;
    src[1] = Bhi + (size_t)colBase * K;
    if (P == 2) src[2] = Blo + (size_t)colBase * K;

    auto prefetch = [&](int c, int s){
        size_t koff = (size_t)c * 64;
        #pragma unroll
        for (int t = 0; t < NARR; t++){
            const __half* gb = src[t] + koff;
            uint32_t sdst = sb + s*STG + t*TG_ARR;
            #pragma unroll
            for (int q = 0; q < 4; q++){
                int i = tid + q*256;
                int r = i >> 3, sg = i & 7;
                cpa16(sdst + r*144 + sg*16, gb + (size_t)r*K + sg*8);
            }
        }
    };

    const int lrow = lane & 15, lhalf = (lane >> 4) << 3;
    uint32_t aoff[4], boff[2];
    #pragma unroll
    for (int mt = 0; mt < 4; mt++) aoff[mt] = (warpM*64 + mt*16 + lrow)*144 + lhalf*2;
    #pragma unroll
    for (int np = 0; np < 2; np++) boff[np] = TG_ARR + (warpN*32 + np*16 + lrow)*144 + lhalf*2;

    float acc[4][4][4];
    #pragma unroll
    for (int a=0;a<4;a++)
        #pragma unroll
        for (int b=0;b<4;b++)
            #pragma unroll
            for (int q=0;q<4;q++) acc[a][b][q] = 0.f;

    auto compute = [&](uint32_t sA){
        #pragma unroll
        for (int ks = 0; ks < 4; ks++){
            const uint32_t kadd = ks * 32;
            uint32_t bh[2][4], bl[2][4];
            #pragma unroll
            for (int np = 0; np < 2; np++){
                uint32_t a = sA + boff[np] + kadd;
                ldm4(bh[np], a);
                if (P == 2) ldm4(bl[np], a + TG_ARR);
            }
            #pragma unroll
            for (int mh = 0; mh < 2; mh++){
                uint32_t ah[2][4];
                #pragma unroll
                for (int mt = 0; mt < 2; mt++)
                    ldm4(ah[mt], sA + aoff[mh*2+mt] + kadd);
                #pragma unroll
                for (int mt = 0; mt < 2; mt++)
                    #pragma unroll
                    for (int nt = 0; nt < 4; nt++){
                        int np = nt >> 1, hh = nt & 1;
                        mma_f16(acc[mh*2+mt][nt], ah[mt], bh[np][hh], bh[np][2+hh]);
                    }
                if (P == 2){
                    #pragma unroll
                    for (int mt = 0; mt < 2; mt++)
                        #pragma unroll
                        for (int nt = 0; nt < 4; nt++){
                            int np = nt >> 1, hh = nt & 1;
                            mma_f16(acc[mh*2+mt][nt], ah[mt], bl[np][hh], bl[np][2+hh]);
                        }
                }
            }
        }
    };

    const int nCh = K >> 6;
    if (P == 1){
        prefetch(0, 0); cpa_commit();
        prefetch(1, 1); cpa_commit();
        uint32_t sA = sb;
        int s2 = 2;
        for (int c = 0; c < nCh; c++){
            if (c + 1 < nCh) cpa_wait<1>(); else cpa_wait<0>();
            __syncthreads();
            if (c + 2 < nCh){ prefetch(c+2, s2); cpa_commit(); s2 = (s2 == 2) ? 0 : s2 + 1; }
            compute(sA);
            sA += STG;
            if (sA == sb + 3*STG) sA = sb;
        }
    } else {
        prefetch(0, 0); cpa_commit();
        for (int c = 0; c < nCh; c++){
            if (c + 1 < nCh){ prefetch(c+1, (c+1)&1); cpa_commit(); cpa_wait<1>(); }
            else            { cpa_wait<0>(); }
            __syncthreads();
            compute(sb + (c&1)*STG);
            __syncthreads();
        }
    }

    // epilogue
    #pragma unroll
    for (int mt = 0; mt < 4; mt++){
        #pragma unroll
        for (int nt = 0; nt < 4; nt++){
            int r0 = rowBase + warpM*64 + mt*16 + (lane >> 2);
            int col = colBase + warpN*32 + nt*8 + (lane & 3)*2;
            #pragma unroll
            for (int hh = 0; hh < 2; hh++){
                int row = r0 + hh*8;
                size_t idx, hidx;
                if (seg){
                    idx = hidx = (size_t)(col >> 11)*GM_ELEMS + (size_t)row*Dn + (col & 2047);
                } else {
                    idx = (size_t)row * ldC + col;
                    hidx = (size_t)row * ldH + col;
                }
                float v0 = acc[mt][nt][hh*2+0];
                float v1 = acc[mt][nt][hh*2+1];
                if      (epi == 1){ v0 += R1[idx]; v1 += R1[idx+1]; }
                else if (epi == 2){ v0 = 1.f/(1.f+expf(-v0)); v1 = 1.f/(1.f+expf(-v1)); }
                else if (epi == 3){ v0 = R1[idx] + R2[idx]*v0; v1 = R1[idx+1] + R2[idx+1]*v1; }
                else if (epi == 4){ v0 = gelu_tanh(v0); v1 = gelu_tanh(v1); }
                else if (epi == 6){
                    size_t bidx = (size_t)(row >> 11) * ldC + col;
                    v0 += R1[bidx]; v1 += R1[bidx+1];
                }
                if (C) *(float2*)(C + idx) = make_float2(v0, v1);
                if (Hout) *(__half2*)(Hout + hidx) = __halves2half2(__float2half_rn(v0), __float2half_rn(v1));
            }
        }
    }
}

// ---------------- convert: fp32 -> fp16 ----------------
__global__ __launch_bounds__(256)
void conv_kernel(const float* __restrict__ in, __half* __restrict__ hi, size_t n)
{
    size_t i = ((size_t)blockIdx.x * 256 + threadIdx.x) * 4;
    if (i >= n) return;
    float4 v = *(const float4*)(in + i);
    __half2* ph = (__half2*)(hi + i);
    ph[0] = __halves2half2(__float2half_rn(v.x), __float2half_rn(v.y));
    ph[1] = __halves2half2(__float2half_rn(v.z), __float2half_rn(v.w));
}

// ---------------- weight transpose-convert (output stride ldo) ----------------
__global__ __launch_bounds__(256)
void wconv_kernel(const float* __restrict__ W, __half* __restrict__ hi,
                  __half* __restrict__ lo, int K, int N, int ldo)
{
    __shared__ float t[32][33];
    int n0 = blockIdx.x * 32, k0 = blockIdx.y * 32;
    int tx = threadIdx.x & 31, ty = threadIdx.x >> 5;
    #pragma unroll
    for (int r = ty; r < 32; r += 8)
        t[r][tx] = W[(size_t)(k0 + r) * N + n0 + tx];
    __syncthreads();
    #pragma unroll
    for (int r = ty; r < 32; r += 8){
        float v = t[tx][r];
        size_t o = (size_t)(n0 + r) * ldo + k0 + tx;
        __half h = __float2half_rn(v);
        hi[o] = h;
        if (lo) lo[o] = __float2half_rn(v - __half2float(h));
    }
}

// ---------------- rmsnorm ----------------
__global__ __launch_bounds__(256)
void rmsnorm_kernel(const float* __restrict__ in, const float* __restrict__ g,
                    float* __restrict__ out, __half* __restrict__ hi, int mode)
{
    __shared__ float red[256];
    int row = blockIdx.x, tid = threadIdx.x;
    const float* xr = in + (size_t)row * Dn;
    float4 xa = *(const float4*)(xr + tid*4);
    float4 xb = *(const float4*)(xr + 1024 + tid*4);
    float ss = xa.x*xa.x + xa.y*xa.y + xa.z*xa.z + xa.w*xa.w
             + xb.x*xb.x + xb.y*xb.y + xb.z*xb.z + xb.w*xb.w;
    red[tid] = ss; __syncthreads();
    for (int o=128;o;o>>=1){ if (tid < o) red[tid] += red[tid+o]; __syncthreads(); }
    float inv = rsqrtf(red[0] * (1.0f/Dn) + EPSn);
    float* orow = out + (size_t)row * Dn;
    #pragma unroll
    for (int half_ = 0; half_ < 2; half_++){
        float4 xv = half_ ? xb : xa;
        int d = half_*1024 + tid*4;
        float4 gv = *(const float4*)(g + d);
        float4 ov;
        ov.x = xv.x*inv*gv.x; ov.y = xv.y*inv*gv.y;
        ov.z = xv.z*inv*gv.z; ov.w = xv.w*inv*gv.w;
        if (mode){ ov.x += xv.x; ov.y += xv.y; ov.z += xv.z; ov.w += xv.w; }
        *(float4*)(orow + d) = ov;
        if (hi){
            __half2* ph = (__half2*)(hi + (size_t)row*Dn + d);
            ph[0] = __halves2half2(__float2half_rn(ov.x), __float2half_rn(ov.y));
            ph[1] = __halves2half2(__float2half_rn(ov.z), __float2half_rn(ov.w));
        }
    }
}

// ---------------- local window attention (fp16 smem, V transposed) ----------------
__global__ __launch_bounds__(256)
void latt_kernel(const __half* __restrict__ qkv, __half* __restrict__ out)
{
    extern __shared__ char smraw[];
    __half* Qh = (__half*)smraw;
    __half* Kh = Qh + 128*130;
    __half* VT = Kh + 128*130;
    float*  Ps = (float*)(VT + 128*130);
    __half2* Q2 = (__half2*)Qh;
    __half2* K2 = (__half2*)Kh;
    __half2* V2 = (__half2*)VT;

    int bid = blockIdx.x;
    int h = bid % Hn;
    int w = (bid / Hn) % nWn;
    int b = bid / (Hn * nWn);
    int tid = threadIdx.x, lane = tid & 31, wp = tid >> 5;

    size_t base = ((size_t)(b*Sn + w*WINn)) * (3*Dn) + (size_t)h * DHn;
    for (int i = tid; i < 128*64; i += 256){
        int r = i >> 6, dc = i & 63, d2 = dc*2;
        size_t gidx = base + (size_t)r * (3*Dn) + d2;
        __half2 q2 = *(const __half2*)(qkv + gidx);
        __half2 k2 = *(const __half2*)(qkv + gidx + Dn);
        __half2 v2 = *(const __half2*)(qkv + gidx + 2*Dn);
        Q2[r*65 + dc] = q2;
        K2[r*65 + dc] = k2;
        VT[d2*130 + r]     = __low2half(v2);
        VT[(d2+1)*130 + r] = __high2half(v2);
    }
    __syncthreads();

    for (int row = wp; row < 128; row += 8){
        float sc[4] = {0,0,0,0};
        for (int dd = 0; dd < 64; dd++){
            float2 q2 = __half22float2(Q2[row*65 + dd]);
            #pragma unroll
            for (int j=0;j<4;j++){
                float2 k2 = __half22float2(K2[(j*32+lane)*65 + dd]);
                sc[j] = fmaf(q2.x, k2.x, sc[j]);
                sc[j] = fmaf(q2.y, k2.y, sc[j]);
            }
        }
        #pragma unroll
        for (int j=0;j<4;j++) sc[j] *= SCALEn;
        float m = fmaxf(fmaxf(sc[0],sc[1]), fmaxf(sc[2],sc[3]));
        m = warpMax(m);
        float l = 0.f;
        #pragma unroll
        for (int j=0;j<4;j++){ sc[j] = expf(sc[j]-m); l += sc[j]; }
        l = warpSum(l);
        float inv = 1.f / l;
        #pragma unroll
        for (int j=0;j<4;j++) Ps[wp*128 + j*32 + lane] = sc[j]*inv;
        __syncwarp();
        float accv[4] = {0,0,0,0};
        for (int kk=0;kk<64;kk++){
            float p0 = Ps[wp*128 + 2*kk], p1 = Ps[wp*128 + 2*kk + 1];
            #pragma unroll
            for (int j=0;j<4;j++){
                float2 v2 = __half22float2(V2[(j*32+lane)*65 + kk]);
                accv[j] = fmaf(p0, v2.x, accv[j]);
                accv[j] = fmaf(p1, v2.y, accv[j]);
            }
        }
        size_t orow = ((size_t)(b*Sn + w*WINn + row)) * Dn + (size_t)h*DHn;
        #pragma unroll
        for (int j=0;j<4;j++) out[orow + j*32 + lane] = __float2half_rn(accv[j]);
        __syncwarp();
    }
}

// ---------------- global-memory read attention (fp16 smem, V transposed) ----------------
__global__ __launch_bounds__(256)
void gatt_kernel(const __half* __restrict__ qg, const __half* __restrict__ kg,
                 const __half* __restrict__ vg, __half* __restrict__ rd)
{
    extern __shared__ char smraw[];
    __half* Qh = (__half*)smraw;
    __half* Kh = Qh + 64*130;
    __half* VT = Kh + 64*130;
    float*  Ps = (float*)(VT + 128*66);
    __half2* Q2 = (__half2*)Qh;
    __half2* K2 = (__half2*)Kh;
    __half2* V2 = (__half2*)VT;

    int bid = blockIdx.x;
    int qt = bid % (Sn/64);
    int h  = (bid / (Sn/64)) % Hn;
    int b  = bid / ((Sn/64) * Hn);
    int tid = threadIdx.x, lane = tid & 31, wp = tid >> 5;
    int s0 = qt * 64;

    for (int i = tid; i < 64*64; i += 256){
        int r = i >> 6, dc = i & 63, d2 = dc*2;
        __half2 q2 = *(const __half2*)(qg + ((size_t)(b*Sn + s0 + r))*Dn + h*DHn + d2);
        size_t gidx = ((size_t)(b*Mn + r))*Dn + h*DHn + d2;
        __half2 k2 = *(const __half2*)(kg + gidx);
        __half2 v2 = *(const __half2*)(vg + gidx);
        Q2[r*65 + dc] = q2;
        K2[r*65 + dc] = k2;
        VT[d2*66 + r]     = __low2half(v2);
        VT[(d2+1)*66 + r] = __high2half(v2);
    }
    __syncthreads();

    for (int row = wp; row < 64; row += 8){
        float sc[2] = {0,0};
        for (int dd = 0; dd < 64; dd++){
            float2 q2 = __half22float2(Q2[row*65 + dd]);
            #pragma unroll
            for (int j=0;j<2;j++){
                float2 k2 = __half22float2(K2[(j*32+lane)*65 + dd]);
                sc[j] = fmaf(q2.x, k2.x, sc[j]);
                sc[j] = fmaf(q2.y, k2.y, sc[j]);
            }
        }
        sc[0] *= SCALEn; sc[1] *= SCALEn;
        float m = warpMax(fmaxf(sc[0], sc[1]));
        float l = 0.f;
        #pragma unroll
        for (int j=0;j<2;j++){ sc[j] = expf(sc[j]-m); l += sc[j]; }
        l = warpSum(l);
        float inv = 1.f/l;
        #pragma unroll
        for (int j=0;j<2;j++) Ps[wp*64 + j*32 + lane] = sc[j]*inv;
        __syncwarp();
        float accv[4] = {0,0,0,0};
        for (int kk=0;kk<32;kk++){
            float p0 = Ps[wp*64 + 2*kk], p1 = Ps[wp*64 + 2*kk + 1];
            #pragma unroll
            for (int j=0;j<4;j++){
                float2 v2 = __half22float2(V2[(j*32+lane)*33 + kk]);
                accv[j] = fmaf(p0, v2.x, accv[j]);
                accv[j] = fmaf(p1, v2.y, accv[j]);
            }
        }
        size_t orow = ((size_t)(b*Sn + s0 + row))*Dn + (size_t)h*DHn;
        #pragma unroll
        for (int j=0;j<4;j++) rd[orow + j*32 + lane] = __float2half_rn(accv[j]);
        __syncwarp();
    }
}

// ---------------- memory-write attention: split-K partials ----------------
__global__ __launch_bounds__(256)
void matt_part_kernel(const __half* __restrict__ qm, const __half* __restrict__ km,
                      const __half* __restrict__ vm,
                      float* __restrict__ pm, float* __restrict__ pl,
                      float* __restrict__ pacc)
{
    extern __shared__ char smraw[];
    __half* Qm = (__half*)smraw;
    __half* Kc = Qm + 64*130;
    __half* VT = Kc + 128*130;
    float*  Ps = (float*)(VT + 128*130);
    __half2* Q2 = (__half2*)Qm;
    __half2* K2 = (__half2*)Kc;
    __half2* V2 = (__half2*)VT;

    int bid = blockIdx.x;
    int ch = bid & (NCH-1);
    int hb = bid >> 3;
    int h = hb % Hn, b = hb / Hn;
    int tid = threadIdx.x, lane = tid & 31, wp = tid >> 5;

    for (int i = tid; i < 64*64; i += 256){
        int r = i >> 6, dc = i & 63;
        Q2[r*65 + dc] = *(const __half2*)(qm + ((size_t)(b*Mn + r))*Dn + h*DHn + dc*2);
    }

    float mrun[8], lrun[8], accv[8][4];
    #pragma unroll
    for (int rr=0;rr<8;rr++){
        mrun[rr] = -1e30f; lrun[rr] = 0.f;
        #pragma unroll
        for (int j=0;j<4;j++) accv[rr][j] = 0.f;
    }

    int cBeg = ch * (Sn / NCH);
    for (int c0 = cBeg; c0 < cBeg + Sn/NCH; c0 += 128){
        __syncthreads();
        for (int i = tid; i < 128*64; i += 256){
            int r = i >> 6, dc = i & 63, d2 = dc*2;
            size_t gidx = ((size_t)(b*Sn + c0 + r))*Dn + h*DHn + d2;
            __half2 k2 = *(const __half2*)(km + gidx);
            __half2 v2 = *(const __half2*)(vm + gidx);
            K2[r*65 + dc] = k2;
            VT[d2*130 + r]     = __low2half(v2);
            VT[(d2+1)*130 + r] = __high2half(v2);
        }
        __syncthreads();

        #pragma unroll 1
        for (int rr=0;rr<8;rr++){
            int row = wp*8 + rr;
            float sc[4] = {0,0,0,0};
            for (int dd = 0; dd < 64; dd++){
                float2 q2 = __half22float2(Q2[row*65 + dd]);
                #pragma unroll
                for (int j=0;j<4;j++){
                    float2 k2 = __half22float2(K2[(j*32+lane)*65 + dd]);
                    sc[j] = fmaf(q2.x, k2.x, sc[j]);
                    sc[j] = fmaf(q2.y, k2.y, sc[j]);
                }
            }
            #pragma unroll
            for (int j=0;j<4;j++) sc[j] *= SCALEn;
            float cm = fmaxf(fmaxf(sc[0],sc[1]), fmaxf(sc[2],sc[3]));
            cm = warpMax(cm);
            float mn = fmaxf(mrun[rr], cm);
            float corr = expf(mrun[rr] - mn);
            float ls = 0.f;
            #pragma unroll
            for (int j=0;j<4;j++){ sc[j] = expf(sc[j]-mn); ls += sc[j]; }
            ls = warpSum(ls);
            lrun[rr] = lrun[rr]*corr + ls;
            mrun[rr] = mn;
            #pragma unroll
            for (int j=0;j<4;j++) accv[rr][j] *= corr;
            #pragma unroll
            for (int j=0;j<4;j++) Ps[wp*128 + j*32 + lane] = sc[j];
            __syncwarp();
            for (int kk=0;kk<64;kk++){
                float p0 = Ps[wp*128 + 2*kk], p1 = Ps[wp*128 + 2*kk + 1];
                #pragma unroll
                for (int j=0;j<4;j++){
                    float2 v2 = __half22float2(V2[(j*32+lane)*65 + kk]);
                    accv[rr][j] = fmaf(p0, v2.x, accv[rr][j]);
                    accv[rr][j] = fmaf(p1, v2.y, accv[rr][j]);
                }
            }
            __syncwarp();
        }
    }

    #pragma unroll
    for (int rr=0;rr<8;rr++){
        int row = wp*8 + rr;
        size_t p = ((size_t)(b*Hn + h)*NCH + ch)*Mn + row;
        if (lane == 0){ pm[p] = mrun[rr]; pl[p] = lrun[rr]; }
        #pragma unroll
        for (int j=0;j<4;j++)
            pacc[p*DHn + j*32 + lane] = accv[rr][j];
    }
}

// ---------------- matt merge ----------------
__global__ __launch_bounds__(256)
void matt_merge_kernel(const float* __restrict__ pm, const float* __restrict__ pl,
                       const float* __restrict__ pacc, __half* __restrict__ wr)
{
    int b = blockIdx.x / Hn, h = blockIdx.x % Hn;
    int tid = threadIdx.x, lane = tid & 31, wp = tid >> 5;
    size_t pb = (size_t)(b*Hn + h)*NCH;

    #pragma unroll 1
    for (int rr=0;rr<8;rr++){
        int row = wp*8 + rr;
        float M = -1e30f;
        float mv[NCH], lv[NCH];
        #pragma unroll
        for (int ccc=0; ccc<NCH; ccc++){
            mv[ccc] = pm[(pb + ccc)*Mn + row];
            lv[ccc] = pl[(pb + ccc)*Mn + row];
            M = fmaxf(M, mv[ccc]);
        }
        float L = 0.f, w[NCH];
        #pragma unroll
        for (int ccc=0; ccc<NCH; ccc++){
            w[ccc] = expf(mv[ccc] - M);
            L += w[ccc]*lv[ccc];
        }
        float invL = 1.f/L;
        #pragma unroll
        for (int j=0;j<4;j++){
            int d = j*32 + lane;
            float s = 0.f;
            #pragma unroll
            for (int ccc=0; ccc<NCH; ccc++)
                s += w[ccc]*pacc[((pb + ccc)*Mn + row)*DHn + d];
            wr[((size_t)(b*Mn + row))*Dn + h*DHn + d] = __float2half_rn(s*invL);
        }
    }
}

// ---------------- small elementwise / reductions ----------------
__global__ __launch_bounds__(256)
void pooled_kernel(const float* __restrict__ gmg, float* __restrict__ pooled)
{
    int d = blockIdx.x*256 + threadIdx.x;
    int b = blockIdx.y;
    const float* p = gmg + (size_t)b*Sn*Dn + d;
    float s = 0.f;
    for (int i=0;i<Sn;i++) s += p[(size_t)i*Dn];
    pooled[b*Dn + d] = s * (1.0f/Sn);
}

__global__ __launch_bounds__(256)
void state_kernel(const float* __restrict__ pooled, const float* __restrict__ w_cz,
                  const float* __restrict__ w_cg, const float* __restrict__ cs,
                  float* __restrict__ state, float* __restrict__ out_state)
{
    int b = blockIdx.x, c = threadIdx.x;
    const float* pr = pooled + (size_t)b*Dn;
    float z = 0.f, gs = 0.f;
    for (int k=0;k<Dn;k++){
        float p = pr[k];
        z  = fmaf(p, w_cz[(size_t)k*Cn + c], z);
        gs = fmaf(p, w_cg[(size_t)k*Cn + c], gs);
    }
    float zt = tanhf(z);
    float gc = 1.f / (1.f + expf(-gs));
    float ns = gc * cs[b*Cn + c] + (1.f - gc) * zt;
    state[b*Cn + c] = ns;
    out_state[b*Cn + c] = ns;
}

__global__ __launch_bounds__(256)
void sp_kernel(const float* __restrict__ state, const float* __restrict__ w_sp,
               float* __restrict__ sp)
{
    int d = blockIdx.x*256 + threadIdx.x;
    int b = blockIdx.y;
    float s = 0.f;
    for (int c=0;c<Cn;c++) s = fmaf(state[b*Cn+c], w_sp[(size_t)c*Dn + d], s);
    sp[b*Dn + d] = s;
}

__global__ __launch_bounds__(256)
void spbias_kernel(const float* __restrict__ sp, const float* __restrict__ wf2,
                   float* __restrict__ bias)
{
    int n = blockIdx.x*256 + threadIdx.x;
    int b = blockIdx.y;
    const float* sr = sp + (size_t)b*Dn;
    float s = 0.f;
    for (int k=0;k<Dn;k++) s = fmaf(sr[k], wf2[(size_t)k*Dn + n], s);
    bias[b*Dn + n] = s;
}

// ---------------- host orchestration ----------------
#define TG1_SMEM (3*2*TG_ARR)   // 110592 (3-stage)
#define TG2_SMEM (2*3*TG_ARR)   // 110592 (2-stage)

static void tg1(const __half* A, const __half* W,
                float* C, int Mr, int Nc, int ldC, int K,
                int epi, const float* R1, const float* R2, __half* Hout,
                int seg = 0, int ldH = 0)
{
    if (!ldH) ldH = ldC;
    tgemm_kernel<1><<<dim3(Nc/128, Mr/128), 256, TG1_SMEM>>>(A, W, nullptr, C, ldC, K, epi, R1, R2, Hout, seg, ldH);
}
static void tg2(const __half* A, const __half* Wh, const __half* Wl,
                float* C, int Mr, int Nc, int ldC, int K,
                int epi, const float* R1, const float* R2, __half* Hout,
                int seg = 0, int ldH = 0)
{
    if (!ldH) ldH = ldC;
    tgemm_kernel<2><<<dim3(Nc/128, Mr/128), 256, TG2_SMEM>>>(A, Wh, Wl, C, ldC, K, epi, R1, R2, Hout, seg, ldH);
}
static void conv(const float* in, __half* hi, size_t n){
    conv_kernel<<<(unsigned)((n+1023)/1024), 256>>>(in, hi, n);
}
static void wconv(const float* W, __half* hi, __half* lo, int K, int N, int ldo = 0){
    if (!ldo) ldo = K;
    wconv_kernel<<<dim3(N/32, K/32), 256>>>(W, hi, lo, K, N, ldo);
}

template <typename T>
static T* sym(const void* symbol){ void* p; cudaGetSymbolAddress(&p, symbol); return (T*)p; }

extern "C" void kernel_launch(void* const* d_in, const int* in_sizes, int n_in,
                              void* d_out, int out_size)
{
    (void)in_sizes; (void)n_in; (void)out_size;
    const float* x      = (const float*)d_in[0];
    const float* gmem   = (const float*)d_in[1];
    const float* cstate = (const float*)d_in[2];
    const float* g1     = (const float*)d_in[3];
    const float* g2     = (const float*)d_in[4];
    const float* g3     = (const float*)d_in[5];
    const float* g4     = (const float*)d_in[6];
    const float* w_qkv  = (const float*)d_in[7];
    const float* w_lo   = (const float*)d_in[8];
    const float* w_gq   = (const float*)d_in[9];
    const float* w_gk   = (const float*)d_in[10];
    const float* w_gv   = (const float*)d_in[11];
    const float* w_go   = (const float*)d_in[12];
    const float* w_gate = (const float*)d_in[13];
    const float* w_mq   = (const float*)d_in[14];
    const float* w_mk   = (const float*)d_in[15];
    const float* w_mv   = (const float*)d_in[16];
    const float* w_mo   = (const float*)d_in[17];
    const float* w_cz   = (const float*)d_in[18];
    const float* w_cg   = (const float*)d_in[19];
    const float* w_sp   = (const float*)d_in[20];
    const float* w_fuse = (const float*)d_in[21];
    const float* w_ff1  = (const float*)d_in[22];
    const float* w_ff2  = (const float*)d_in[23];
    float* out = (float*)d_out;

    float* h1    = sym<float>(g_h1);
    float* lcp   = sym<float>(g_lcp);
    float* h2    = sym<float>(g_h2);
    float* gate  = sym<float>(g_gate);
    float* gmgv  = sym<float>(g_gmg);
    float* pool  = sym<float>(g_pool);
    float* state = sym<float>(g_state);
    float* sp    = sym<float>(g_sp);
    float* bias  = sym<float>(g_bias);
    float* fused = sym<float>(g_fused);
    float* hv    = sym<float>(g_h);
    float* h4    = sym<float>(g_h4);
    float* pm    = sym<float>(g_pm);
    float* pl    = sym<float>(g_pl);
    float* pacc  = sym<float>(g_pacc);

    __half* ch1  = sym<__half>(c_h1);
    __half* ch2  = sym<__half>(c_h2);
    __half* cgm  = sym<__half>(c_gm);
    __half* cqkv = sym<__half>(c_qkv);
    __half* cat  = sym<__half>(c_atto);
    __half* cqg  = sym<__half>(c_qg);
    __half* ckvq = sym<__half>(c_kvq);
    __half* ckm  = sym<__half>(c_km);
    __half* cvm  = sym<__half>(c_vm);
    __half* crd  = sym<__half>(c_rd);
    __half* cf01 = sym<__half>(c_f01);
    __half* ch4  = sym<__half>(c_h4);
    __half* cffa = sym<__half>(c_ffa);
    __half* cwr  = sym<__half>(c_wr);
    __half* tqkv = sym<__half>(t_qkv);
    __half* tgq  = sym<__half>(t_gq);
    __half* tmk  = sym<__half>(t_mk);
    __half* tlo  = sym<__half>(t_lo);
    __half* tgt  = sym<__half>(t_gate);
    __half* tgo  = sym<__half>(t_go);
    __half* tmv  = sym<__half>(t_mv);
    __half* tf01 = sym<__half>(t_f01);
    __half* tgm3 = sym<__half>(t_gm3);
    __half* tmo  = sym<__half>(t_mo);
    __half* tff1 = sym<__half>(t_ff1);
    __half* tff2 = sym<__half>(t_ff2);

    const size_t W1 = (size_t)Dn*Dn;
    const size_t WQ = (size_t)3*Dn*Dn;

    const int LATT_SMEM = 3*128*130*2 + 8*128*4;
    const int GATT_SMEM = 2*64*130*2 + 128*66*2 + 8*64*4;
    const int MATT_SMEM = 64*130*2 + 2*128*130*2 + 8*128*4;
    cudaFuncSetAttribute(latt_kernel, cudaFuncAttributeMaxDynamicSharedMemorySize, LATT_SMEM);
    cudaFuncSetAttribute(gatt_kernel, cudaFuncAttributeMaxDynamicSharedMemorySize, GATT_SMEM);
    cudaFuncSetAttribute(matt_part_kernel, cudaFuncAttributeMaxDynamicSharedMemorySize, MATT_SMEM);
    cudaFuncSetAttribute(tgemm_kernel<1>, cudaFuncAttributeMaxDynamicSharedMemorySize, TG1_SMEM);
    cudaFuncSetAttribute(tgemm_kernel<2>, cudaFuncAttributeMaxDynamicSharedMemorySize, TG2_SMEM);

    // ---- front: qkv path first (launch #5 = P1 tgemm) ----
    wconv(w_qkv, tqkv, tqkv + WQ, Dn, 3*Dn);                        // 0
    rmsnorm_kernel<<<ROWS, 256>>>(x, g1, h1, ch1, 0);               // 1
    wconv(w_lo,  tlo,  nullptr, Dn, Dn);                            // 2
    tg2(ch1, tqkv, tqkv + WQ, nullptr, ROWS, 3*Dn, 3*Dn, Dn, 0, nullptr, nullptr, cqkv); // 3
    latt_kernel<<<Bn*nWn*Hn, 256, LATT_SMEM>>>(cqkv, cat);          // 4
    tg1(cat, tlo, lcp, ROWS, Dn, Dn, Dn, 1, x, nullptr, cf01, 0, 2*Dn); // 5 <- profiled

    // ---- remaining weight converts ----
    wconv(w_gq,   tgq,  tgq + W1, Dn, Dn);
    wconv(w_mk,   tmk,  tmk + W1, Dn, Dn);
    wconv(w_gate, tgt,  nullptr, Dn, Dn);
    wconv(w_go,   tgo,  nullptr, Dn, Dn);
    wconv(w_mv,   tmv,  nullptr, Dn, Dn);
    wconv(w_fuse,      tf01,      nullptr, Dn, Dn, 2*Dn);
    wconv(w_fuse + W1, tf01 + Dn, nullptr, Dn, Dn, 2*Dn);
    wconv(w_gk,   tgm3,          nullptr, Dn, Dn);
    wconv(w_gv,   tgm3 + W1,     nullptr, Dn, Dn);
    wconv(w_mq,   tgm3 + 2*W1,   nullptr, Dn, Dn);
    wconv(w_mo,   tmo,  nullptr, Dn, Dn);
    wconv(w_ff1,  tff1, nullptr, Dn, FFn);
    wconv(w_ff2,  tff2, nullptr, FFn, Dn);
    conv(gmem, cgm, GM_ELEMS);

    // 5) h2 = rmsnorm(lcp, g2)
    rmsnorm_kernel<<<ROWS, 256>>>(lcp, g2, h2, ch2, 0);
    // 6) qg ; batched kg|vg|qm (segmented epilogue)
    tg2(ch2, tgq, tgq + W1, nullptr, ROWS, Dn, Dn, Dn, 0, nullptr, nullptr, cqg);
    tg1(cgm, tgm3, nullptr, Bn*Mn, 3*Dn, Dn, Dn, 0, nullptr, nullptr, ckvq, 1);
    // 7) read attention
    gatt_kernel<<<Bn*Hn*(Sn/64), 256, GATT_SMEM>>>(cqg, ckvq, ckvq + GM_ELEMS, crd);
    // 8) gate / gmg (gmg fp16 goes into cf01 cols 2048..4095)
    tg1(ch2, tgt, gate, ROWS, Dn, Dn, Dn, 2, nullptr, nullptr, nullptr);
    tg1(crd, tgo, gmgv, ROWS, Dn, Dn, Dn, 3, h2, gate, cf01 + Dn, 0, 2*Dn);
    // 9) km / vm
    tg2(ch2, tmk, tmk + W1, nullptr, ROWS, Dn, Dn, Dn, 0, nullptr, nullptr, ckm);
    tg1(ch2, tmv, nullptr, ROWS, Dn, Dn, Dn, 0, nullptr, nullptr, cvm);
    // 10) memory-write attention: split-K + merge
    matt_part_kernel<<<Bn*Hn*NCH, 256, MATT_SMEM>>>(ckvq + 2*GM_ELEMS, ckm, cvm, pm, pl, pacc);
    matt_merge_kernel<<<Bn*Hn, 256>>>(pm, pl, pacc, cwr);
    // 11) new_memory
    tg1(cwr, tmo, out + OUT_ELEMS, Bn*Mn, Dn, Dn, Dn, 1, gmem, nullptr, nullptr);
    // 12) pooled / state / sp / bias
    pooled_kernel<<<dim3(Dn/256, Bn), 256>>>(gmgv, pool);
    state_kernel<<<Bn, Cn>>>(pool, w_cz, w_cg, cstate, state, out + OUT_ELEMS + MEM_ELEMS);
    sp_kernel<<<dim3(Dn/256, Bn), 256>>>(state, w_sp, sp);
    spbias_kernel<<<dim3(Dn/256, Bn), 256>>>(sp, w_fuse + (size_t)2*Dn*Dn, bias);
    // 13) fused = [lcp|gmg] @ [Wf0;Wf1] + bias[b]  (single K=4096 GEMM)
    tg1(cf01, tf01, fused, ROWS, Dn, Dn, 2*Dn, 6, bias, nullptr, nullptr);
    // 14) h / h4
    rmsnorm_kernel<<<ROWS, 256>>>(fused, g3, hv, nullptr, 1);
    rmsnorm_kernel<<<ROWS, 256>>>(hv, g4, h4, ch4, 0);
    // 15) FFN
    tg1(ch4, tff1, nullptr, ROWS, FFn, FFn, Dn, 4, nullptr, nullptr, cffa);
    tg1(cffa, tff2, out, ROWS, Dn, Dn, FFn, 1, hv, nullptr, nullptr);
}

// round 15
// speedup vs baseline: 1.0766x; 1.0106x over previous
#include <cuda_runtime.h>
#include <cuda_fp16.h>
#include <math.h>
#include <stdint.h>

// ---------------- problem constants ----------------
#define Bn   4
#define Sn   2048
#define Dn   2048
#define Hn   16
#define DHn  128
#define WINn 128
#define nWn  16
#define Mn   64
#define Cn   256
#define FFn  8192
#define EPSn 1e-6f
#define SCALEn 0.08838834764831843f   // 1/sqrt(128)

#define ROWS (Bn*Sn)                  // 8192
#define OUT_ELEMS  ((size_t)Bn*Sn*Dn)
#define MEM_ELEMS  ((size_t)Bn*Mn*Dn)
#define GM_ELEMS   ((size_t)Bn*Mn*Dn)
#define NCH  8                        // matt key chunks
#define PCH  16                       // pooled S chunks

// ---------------- fp32 scratch ----------------
__device__ float g_h1   [ROWS*Dn];
__device__ float g_lcp  [ROWS*Dn];
__device__ float g_h2   [ROWS*Dn];
__device__ float g_gate [ROWS*Dn];
__device__ float g_gmg  [ROWS*Dn];
__device__ float g_pool [Bn*Dn];
__device__ float g_pp   [PCH*Bn*Dn];
__device__ float g_state[Bn*Cn];
__device__ float g_sp   [Bn*Dn];
__device__ float g_bias [Bn*Dn];
__device__ float g_fused[ROWS*Dn];
__device__ float g_h    [ROWS*Dn];
// matt split-K partials
__device__ float g_pm   [Bn*Hn*NCH*Mn];
__device__ float g_pl   [Bn*Hn*NCH*Mn];
__device__ float g_pacc [(size_t)Bn*Hn*NCH*Mn*DHn];

// ---------------- fp16 scratch ----------------
#define AD __device__ __align__(256)
AD __half c_h1  [(size_t)ROWS*Dn];
AD __half c_h2  [(size_t)ROWS*Dn];
AD __half c_gm  [GM_ELEMS];
AD __half c_qkv [(size_t)ROWS*3*Dn];
AD __half c_atto[(size_t)ROWS*Dn];
AD __half c_qg  [(size_t)ROWS*Dn];
AD __half c_kvq [3*GM_ELEMS];            // kg | vg | qm
AD __half c_km  [(size_t)ROWS*Dn];
AD __half c_vm  [(size_t)ROWS*Dn];
AD __half c_rd  [(size_t)ROWS*Dn];
AD __half c_f01 [(size_t)ROWS*2*Dn];     // [lcp | gmg] fp16, ld 4096
AD __half c_h4  [(size_t)ROWS*Dn];
AD __half c_ffa [(size_t)ROWS*FFn];
AD __half c_wr  [GM_ELEMS];
// transposed weights [N][K]; [2] = hi/lo (lo only for qkv/gq/mk)
AD __half t_qkv [2][(size_t)3*Dn*Dn];
AD __half t_gq  [2][(size_t)Dn*Dn];
AD __half t_mk  [2][(size_t)Dn*Dn];
AD __half t_lo  [(size_t)Dn*Dn];
AD __half t_gate[(size_t)Dn*Dn];
AD __half t_go  [(size_t)Dn*Dn];
AD __half t_mv  [(size_t)Dn*Dn];
AD __half t_f01 [(size_t)Dn*2*Dn];       // [2048 N][4096 K]: fuse0 | fuse1 along K
AD __half t_gm3 [(size_t)3*Dn*Dn];       // gk | gv | mq
AD __half t_mo  [(size_t)Dn*Dn];
AD __half t_ff1 [(size_t)FFn*Dn];
AD __half t_ff2 [(size_t)Dn*FFn];

// ---------------- helpers ----------------
__device__ __forceinline__ float warpMax(float v){
    #pragma unroll
    for (int o=16;o;o>>=1) v = fmaxf(v, __shfl_xor_sync(0xffffffffu, v, o));
    return v;
}
__device__ __forceinline__ float warpSum(float v){
    #pragma unroll
    for (int o=16;o;o>>=1) v += __shfl_xor_sync(0xffffffffu, v, o);
    return v;
}
__device__ __forceinline__ float gelu_tanh(float v){
    const float c0 = 0.7978845608028654f;
    float t = tanhf(c0 * (v + 0.044715f * v * v * v));
    return 0.5f * v * (1.0f + t);
}
__device__ __forceinline__ uint32_t smem_u32(const void* p){
    uint32_t a;
    asm("{ .reg .u64 t; cvta.to.shared.u64 t, %1; cvt.u32.u64 %0, t; }" : "=r"(a) : "l"(p));
    return a;
}
__device__ __forceinline__ void cpa16(uint32_t d, const void* g){
    asm volatile("cp.async.cg.shared.global [%0], [%1], 16;" :: "r"(d), "l"(g));
}
__device__ __forceinline__ void cpa_commit(){ asm volatile("cp.async.commit_group;" ::: "memory"); }
template<int NN> __device__ __forceinline__ void cpa_wait(){
    asm volatile("cp.async.wait_group %0;" :: "n"(NN) : "memory");
}
__device__ __forceinline__ void ldm4(uint32_t* r, uint32_t addr){
    asm volatile("ldmatrix.sync.aligned.m8n8.x4.shared.b16 {%0,%1,%2,%3}, [%4];"
        : "=r"(r[0]),"=r"(r[1]),"=r"(r[2]),"=r"(r[3]) : "r"(addr));
}
__device__ __forceinline__ void mma_f16(float* c, const uint32_t* a, uint32_t b0, uint32_t b1){
    asm volatile("mma.sync.aligned.m16n8k16.row.col.f32.f16.f16.f32 "
        "{%0,%1,%2,%3}, {%4,%5,%6,%7}, {%8,%9}, {%0,%1,%2,%3};"
        : "+f"(c[0]),"+f"(c[1]),"+f"(c[2]),"+f"(c[3])
        : "r"(a[0]),"r"(a[1]),"r"(a[2]),"r"(a[3]), "r"(b0),"r"(b1));
}

// ---------------- tensor GEMM via mma.sync (BK=64; single sync/chunk) ----------------
#define TG_ARR    18432                 // 128 rows * 72 halfs * 2B
template<int P>
__global__ void __launch_bounds__(256, 2)
tgemm_kernel(const __half* __restrict__ Ahi,
             const __half* __restrict__ Bhi, const __half* __restrict__ Blo,
             float* __restrict__ C, int ldC, int K,
             int epi, const float* __restrict__ R1, const float* __restrict__ R2,
             __half* __restrict__ Hout, int seg, int ldH)
{
    constexpr int NARR = (P == 2) ? 3 : 2;
    constexpr int STG  = NARR * TG_ARR;
    extern __shared__ char smem[];
    uint32_t sb = smem_u32(smem);
    const int tid = threadIdx.x, lane = tid & 31, wid = tid >> 5;
    const int warpM = wid >> 2, warpN = wid & 3;
    const int rowBase = blockIdx.y * 128, colBase = blockIdx.x * 128;

    const __half* src[NARR];
    src[0] = Ahi + (size_t)rowBase * K;
    src[1] = Bhi + (size_t)colBase * K;
    if (P == 2) src[2] = Blo + (size_t)colBase * K;

    auto prefetch = [&](int c, int s){
        size_t koff = (size_t)c * 64;
        #pragma unroll
        for (int t = 0; t < NARR; t++){
            const __half* gb = src[t] + koff;
            uint32_t sdst = sb + s*STG + t*TG_ARR;
            #pragma unroll
            for (int q = 0; q < 4; q++){
                int i = tid + q*256;
                int r = i >> 3, sg = i & 7;
                cpa16(sdst + r*144 + sg*16, gb + (size_t)r*K + sg*8);
            }
        }
    };

    const int lrow = lane & 15, lhalf = (lane >> 4) << 3;
    uint32_t aoff[4], boff[2];
    #pragma unroll
    for (int mt = 0; mt < 4; mt++) aoff[mt] = (warpM*64 + mt*16 + lrow)*144 + lhalf*2;
    #pragma unroll
    for (int np = 0; np < 2; np++) boff[np] = TG_ARR + (warpN*32 + np*16 + lrow)*144 + lhalf*2;

    float acc[4][4][4];
    #pragma unroll
    for (int a=0;a<4;a++)
        #pragma unroll
        for (int b=0;b<4;b++)
            #pragma unroll
            for (int q=0;q<4;q++) acc[a][b][q] = 0.f;

    auto compute = [&](uint32_t sA){
        #pragma unroll
        for (int ks = 0; ks < 4; ks++){
            const uint32_t kadd = ks * 32;
            uint32_t bh[2][4], bl[2][4];
            #pragma unroll
            for (int np = 0; np < 2; np++){
                uint32_t a = sA + boff[np] + kadd;
                ldm4(bh[np], a);
                if (P == 2) ldm4(bl[np], a + TG_ARR);
            }
            #pragma unroll
            for (int mh = 0; mh < 2; mh++){
                uint32_t ah[2][4];
                #pragma unroll
                for (int mt = 0; mt < 2; mt++)
                    ldm4(ah[mt], sA + aoff[mh*2+mt] + kadd);
                #pragma unroll
                for (int mt = 0; mt < 2; mt++)
                    #pragma unroll
                    for (int nt = 0; nt < 4; nt++){
                        int np = nt >> 1, hh = nt & 1;
                        mma_f16(acc[mh*2+mt][nt], ah[mt], bh[np][hh], bh[np][2+hh]);
                    }
                if (P == 2){
                    #pragma unroll
                    for (int mt = 0; mt < 2; mt++)
                        #pragma unroll
                        for (int nt = 0; nt < 4; nt++){
                            int np = nt >> 1, hh = nt & 1;
                            mma_f16(acc[mh*2+mt][nt], ah[mt], bl[np][hh], bl[np][2+hh]);
                        }
                }
            }
        }
    };

    const int nCh = K >> 6;
    if (P == 1){
        // 3-stage, single sync per chunk
        prefetch(0, 0); cpa_commit();
        prefetch(1, 1); cpa_commit();
        uint32_t sA = sb;
        int s2 = 2;
        for (int c = 0; c < nCh; c++){
            if (c + 1 < nCh) cpa_wait<1>(); else cpa_wait<0>();
            __syncthreads();
            if (c + 2 < nCh){ prefetch(c+2, s2); cpa_commit(); s2 = (s2 == 2) ? 0 : s2 + 1; }
            compute(sA);
            sA += STG;
            if (sA == sb + 3*STG) sA = sb;
        }
    } else {
        // 2-stage, single sync per chunk (prefetch AFTER barrier)
        prefetch(0, 0); cpa_commit();
        for (int c = 0; c < nCh; c++){
            cpa_wait<0>();
            __syncthreads();
            if (c + 1 < nCh){ prefetch(c+1, (c+1)&1); cpa_commit(); }
            compute(sb + (c&1)*STG);
        }
    }

    // epilogue
    #pragma unroll
    for (int mt = 0; mt < 4; mt++){
        #pragma unroll
        for (int nt = 0; nt < 4; nt++){
            int r0 = rowBase + warpM*64 + mt*16 + (lane >> 2);
            int col = colBase + warpN*32 + nt*8 + (lane & 3)*2;
            #pragma unroll
            for (int hh = 0; hh < 2; hh++){
                int row = r0 + hh*8;
                size_t idx, hidx;
                if (seg){
                    idx = hidx = (size_t)(col >> 11)*GM_ELEMS + (size_t)row*Dn + (col & 2047);
                } else {
                    idx = (size_t)row * ldC + col;
                    hidx = (size_t)row * ldH + col;
                }
                float v0 = acc[mt][nt][hh*2+0];
                float v1 = acc[mt][nt][hh*2+1];
                if      (epi == 1){ v0 += R1[idx]; v1 += R1[idx+1]; }
                else if (epi == 2){ v0 = 1.f/(1.f+expf(-v0)); v1 = 1.f/(1.f+expf(-v1)); }
                else if (epi == 3){ v0 = R1[idx] + R2[idx]*v0; v1 = R1[idx+1] + R2[idx+1]*v1; }
                else if (epi == 4){ v0 = gelu_tanh(v0); v1 = gelu_tanh(v1); }
                else if (epi == 6){
                    size_t bidx = (size_t)(row >> 11) * ldC + col;
                    v0 += R1[bidx]; v1 += R1[bidx+1];
                }
                if (C) *(float2*)(C + idx) = make_float2(v0, v1);
                if (Hout) *(__half2*)(Hout + hidx) = __halves2half2(__float2half_rn(v0), __float2half_rn(v1));
            }
        }
    }
}

// ---------------- convert: fp32 -> fp16 ----------------
__global__ __launch_bounds__(256)
void conv_kernel(const float* __restrict__ in, __half* __restrict__ hi, size_t n)
{
    size_t i = ((size_t)blockIdx.x * 256 + threadIdx.x) * 4;
    if (i >= n) return;
    float4 v = *(const float4*)(in + i);
    __half2* ph = (__half2*)(hi + i);
    ph[0] = __halves2half2(__float2half_rn(v.x), __float2half_rn(v.y));
    ph[1] = __halves2half2(__float2half_rn(v.z), __float2half_rn(v.w));
}

// ---------------- weight transpose-convert (output stride ldo) ----------------
__global__ __launch_bounds__(256)
void wconv_kernel(const float* __restrict__ W, __half* __restrict__ hi,
                  __half* __restrict__ lo, int K, int N, int ldo)
{
    __shared__ float t[32][33];
    int n0 = blockIdx.x * 32, k0 = blockIdx.y * 32;
    int tx = threadIdx.x & 31, ty = threadIdx.x >> 5;
    #pragma unroll
    for (int r = ty; r < 32; r += 8)
        t[r][tx] = W[(size_t)(k0 + r) * N + n0 + tx];
    __syncthreads();
    #pragma unroll
    for (int r = ty; r < 32; r += 8){
        float v = t[tx][r];
        size_t o = (size_t)(n0 + r) * ldo + k0 + tx;
        __half h = __float2half_rn(v);
        hi[o] = h;
        if (lo) lo[o] = __float2half_rn(v - __half2float(h));
    }
}

// ---------------- rmsnorm ----------------
__global__ __launch_bounds__(256)
void rmsnorm_kernel(const float* __restrict__ in, const float* __restrict__ g,
                    float* __restrict__ out, __half* __restrict__ hi, int mode)
{
    __shared__ float red[256];
    int row = blockIdx.x, tid = threadIdx.x;
    const float* xr = in + (size_t)row * Dn;
    float4 xa = *(const float4*)(xr + tid*4);
    float4 xb = *(const float4*)(xr + 1024 + tid*4);
    float ss = xa.x*xa.x + xa.y*xa.y + xa.z*xa.z + xa.w*xa.w
             + xb.x*xb.x + xb.y*xb.y + xb.z*xb.z + xb.w*xb.w;
    red[tid] = ss; __syncthreads();
    for (int o=128;o;o>>=1){ if (tid < o) red[tid] += red[tid+o]; __syncthreads(); }
    float inv = rsqrtf(red[0] * (1.0f/Dn) + EPSn);
    float* orow = out + (size_t)row * Dn;
    #pragma unroll
    for (int half_ = 0; half_ < 2; half_++){
        float4 xv = half_ ? xb : xa;
        int d = half_*1024 + tid*4;
        float4 gv = *(const float4*)(g + d);
        float4 ov;
        ov.x = xv.x*inv*gv.x; ov.y = xv.y*inv*gv.y;
        ov.z = xv.z*inv*gv.z; ov.w = xv.w*inv*gv.w;
        if (mode){ ov.x += xv.x; ov.y += xv.y; ov.z += xv.z; ov.w += xv.w; }
        *(float4*)(orow + d) = ov;
        if (hi){
            __half2* ph = (__half2*)(hi + (size_t)row*Dn + d);
            ph[0] = __halves2half2(__float2half_rn(ov.x), __float2half_rn(ov.y));
            ph[1] = __halves2half2(__float2half_rn(ov.z), __float2half_rn(ov.w));
        }
    }
}

// ---------------- fused double rmsnorm: hv = fused + norm(fused)*g3 ; ch4 = fp16(norm(hv)*g4) ----------------
__global__ __launch_bounds__(256)
void rmsnorm2_kernel(const float* __restrict__ in, const float* __restrict__ g3,
                     const float* __restrict__ g4, float* __restrict__ hvout,
                     __half* __restrict__ h4h)
{
    __shared__ float red[256];
    int row = blockIdx.x, tid = threadIdx.x;
    const float* xr = in + (size_t)row * Dn;
    float4 xa = *(const float4*)(xr + tid*4);
    float4 xb = *(const float4*)(xr + 1024 + tid*4);
    float ss = xa.x*xa.x + xa.y*xa.y + xa.z*xa.z + xa.w*xa.w
             + xb.x*xb.x + xb.y*xb.y + xb.z*xb.z + xb.w*xb.w;
    red[tid] = ss; __syncthreads();
    for (int o=128;o;o>>=1){ if (tid < o) red[tid] += red[tid+o]; __syncthreads(); }
    float inv1 = rsqrtf(red[0] * (1.0f/Dn) + EPSn);

    // hv = x + norm(x)*g3 (keep in regs, write fp32), accumulate ss2
    float4 ga3 = *(const float4*)(g3 + tid*4);
    float4 gb3 = *(const float4*)(g3 + 1024 + tid*4);
    float4 ha, hb;
    ha.x = xa.x + xa.x*inv1*ga3.x; ha.y = xa.y + xa.y*inv1*ga3.y;
    ha.z = xa.z + xa.z*inv1*ga3.z; ha.w = xa.w + xa.w*inv1*ga3.w;
    hb.x = xb.x + xb.x*inv1*gb3.x; hb.y = xb.y + xb.y*inv1*gb3.y;
    hb.z = xb.z + xb.z*inv1*gb3.z; hb.w = xb.w + xb.w*inv1*gb3.w;
    float* hrow = hvout + (size_t)row * Dn;
    *(float4*)(hrow + tid*4) = ha;
    *(float4*)(hrow + 1024 + tid*4) = hb;
    float ss2 = ha.x*ha.x + ha.y*ha.y + ha.z*ha.z + ha.w*ha.w
              + hb.x*hb.x + hb.y*hb.y + hb.z*hb.z + hb.w*hb.w;
    __syncthreads();
    red[tid] = ss2; __syncthreads();
    for (int o=128;o;o>>=1){ if (tid < o) red[tid] += red[tid+o]; __syncthreads(); }
    float inv2 = rsqrtf(red[0] * (1.0f/Dn) + EPSn);

    float4 ga4 = *(const float4*)(g4 + tid*4);
    float4 gb4 = *(const float4*)(g4 + 1024 + tid*4);
    __half2* ph = (__half2*)(h4h + (size_t)row*Dn + tid*4);
    ph[0] = __halves2half2(__float2half_rn(ha.x*inv2*ga4.x), __float2half_rn(ha.y*inv2*ga4.y));
    ph[1] = __halves2half2(__float2half_rn(ha.z*inv2*ga4.z), __float2half_rn(ha.w*inv2*ga4.w));
    __half2* ph2 = (__half2*)(h4h + (size_t)row*Dn + 1024 + tid*4);
    ph2[0] = __halves2half2(__float2half_rn(hb.x*inv2*gb4.x), __float2half_rn(hb.y*inv2*gb4.y));
    ph2[1] = __halves2half2(__float2half_rn(hb.z*inv2*gb4.z), __float2half_rn(hb.w*inv2*gb4.w));
}

// ---------------- local window attention (fp16 smem, V transposed) ----------------
__global__ __launch_bounds__(256)
void latt_kernel(const __half* __restrict__ qkv, __half* __restrict__ out)
{
    extern __shared__ char smraw[];
    __half* Qh = (__half*)smraw;
    __half* Kh = Qh + 128*130;
    __half* VT = Kh + 128*130;
    float*  Ps = (float*)(VT + 128*130);
    __half2* Q2 = (__half2*)Qh;
    __half2* K2 = (__half2*)Kh;
    __half2* V2 = (__half2*)VT;

    int bid = blockIdx.x;
    int h = bid % Hn;
    int w = (bid / Hn) % nWn;
    int b = bid / (Hn * nWn);
    int tid = threadIdx.x, lane = tid & 31, wp = tid >> 5;

    size_t base = ((size_t)(b*Sn + w*WINn)) * (3*Dn) + (size_t)h * DHn;
    for (int i = tid; i < 128*64; i += 256){
        int r = i >> 6, dc = i & 63, d2 = dc*2;
        size_t gidx = base + (size_t)r * (3*Dn) + d2;
        __half2 q2 = *(const __half2*)(qkv + gidx);
        __half2 k2 = *(const __half2*)(qkv + gidx + Dn);
        __half2 v2 = *(const __half2*)(qkv + gidx + 2*Dn);
        Q2[r*65 + dc] = q2;
        K2[r*65 + dc] = k2;
        VT[d2*130 + r]     = __low2half(v2);
        VT[(d2+1)*130 + r] = __high2half(v2);
    }
    __syncthreads();

    for (int row = wp; row < 128; row += 8){
        float sc[4] = {0,0,0,0};
        for (int dd = 0; dd < 64; dd++){
            float2 q2 = __half22float2(Q2[row*65 + dd]);
            #pragma unroll
            for (int j=0;j<4;j++){
                float2 k2 = __half22float2(K2[(j*32+lane)*65 + dd]);
                sc[j] = fmaf(q2.x, k2.x, sc[j]);
                sc[j] = fmaf(q2.y, k2.y, sc[j]);
            }
        }
        #pragma unroll
        for (int j=0;j<4;j++) sc[j] *= SCALEn;
        float m = fmaxf(fmaxf(sc[0],sc[1]), fmaxf(sc[2],sc[3]));
        m = warpMax(m);
        float l = 0.f;
        #pragma unroll
        for (int j=0;j<4;j++){ sc[j] = expf(sc[j]-m); l += sc[j]; }
        l = warpSum(l);
        float inv = 1.f / l;
        #pragma unroll
        for (int j=0;j<4;j++) Ps[wp*128 + j*32 + lane] = sc[j]*inv;
        __syncwarp();
        float accv[4] = {0,0,0,0};
        for (int kk=0;kk<64;kk++){
            float p0 = Ps[wp*128 + 2*kk], p1 = Ps[wp*128 + 2*kk + 1];
            #pragma unroll
            for (int j=0;j<4;j++){
                float2 v2 = __half22float2(V2[(j*32+lane)*65 + kk]);
                accv[j] = fmaf(p0, v2.x, accv[j]);
                accv[j] = fmaf(p1, v2.y, accv[j]);
            }
        }
        size_t orow = ((size_t)(b*Sn + w*WINn + row)) * Dn + (size_t)h*DHn;
        #pragma unroll
        for (int j=0;j<4;j++) out[orow + j*32 + lane] = __float2half_rn(accv[j]);
        __syncwarp();
    }
}

// ---------------- global-memory read attention (fp16 smem, V transposed) ----------------
__global__ __launch_bounds__(256)
void gatt_kernel(const __half* __restrict__ qg, const __half* __restrict__ kg,
                 const __half* __restrict__ vg, __half* __restrict__ rd)
{
    extern __shared__ char smraw[];
    __half* Qh = (__half*)smraw;
    __half* Kh = Qh + 64*130;
    __half* VT = Kh + 64*130;
    float*  Ps = (float*)(VT + 128*66);
    __half2* Q2 = (__half2*)Qh;
    __half2* K2 = (__half2*)Kh;
    __half2* V2 = (__half2*)VT;

    int bid = blockIdx.x;
    int qt = bid % (Sn/64);
    int h  = (bid / (Sn/64)) % Hn;
    int b  = bid / ((Sn/64) * Hn);
    int tid = threadIdx.x, lane = tid & 31, wp = tid >> 5;
    int s0 = qt * 64;

    for (int i = tid; i < 64*64; i += 256){
        int r = i >> 6, dc = i & 63, d2 = dc*2;
        __half2 q2 = *(const __half2*)(qg + ((size_t)(b*Sn + s0 + r))*Dn + h*DHn + d2);
        size_t gidx = ((size_t)(b*Mn + r))*Dn + h*DHn + d2;
        __half2 k2 = *(const __half2*)(kg + gidx);
        __half2 v2 = *(const __half2*)(vg + gidx);
        Q2[r*65 + dc] = q2;
        K2[r*65 + dc] = k2;
        VT[d2*66 + r]     = __low2half(v2);
        VT[(d2+1)*66 + r] = __high2half(v2);
    }
    __syncthreads();

    for (int row = wp; row < 64; row += 8){
        float sc[2] = {0,0};
        for (int dd = 0; dd < 64; dd++){
            float2 q2 = __half22float2(Q2[row*65 + dd]);
            #pragma unroll
            for (int j=0;j<2;j++){
                float2 k2 = __half22float2(K2[(j*32+lane)*65 + dd]);
                sc[j] = fmaf(q2.x, k2.x, sc[j]);
                sc[j] = fmaf(q2.y, k2.y, sc[j]);
            }
        }
        sc[0] *= SCALEn; sc[1] *= SCALEn;
        float m = warpMax(fmaxf(sc[0], sc[1]));
        float l = 0.f;
        #pragma unroll
        for (int j=0;j<2;j++){ sc[j] = expf(sc[j]-m); l += sc[j]; }
        l = warpSum(l);
        float inv = 1.f/l;
        #pragma unroll
        for (int j=0;j<2;j++) Ps[wp*64 + j*32 + lane] = sc[j]*inv;
        __syncwarp();
        float accv[4] = {0,0,0,0};
        for (int kk=0;kk<32;kk++){
            float p0 = Ps[wp*64 + 2*kk], p1 = Ps[wp*64 + 2*kk + 1];
            #pragma unroll
            for (int j=0;j<4;j++){
                float2 v2 = __half22float2(V2[(j*32+lane)*33 + kk]);
                accv[j] = fmaf(p0, v2.x, accv[j]);
                accv[j] = fmaf(p1, v2.y, accv[j]);
            }
        }
        size_t orow = ((size_t)(b*Sn + s0 + row))*Dn + (size_t)h*DHn;
        #pragma unroll
        for (int j=0;j<4;j++) rd[orow + j*32 + lane] = __float2half_rn(accv[j]);
        __syncwarp();
    }
}

// ---------------- memory-write attention: split-K partials ----------------
__global__ __launch_bounds__(256)
void matt_part_kernel(const __half* __restrict__ qm, const __half* __restrict__ km,
                      const __half* __restrict__ vm,
                      float* __restrict__ pm, float* __restrict__ pl,
                      float* __restrict__ pacc)
{
    extern __shared__ char smraw[];
    __half* Qm = (__half*)smraw;
    __half* Kc = Qm + 64*130;
    __half* VT = Kc + 128*130;
    float*  Ps = (float*)(VT + 128*130);
    __half2* Q2 = (__half2*)Qm;
    __half2* K2 = (__half2*)Kc;
    __half2* V2 = (__half2*)VT;

    int bid = blockIdx.x;
    int ch = bid & (NCH-1);
    int hb = bid >> 3;
    int h = hb % Hn, b = hb / Hn;
    int tid = threadIdx.x, lane = tid & 31, wp = tid >> 5;

    for (int i = tid; i < 64*64; i += 256){
        int r = i >> 6, dc = i & 63;
        Q2[r*65 + dc] = *(const __half2*)(qm + ((size_t)(b*Mn + r))*Dn + h*DHn + dc*2);
    }

    float mrun[8], lrun[8], accv[8][4];
    #pragma unroll
    for (int rr=0;rr<8;rr++){
        mrun[rr] = -1e30f; lrun[rr] = 0.f;
        #pragma unroll
        for (int j=0;j<4;j++) accv[rr][j] = 0.f;
    }

    int cBeg = ch * (Sn / NCH);
    for (int c0 = cBeg; c0 < cBeg + Sn/NCH; c0 += 128){
        __syncthreads();
        for (int i = tid; i < 128*64; i += 256){
            int r = i >> 6, dc = i & 63, d2 = dc*2;
            size_t gidx = ((size_t)(b*Sn + c0 + r))*Dn + h*DHn + d2;
            __half2 k2 = *(const __half2*)(km + gidx);
            __half2 v2 = *(const __half2*)(vm + gidx);
            K2[r*65 + dc] = k2;
            VT[d2*130 + r]     = __low2half(v2);
            VT[(d2+1)*130 + r] = __high2half(v2);
        }
        __syncthreads();

        #pragma unroll 1
        for (int rr=0;rr<8;rr++){
            int row = wp*8 + rr;
            float sc[4] = {0,0,0,0};
            for (int dd = 0; dd < 64; dd++){
                float2 q2 = __half22float2(Q2[row*65 + dd]);
                #pragma unroll
                for (int j=0;j<4;j++){
                    float2 k2 = __half22float2(K2[(j*32+lane)*65 + dd]);
                    sc[j] = fmaf(q2.x, k2.x, sc[j]);
                    sc[j] = fmaf(q2.y, k2.y, sc[j]);
                }
            }
            #pragma unroll
            for (int j=0;j<4;j++) sc[j] *= SCALEn;
            float cm = fmaxf(fmaxf(sc[0],sc[1]), fmaxf(sc[2],sc[3]));
            cm = warpMax(cm);
            float mn = fmaxf(mrun[rr], cm);
            float corr = expf(mrun[rr] - mn);
            float ls = 0.f;
            #pragma unroll
            for (int j=0;j<4;j++){ sc[j] = expf(sc[j]-mn); ls += sc[j]; }
            ls = warpSum(ls);
            lrun[rr] = lrun[rr]*corr + ls;
            mrun[rr] = mn;
            #pragma unroll
            for (int j=0;j<4;j++) accv[rr][j] *= corr;
            #pragma unroll
            for (int j=0;j<4;j++) Ps[wp*128 + j*32 + lane] = sc[j];
            __syncwarp();
            for (int kk=0;kk<64;kk++){
                float p0 = Ps[wp*128 + 2*kk], p1 = Ps[wp*128 + 2*kk + 1];
                #pragma unroll
                for (int j=0;j<4;j++){
                    float2 v2 = __half22float2(V2[(j*32+lane)*65 + kk]);
                    accv[rr][j] = fmaf(p0, v2.x, accv[rr][j]);
                    accv[rr][j] = fmaf(p1, v2.y, accv[rr][j]);
                }
            }
            __syncwarp();
        }
    }

    #pragma unroll
    for (int rr=0;rr<8;rr++){
        int row = wp*8 + rr;
        size_t p = ((size_t)(b*Hn + h)*NCH + ch)*Mn + row;
        if (lane == 0){ pm[p] = mrun[rr]; pl[p] = lrun[rr]; }
        #pragma unroll
        for (int j=0;j<4;j++)
            pacc[p*DHn + j*32 + lane] = accv[rr][j];
    }
}

// ---------------- matt merge ----------------
__global__ __launch_bounds__(256)
void matt_merge_kernel(const float* __restrict__ pm, const float* __restrict__ pl,
                       const float* __restrict__ pacc, __half* __restrict__ wr)
{
    int b = blockIdx.x / Hn, h = blockIdx.x % Hn;
    int tid = threadIdx.x, lane = tid & 31, wp = tid >> 5;
    size_t pb = (size_t)(b*Hn + h)*NCH;

    #pragma unroll 1
    for (int rr=0;rr<8;rr++){
        int row = wp*8 + rr;
        float M = -1e30f;
        float mv[NCH], lv[NCH];
        #pragma unroll
        for (int ccc=0; ccc<NCH; ccc++){
            mv[ccc] = pm[(pb + ccc)*Mn + row];
            lv[ccc] = pl[(pb + ccc)*Mn + row];
            M = fmaxf(M, mv[ccc]);
        }
        float L = 0.f, w[NCH];
        #pragma unroll
        for (int ccc=0; ccc<NCH; ccc++){
            w[ccc] = expf(mv[ccc] - M);
            L += w[ccc]*lv[ccc];
        }
        float invL = 1.f/L;
        #pragma unroll
        for (int j=0;j<4;j++){
            int d = j*32 + lane;
            float s = 0.f;
            #pragma unroll
            for (int ccc=0; ccc<NCH; ccc++)
                s += w[ccc]*pacc[((pb + ccc)*Mn + row)*DHn + d];
            wr[((size_t)(b*Mn + row))*Dn + h*DHn + d] = __float2half_rn(s*invL);
        }
    }
}

// ---------------- pooled mean: two-phase ----------------
__global__ __launch_bounds__(256)
void pooled_part_kernel(const float* __restrict__ gmg, float* __restrict__ pp)
{
    int d = blockIdx.x*256 + threadIdx.x;
    int b = blockIdx.y;
    int z = blockIdx.z;
    const float* p = gmg + (size_t)b*Sn*Dn + (size_t)z*(Sn/PCH)*Dn + d;
    float s = 0.f;
    for (int i=0;i<Sn/PCH;i++) s += p[(size_t)i*Dn];
    pp[((size_t)z*Bn + b)*Dn + d] = s;
}
__global__ __launch_bounds__(256)
void pooled_final_kernel(const float* __restrict__ pp, float* __restrict__ pooled)
{
    int d = blockIdx.x*256 + threadIdx.x;
    int b = blockIdx.y;
    float s = 0.f;
    #pragma unroll
    for (int z=0;z<PCH;z++) s += pp[((size_t)z*Bn + b)*Dn + d];
    pooled[b*Dn + d] = s * (1.0f/Sn);
}

__global__ __launch_bounds__(256)
void state_kernel(const float* __restrict__ pooled, const float* __restrict__ w_cz,
                  const float* __restrict__ w_cg, const float* __restrict__ cs,
                  float* __restrict__ state, float* __restrict__ out_state)
{
    int b = blockIdx.x, c = threadIdx.x;
    const float* pr = pooled + (size_t)b*Dn;
    float z = 0.f, gs = 0.f;
    for (int k=0;k<Dn;k++){
        float p = pr[k];
        z  = fmaf(p, w_cz[(size_t)k*Cn + c], z);
        gs = fmaf(p, w_cg[(size_t)k*Cn + c], gs);
    }
    float zt = tanhf(z);
    float gc = 1.f / (1.f + expf(-gs));
    float ns = gc * cs[b*Cn + c] + (1.f - gc) * zt;
    state[b*Cn + c] = ns;
    out_state[b*Cn + c] = ns;
}

__global__ __launch_bounds__(256)
void sp_kernel(const float* __restrict__ state, const float* __restrict__ w_sp,
               float* __restrict__ sp)
{
    int d = blockIdx.x*256 + threadIdx.x;
    int b = blockIdx.y;
    float s = 0.f;
    for (int c=0;c<Cn;c++) s = fmaf(state[b*Cn+c], w_sp[(size_t)c*Dn + d], s);
    sp[b*Dn + d] = s;
}

__global__ __launch_bounds__(256)
void spbias_kernel(const float* __restrict__ sp, const float* __restrict__ wf2,
                   float* __restrict__ bias)
{
    int n = blockIdx.x*256 + threadIdx.x;
    int b = blockIdx.y;
    const float* sr = sp + (size_t)b*Dn;
    float s = 0.f;
    for (int k=0;k<Dn;k++) s = fmaf(sr[k], wf2[(size_t)k*Dn + n], s);
    bias[b*Dn + n] = s;
}

// ---------------- host orchestration ----------------
#define TG1_SMEM (3*2*TG_ARR)   // 110592 (3-stage)
#define TG2_SMEM (2*3*TG_ARR)   // 110592 (2-stage)

static void tg1(const __half* A, const __half* W,
                float* C, int Mr, int Nc, int ldC, int K,
                int epi, const float* R1, const float* R2, __half* Hout,
                int seg = 0, int ldH = 0)
{
    if (!ldH) ldH = ldC;
    tgemm_kernel<1><<<dim3(Nc/128, Mr/128), 256, TG1_SMEM>>>(A, W, nullptr, C, ldC, K, epi, R1, R2, Hout, seg, ldH);
}
static void tg2(const __half* A, const __half* Wh, const __half* Wl,
                float* C, int Mr, int Nc, int ldC, int K,
                int epi, const float* R1, const float* R2, __half* Hout,
                int seg = 0, int ldH = 0)
{
    if (!ldH) ldH = ldC;
    tgemm_kernel<2><<<dim3(Nc/128, Mr/128), 256, TG2_SMEM>>>(A, Wh, Wl, C, ldC, K, epi, R1, R2, Hout, seg, ldH);
}
static void conv(const float* in, __half* hi, size_t n){
    conv_kernel<<<(unsigned)((n+1023)/1024), 256>>>(in, hi, n);
}
static void wconv(const float* W, __half* hi, __half* lo, int K, int N, int ldo = 0){
    if (!ldo) ldo = K;
    wconv_kernel<<<dim3(N/32, K/32), 256>>>(W, hi, lo, K, N, ldo);
}

template <typename T>
static T* sym(const void* symbol){ void* p; cudaGetSymbolAddress(&p, symbol); return (T*)p; }

extern "C" void kernel_launch(void* const* d_in, const int* in_sizes, int n_in,
                              void* d_out, int out_size)
{
    (void)in_sizes; (void)n_in; (void)out_size;
    const float* x      = (const float*)d_in[0];
    const float* gmem   = (const float*)d_in[1];
    const float* cstate = (const float*)d_in[2];
    const float* g1     = (const float*)d_in[3];
    const float* g2     = (const float*)d_in[4];
    const float* g3     = (const float*)d_in[5];
    const float* g4     = (const float*)d_in[6];
    const float* w_qkv  = (const float*)d_in[7];
    const float* w_lo   = (const float*)d_in[8];
    const float* w_gq   = (const float*)d_in[9];
    const float* w_gk   = (const float*)d_in[10];
    const float* w_gv   = (const float*)d_in[11];
    const float* w_go   = (const float*)d_in[12];
    const float* w_gate = (const float*)d_in[13];
    const float* w_mq   = (const float*)d_in[14];
    const float* w_mk   = (const float*)d_in[15];
    const float* w_mv   = (const float*)d_in[16];
    const float* w_mo   = (const float*)d_in[17];
    const float* w_cz   = (const float*)d_in[18];
    const float* w_cg   = (const float*)d_in[19];
    const float* w_sp   = (const float*)d_in[20];
    const float* w_fuse = (const float*)d_in[21];
    const float* w_ff1  = (const float*)d_in[22];
    const float* w_ff2  = (const float*)d_in[23];
    float* out = (float*)d_out;

    float* h1    = sym<float>(g_h1);
    float* lcp   = sym<float>(g_lcp);
    float* h2    = sym<float>(g_h2);
    float* gate  = sym<float>(g_gate);
    float* gmgv  = sym<float>(g_gmg);
    float* pool  = sym<float>(g_pool);
    float* pp    = sym<float>(g_pp);
    float* state = sym<float>(g_state);
    float* sp    = sym<float>(g_sp);
    float* bias  = sym<float>(g_bias);
    float* fused = sym<float>(g_fused);
    float* hv    = sym<float>(g_h);
    float* pm    = sym<float>(g_pm);
    float* pl    = sym<float>(g_pl);
    float* pacc  = sym<float>(g_pacc);

    __half* ch1  = sym<__half>(c_h1);
    __half* ch2  = sym<__half>(c_h2);
    __half* cgm  = sym<__half>(c_gm);
    __half* cqkv = sym<__half>(c_qkv);
    __half* cat  = sym<__half>(c_atto);
    __half* cqg  = sym<__half>(c_qg);
    __half* ckvq = sym<__half>(c_kvq);
    __half* ckm  = sym<__half>(c_km);
    __half* cvm  = sym<__half>(c_vm);
    __half* crd  = sym<__half>(c_rd);
    __half* cf01 = sym<__half>(c_f01);
    __half* ch4  = sym<__half>(c_h4);
    __half* cffa = sym<__half>(c_ffa);
    __half* cwr  = sym<__half>(c_wr);
    __half* tqkv = sym<__half>(t_qkv);
    __half* tgq  = sym<__half>(t_gq);
    __half* tmk  = sym<__half>(t_mk);
    __half* tlo  = sym<__half>(t_lo);
    __half* tgt  = sym<__half>(t_gate);
    __half* tgo  = sym<__half>(t_go);
    __half* tmv  = sym<__half>(t_mv);
    __half* tf01 = sym<__half>(t_f01);
    __half* tgm3 = sym<__half>(t_gm3);
    __half* tmo  = sym<__half>(t_mo);
    __half* tff1 = sym<__half>(t_ff1);
    __half* tff2 = sym<__half>(t_ff2);

    const size_t W1 = (size_t)Dn*Dn;
    const size_t WQ = (size_t)3*Dn*Dn;

    const int LATT_SMEM = 3*128*130*2 + 8*128*4;
    const int GATT_SMEM = 2*64*130*2 + 128*66*2 + 8*64*4;
    const int MATT_SMEM = 64*130*2 + 2*128*130*2 + 8*128*4;
    cudaFuncSetAttribute(latt_kernel, cudaFuncAttributeMaxDynamicSharedMemorySize, LATT_SMEM);
    cudaFuncSetAttribute(gatt_kernel, cudaFuncAttributeMaxDynamicSharedMemorySize, GATT_SMEM);
    cudaFuncSetAttribute(matt_part_kernel, cudaFuncAttributeMaxDynamicSharedMemorySize, MATT_SMEM);
    cudaFuncSetAttribute(tgemm_kernel<1>, cudaFuncAttributeMaxDynamicSharedMemorySize, TG1_SMEM);
    cudaFuncSetAttribute(tgemm_kernel<2>, cudaFuncAttributeMaxDynamicSharedMemorySize, TG2_SMEM);

    // ---- front: qkv path first (launch #5 = P1 tgemm) ----
    wconv(w_qkv, tqkv, tqkv + WQ, Dn, 3*Dn);                        // 0
    rmsnorm_kernel<<<ROWS, 256>>>(x, g1, h1, ch1, 0);               // 1
    wconv(w_lo,  tlo,  nullptr, Dn, Dn);                            // 2
    tg2(ch1, tqkv, tqkv + WQ, nullptr, ROWS, 3*Dn, 3*Dn, Dn, 0, nullptr, nullptr, cqkv); // 3
    latt_kernel<<<Bn*nWn*Hn, 256, LATT_SMEM>>>(cqkv, cat);          // 4
    tg1(cat, tlo, lcp, ROWS, Dn, Dn, Dn, 1, x, nullptr, cf01, 0, 2*Dn); // 5 <- profiled

    // ---- remaining weight converts ----
    wconv(w_gq,   tgq,  tgq + W1, Dn, Dn);
    wconv(w_mk,   tmk,  tmk + W1, Dn, Dn);
    wconv(w_gate, tgt,  nullptr, Dn, Dn);
    wconv(w_go,   tgo,  nullptr, Dn, Dn);
    wconv(w_mv,   tmv,  nullptr, Dn, Dn);
    wconv(w_fuse,      tf01,      nullptr, Dn, Dn, 2*Dn);
    wconv(w_fuse + W1, tf01 + Dn, nullptr, Dn, Dn, 2*Dn);
    wconv(w_gk,   tgm3,          nullptr, Dn, Dn);
    wconv(w_gv,   tgm3 + W1,     nullptr, Dn, Dn);
    wconv(w_mq,   tgm3 + 2*W1,   nullptr, Dn, Dn);
    wconv(w_mo,   tmo,  nullptr, Dn, Dn);
    wconv(w_ff1,  tff1, nullptr, Dn, FFn);
    wconv(w_ff2,  tff2, nullptr, FFn, Dn);
    conv(gmem, cgm, GM_ELEMS);

    // 5) h2 = rmsnorm(lcp, g2)
    rmsnorm_kernel<<<ROWS, 256>>>(lcp, g2, h2, ch2, 0);
    // 6) qg ; batched kg|vg|qm (segmented epilogue)
    tg2(ch2, tgq, tgq + W1, nullptr, ROWS, Dn, Dn, Dn, 0, nullptr, nullptr, cqg);
    tg1(cgm, tgm3, nullptr, Bn*Mn, 3*Dn, Dn, Dn, 0, nullptr, nullptr, ckvq, 1);
    // 7) read attention
    gatt_kernel<<<Bn*Hn*(Sn/64), 256, GATT_SMEM>>>(cqg, ckvq, ckvq + GM_ELEMS, crd);
    // 8) gate / gmg (gmg fp16 goes into cf01 cols 2048..4095)
    tg1(ch2, tgt, gate, ROWS, Dn, Dn, Dn, 2, nullptr, nullptr, nullptr);
    tg1(crd, tgo, gmgv, ROWS, Dn, Dn, Dn, 3, h2, gate, cf01 + Dn, 0, 2*Dn);
    // 9) km / vm
    tg2(ch2, tmk, tmk + W1, nullptr, ROWS, Dn, Dn, Dn, 0, nullptr, nullptr, ckm);
    tg1(ch2, tmv, nullptr, ROWS, Dn, Dn, Dn, 0, nullptr, nullptr, cvm);
    // 10) memory-write attention: split-K + merge
    matt_part_kernel<<<Bn*Hn*NCH, 256, MATT_SMEM>>>(ckvq + 2*GM_ELEMS, ckm, cvm, pm, pl, pacc);
    matt_merge_kernel<<<Bn*Hn, 256>>>(pm, pl, pacc, cwr);
    // 11) new_memory
    tg1(cwr, tmo, out + OUT_ELEMS, Bn*Mn, Dn, Dn, Dn, 1, gmem, nullptr, nullptr);
    // 12) pooled (two-phase) / state / sp / bias
    pooled_part_kernel<<<dim3(Dn/256, Bn, PCH), 256>>>(gmgv, pp);
    pooled_final_kernel<<<dim3(Dn/256, Bn), 256>>>(pp, pool);
    state_kernel<<<Bn, Cn>>>(pool, w_cz, w_cg, cstate, state, out + OUT_ELEMS + MEM_ELEMS);
    sp_kernel<<<dim3(Dn/256, Bn), 256>>>(state, w_sp, sp);
    spbias_kernel<<<dim3(Dn/256, Bn), 256>>>(sp, w_fuse + (size_t)2*Dn*Dn, bias);
    // 13) fused = [lcp|gmg] @ [Wf0;Wf1] + bias[b]  (single K=4096 GEMM)
    tg1(cf01, tf01, fused, ROWS, Dn, Dn, 2*Dn, 6, bias, nullptr, nullptr);
    // 14) h / h4 fused: hv = fused + norm(fused)*g3 ; ch4 = fp16(norm(hv)*g4)
    rmsnorm2_kernel<<<ROWS, 256>>>(fused, g3, g4, hv, ch4);
    // 15) FFN
    tg1(ch4, tff1, nullptr, ROWS, FFn, FFn, Dn, 4, nullptr, nullptr, cffa);
    tg1(cffa, tff2, out, ROWS, Dn, Dn, FFn, 1, hv, nullptr, nullptr);
}

// round 17
// speedup vs baseline: 1.1058x; 1.0271x over previous
#include <cuda_runtime.h>
#include <cuda_fp16.h>
#include <math.h>
#include <stdint.h>

// ---------------- problem constants ----------------
#define Bn   4
#define Sn   2048
#define Dn   2048
#define Hn   16
#define DHn  128
#define WINn 128
#define nWn  16
#define Mn   64
#define Cn   256
#define FFn  8192
#define EPSn 1e-6f
#define SCALEn 0.08838834764831843f   // 1/sqrt(128)

#define ROWS (Bn*Sn)                  // 8192
#define OUT_ELEMS  ((size_t)Bn*Sn*Dn)
#define MEM_ELEMS  ((size_t)Bn*Mn*Dn)
#define GM_ELEMS   ((size_t)Bn*Mn*Dn)
#define NCH  8                        // matt key chunks
#define PCH  16                       // pooled S chunks

// ---------------- fp32 scratch ----------------
__device__ float g_lcp  [ROWS*Dn];
__device__ float g_h2   [ROWS*Dn];
__device__ float g_gate [ROWS*Dn];
__device__ float g_gmg  [ROWS*Dn];
__device__ float g_pool [Bn*Dn];
__device__ float g_pp   [PCH*Bn*Dn];
__device__ float g_state[Bn*Cn];
__device__ float g_sp   [Bn*Dn];
__device__ float g_bias [Bn*Dn];
__device__ float g_fused[ROWS*Dn];
__device__ float g_h    [ROWS*Dn];
// matt split-K partials
__device__ float g_pm   [Bn*Hn*NCH*Mn];
__device__ float g_pl   [Bn*Hn*NCH*Mn];
__device__ float g_pacc [(size_t)Bn*Hn*NCH*Mn*DHn];

// ---------------- fp16 scratch ----------------
#define AD __device__ __align__(256)
AD __half c_h1  [(size_t)ROWS*Dn];
AD __half c_h2  [(size_t)ROWS*Dn];
AD __half c_gm  [GM_ELEMS];
AD __half c_qkv [(size_t)ROWS*3*Dn];
AD __half c_atto[(size_t)ROWS*Dn];
AD __half c_qg  [(size_t)ROWS*Dn];
AD __half c_kvq [3*GM_ELEMS];            // kg | vg | qm
AD __half c_km  [(size_t)ROWS*Dn];
AD __half c_vm  [(size_t)ROWS*Dn];
AD __half c_rd  [(size_t)ROWS*Dn];
AD __half c_f01 [(size_t)ROWS*2*Dn];     // [lcp | gmg] fp16, ld 4096
AD __half c_h4  [(size_t)ROWS*Dn];
AD __half c_ffa [(size_t)ROWS*FFn];
AD __half c_wr  [GM_ELEMS];
// transposed weights [N][K]; [2] = hi/lo (lo only for qkv/gq/mk)
AD __half t_qkv [2][(size_t)3*Dn*Dn];
AD __half t_gq  [2][(size_t)Dn*Dn];
AD __half t_mk  [2][(size_t)Dn*Dn];
AD __half t_lo  [(size_t)Dn*Dn];
AD __half t_gate[(size_t)Dn*Dn];
AD __half t_go  [(size_t)Dn*Dn];
AD __half t_mv  [(size_t)Dn*Dn];
AD __half t_f01 [(size_t)Dn*2*Dn];       // [2048 N][4096 K]: fuse0 | fuse1 along K
AD __half t_gm3 [(size_t)3*Dn*Dn];       // gk | gv | mq
AD __half t_mo  [(size_t)Dn*Dn];
AD __half t_ff1 [(size_t)FFn*Dn];
AD __half t_ff2 [(size_t)Dn*FFn];

// ---------------- helpers ----------------
__device__ __forceinline__ float warpMax(float v){
    #pragma unroll
    for (int o=16;o;o>>=1) v = fmaxf(v, __shfl_xor_sync(0xffffffffu, v, o));
    return v;
}
__device__ __forceinline__ float warpSum(float v){
    #pragma unroll
    for (int o=16;o;o>>=1) v += __shfl_xor_sync(0xffffffffu, v, o);
    return v;
}
__device__ __forceinline__ float gelu_tanh(float v){
    const float c0 = 0.7978845608028654f;
    float t = tanhf(c0 * (v + 0.044715f * v * v * v));
    return 0.5f * v * (1.0f + t);
}
__device__ __forceinline__ uint32_t smem_u32(const void* p){
    uint32_t a;
    asm("{ .reg .u64 t; cvta.to.shared.u64 t, %1; cvt.u32.u64 %0, t; }" : "=r"(a) : "l"(p));
    return a;
}
__device__ __forceinline__ void cpa16(uint32_t d, const void* g){
    asm volatile("cp.async.cg.shared.global [%0], [%1], 16;" :: "r"(d), "l"(g));
}
__device__ __forceinline__ void cpa_commit(){ asm volatile("cp.async.commit_group;" ::: "memory"); }
template<int NN> __device__ __forceinline__ void cpa_wait(){
    asm volatile("cp.async.wait_group %0;" :: "n"(NN) : "memory");
}
__device__ __forceinline__ void ldm4(uint32_t* r, uint32_t addr){
    asm volatile("ldmatrix.sync.aligned.m8n8.x4.shared.b16 {%0,%1,%2,%3}, [%4];"
        : "=r"(r[0]),"=r"(r[1]),"=r"(r[2]),"=r"(r[3]) : "r"(addr));
}
__device__ __forceinline__ void mma_f16(float* c, const uint32_t* a, uint32_t b0, uint32_t b1){
    asm volatile("mma.sync.aligned.m16n8k16.row.col.f32.f16.f16.f32 "
        "{%0,%1,%2,%3}, {%4,%5,%6,%7}, {%8,%9}, {%0,%1,%2,%3};"
        : "+f"(c[0]),"+f"(c[1]),"+f"(c[2]),"+f"(c[3])
        : "r"(a[0]),"r"(a[1]),"r"(a[2]),"r"(a[3]), "r"(b0),"r"(b1));
}

// ---------------- tensor GEMM via mma.sync (BK=64; TM rows x 128 cols; single sync/chunk) ----------------
#define TG_B_ARR 18432                  // 128 rows * 72 halfs * 2B
template<int P, int TM>
__global__ void __launch_bounds__(256, 2)
tgemm_kernel(const __half* __restrict__ Ahi,
             const __half* __restrict__ Bhi, const __half* __restrict__ Blo,
             float* __restrict__ C, int ldC, int K,
             int epi, const float* __restrict__ R1, const float* __restrict__ R2,
             __half* __restrict__ Hout, int seg, int ldH)
{
    constexpr int NARR = (P == 2) ? 3 : 2;
    constexpr int A_SZ = TM * 144;
    constexpr int STG  = A_SZ + (NARR - 1) * TG_B_ARR;
    constexpr int MT   = TM / 32;
    extern __shared__ char smem[];
    uint32_t sb = smem_u32(smem);
    const int tid = threadIdx.x, lane = tid & 31, wid = tid >> 5;
    const int warpM = wid >> 2, warpN = wid & 3;
    const int rowBase = blockIdx.y * TM, colBase = blockIdx.x * 128;

    const __half* srcA = Ahi + (size_t)rowBase * K;
    const __half* srcB = Bhi + (size_t)colBase * K;
    const __half* srcL = (P == 2) ? Blo + (size_t)colBase * K : nullptr;

    auto prefetch = [&](int c, int s){
        size_t koff = (size_t)c * 64;
        uint32_t sbase = sb + s*STG;
        const __half* ga = srcA + koff;
        #pragma unroll
        for (int q = 0; q < TM/32; q++){
            int i = tid + q*256;
            int r = i >> 3, sg = i & 7;
            cpa16(sbase + r*144 + sg*16, ga + (size_t)r*K + sg*8);
        }
        const __half* gb = srcB + koff;
        #pragma unroll
        for (int q = 0; q < 4; q++){
            int i = tid + q*256;
            int r = i >> 3, sg = i & 7;
            cpa16(sbase + A_SZ + r*144 + sg*16, gb + (size_t)r*K + sg*8);
        }
        if (P == 2){
            const __half* gl = srcL + koff;
            #pragma unroll
            for (int q = 0; q < 4; q++){
                int i = tid + q*256;
                int r = i >> 3, sg = i & 7;
                cpa16(sbase + A_SZ + TG_B_ARR + r*144 + sg*16, gl + (size_t)r*K + sg*8);
            }
        }
    };

    const int lrow = lane & 15, lhalf = (lane >> 4) << 3;
    uint32_t aoff[MT], boff[2];
    #pragma unroll
    for (int mt = 0; mt < MT; mt++) aoff[mt] = (warpM*(TM/2) + mt*16 + lrow)*144 + lhalf*2;
    #pragma unroll
    for (int np = 0; np < 2; np++) boff[np] = A_SZ + (warpN*32 + np*16 + lrow)*144 + lhalf*2;

    float acc[MT][4][4];
    #pragma unroll
    for (int a=0;a<MT;a++)
        #pragma unroll
        for (int b=0;b<4;b++)
            #pragma unroll
            for (int q=0;q<4;q++) acc[a][b][q] = 0.f;

    auto compute = [&](uint32_t sA){
        #pragma unroll
        for (int ks = 0; ks < 4; ks++){
            const uint32_t kadd = ks * 32;
            uint32_t bh[2][4], bl[2][4];
            #pragma unroll
            for (int np = 0; np < 2; np++){
                uint32_t a = sA + boff[np] + kadd;
                ldm4(bh[np], a);
                if (P == 2) ldm4(bl[np], a + TG_B_ARR);
            }
            #pragma unroll
            for (int mg = 0; mg < MT/2; mg++){
                uint32_t ah[2][4];
                #pragma unroll
                for (int mt = 0; mt < 2; mt++)
                    ldm4(ah[mt], sA + aoff[mg*2+mt] + kadd);
                #pragma unroll
                for (int mt = 0; mt < 2; mt++)
                    #pragma unroll
                    for (int nt = 0; nt < 4; nt++){
                        int np = nt >> 1, hh = nt & 1;
                        mma_f16(acc[mg*2+mt][nt], ah[mt], bh[np][hh], bh[np][2+hh]);
                    }
                if (P == 2){
                    #pragma unroll
                    for (int mt = 0; mt < 2; mt++)
                        #pragma unroll
                        for (int nt = 0; nt < 4; nt++){
                            int np = nt >> 1, hh = nt & 1;
                            mma_f16(acc[mg*2+mt][nt], ah[mt], bl[np][hh], bl[np][2+hh]);
                        }
                }
            }
        }
    };

    const int nCh = K >> 6;
    if (P == 1){
        // 3-stage, single sync per chunk
        prefetch(0, 0); cpa_commit();
        prefetch(1, 1); cpa_commit();
        uint32_t sA = sb;
        int s2 = 2;
        for (int c = 0; c < nCh; c++){
            if (c + 1 < nCh) cpa_wait<1>(); else cpa_wait<0>();
            __syncthreads();
            if (c + 2 < nCh){ prefetch(c+2, s2); cpa_commit(); s2 = (s2 == 2) ? 0 : s2 + 1; }
            compute(sA);
            sA += STG;
            if (sA == sb + 3*STG) sA = sb;
        }
    } else {
        // 2-stage, single sync per chunk (prefetch AFTER barrier)
        prefetch(0, 0); cpa_commit();
        for (int c = 0; c < nCh; c++){
            cpa_wait<0>();
            __syncthreads();
            if (c + 1 < nCh){ prefetch(c+1, (c+1)&1); cpa_commit(); }
            compute(sb + (c&1)*STG);
        }
    }

    // epilogue
    #pragma unroll
    for (int mt = 0; mt < MT; mt++){
        #pragma unroll
        for (int nt = 0; nt < 4; nt++){
            int r0 = rowBase + warpM*(TM/2) + mt*16 + (lane >> 2);
            int col = colBase + warpN*32 + nt*8 + (lane & 3)*2;
            #pragma unroll
            for (int hh = 0; hh < 2; hh++){
                int row = r0 + hh*8;
                size_t idx, hidx;
                if (seg){
                    idx = hidx = (size_t)(col >> 11)*GM_ELEMS + (size_t)row*Dn + (col & 2047);
                } else {
                    idx = (size_t)row * ldC + col;
                    hidx = (size_t)row * ldH + col;
                }
                float v0 = acc[mt][nt][hh*2+0];
                float v1 = acc[mt][nt][hh*2+1];
                if      (epi == 1){ v0 += R1[idx]; v1 += R1[idx+1]; }
                else if (epi == 2){ v0 = 1.f/(1.f+expf(-v0)); v1 = 1.f/(1.f+expf(-v1)); }
                else if (epi == 3){ v0 = R1[idx] + R2[idx]*v0; v1 = R1[idx+1] + R2[idx+1]*v1; }
                else if (epi == 4){ v0 = gelu_tanh(v0); v1 = gelu_tanh(v1); }
                else if (epi == 6){
                    size_t bidx = (size_t)(row >> 11) * ldC + col;
                    v0 += R1[bidx]; v1 += R1[bidx+1];
                }
                if (C) *(float2*)(C + idx) = make_float2(v0, v1);
                if (Hout) *(__half2*)(Hout + hidx) = __halves2half2(__float2half_rn(v0), __float2half_rn(v1));
            }
        }
    }
}

// ---------------- convert: fp32 -> fp16 ----------------
__global__ __launch_bounds__(256)
void conv_kernel(const float* __restrict__ in, __half* __restrict__ hi, size_t n)
{
    size_t i = ((size_t)blockIdx.x * 256 + threadIdx.x) * 4;
    if (i >= n) return;
    float4 v = *(const float4*)(in + i);
    __half2* ph = (__half2*)(hi + i);
    ph[0] = __halves2half2(__float2half_rn(v.x), __float2half_rn(v.y));
    ph[1] = __halves2half2(__float2half_rn(v.z), __float2half_rn(v.w));
}

// ---------------- weight transpose-convert (output stride ldo) ----------------
__global__ __launch_bounds__(256)
void wconv_kernel(const float* __restrict__ W, __half* __restrict__ hi,
                  __half* __restrict__ lo, int K, int N, int ldo)
{
    __shared__ float t[32][33];
    int n0 = blockIdx.x * 32, k0 = blockIdx.y * 32;
    int tx = threadIdx.x & 31, ty = threadIdx.x >> 5;
    #pragma unroll
    for (int r = ty; r < 32; r += 8)
        t[r][tx] = W[(size_t)(k0 + r) * N + n0 + tx];
    __syncthreads();
    #pragma unroll
    for (int r = ty; r < 32; r += 8){
        float v = t[tx][r];
        size_t o = (size_t)(n0 + r) * ldo + k0 + tx;
        __half h = __float2half_rn(v);
        hi[o] = h;
        if (lo) lo[o] = __float2half_rn(v - __half2float(h));
    }
}

// ---------------- rmsnorm (fp32 out optional) ----------------
__global__ __launch_bounds__(256)
void rmsnorm_kernel(const float* __restrict__ in, const float* __restrict__ g,
                    float* __restrict__ out, __half* __restrict__ hi, int mode)
{
    __shared__ float red[256];
    int row = blockIdx.x, tid = threadIdx.x;
    const float* xr = in + (size_t)row * Dn;
    float4 xa = *(const float4*)(xr + tid*4);
    float4 xb = *(const float4*)(xr + 1024 + tid*4);
    float ss = xa.x*xa.x + xa.y*xa.y + xa.z*xa.z + xa.w*xa.w
             + xb.x*xb.x + xb.y*xb.y + xb.z*xb.z + xb.w*xb.w;
    red[tid] = ss; __syncthreads();
    for (int o=128;o;o>>=1){ if (tid < o) red[tid] += red[tid+o]; __syncthreads(); }
    float inv = rsqrtf(red[0] * (1.0f/Dn) + EPSn);
    #pragma unroll
    for (int half_ = 0; half_ < 2; half_++){
        float4 xv = half_ ? xb : xa;
        int d = half_*1024 + tid*4;
        float4 gv = *(const float4*)(g + d);
        float4 ov;
        ov.x = xv.x*inv*gv.x; ov.y = xv.y*inv*gv.y;
        ov.z = xv.z*inv*gv.z; ov.w = xv.w*inv*gv.w;
        if (mode){ ov.x += xv.x; ov.y += xv.y; ov.z += xv.z; ov.w += xv.w; }
        if (out) *(float4*)(out + (size_t)row*Dn + d) = ov;
        if (hi){
            __half2* ph = (__half2*)(hi + (size_t)row*Dn + d);
            ph[0] = __halves2half2(__float2half_rn(ov.x), __float2half_rn(ov.y));
            ph[1] = __halves2half2(__float2half_rn(ov.z), __float2half_rn(ov.w));
        }
    }
}

// ---------------- fused double rmsnorm ----------------
__global__ __launch_bounds__(256)
void rmsnorm2_kernel(const float* __restrict__ in, const float* __restrict__ g3,
                     const float* __restrict__ g4, float* __restrict__ hvout,
                     __half* __restrict__ h4h)
{
    __shared__ float red[256];
    int row = blockIdx.x, tid = threadIdx.x;
    const float* xr = in + (size_t)row * Dn;
    float4 xa = *(const float4*)(xr + tid*4);
    float4 xb = *(const float4*)(xr + 1024 + tid*4);
    float ss = xa.x*xa.x + xa.y*xa.y + xa.z*xa.z + xa.w*xa.w
             + xb.x*xb.x + xb.y*xb.y + xb.z*xb.z + xb.w*xb.w;
    red[tid] = ss; __syncthreads();
    for (int o=128;o;o>>=1){ if (tid < o) red[tid] += red[tid+o]; __syncthreads(); }
    float inv1 = rsqrtf(red[0] * (1.0f/Dn) + EPSn);

    float4 ga3 = *(const float4*)(g3 + tid*4);
    float4 gb3 = *(const float4*)(g3 + 1024 + tid*4);
    float4 ha, hb;
    ha.x = xa.x + xa.x*inv1*ga3.x; ha.y = xa.y + xa.y*inv1*ga3.y;
    ha.z = xa.z + xa.z*inv1*ga3.z; ha.w = xa.w + xa.w*inv1*ga3.w;
    hb.x = xb.x + xb.x*inv1*gb3.x; hb.y = xb.y + xb.y*inv1*gb3.y;
    hb.z = xb.z + xb.z*inv1*gb3.z; hb.w = xb.w + xb.w*inv1*gb3.w;
    float* hrow = hvout + (size_t)row * Dn;
    *(float4*)(hrow + tid*4) = ha;
    *(float4*)(hrow + 1024 + tid*4) = hb;
    float ss2 = ha.x*ha.x + ha.y*ha.y + ha.z*ha.z + ha.w*ha.w
              + hb.x*hb.x + hb.y*hb.y + hb.z*hb.z + hb.w*hb.w;
    __syncthreads();
    red[tid] = ss2; __syncthreads();
    for (int o=128;o;o>>=1){ if (tid < o) red[tid] += red[tid+o]; __syncthreads(); }
    float inv2 = rsqrtf(red[0] * (1.0f/Dn) + EPSn);

    float4 ga4 = *(const float4*)(g4 + tid*4);
    float4 gb4 = *(const float4*)(g4 + 1024 + tid*4);
    __half2* ph = (__half2*)(h4h + (size_t)row*Dn + tid*4);
    ph[0] = __halves2half2(__float2half_rn(ha.x*inv2*ga4.x), __float2half_rn(ha.y*inv2*ga4.y));
    ph[1] = __halves2half2(__float2half_rn(ha.z*inv2*ga4.z), __float2half_rn(ha.w*inv2*ga4.w));
    __half2* ph2 = (__half2*)(h4h + (size_t)row*Dn + 1024 + tid*4);
    ph2[0] = __halves2half2(__float2half_rn(hb.x*inv2*gb4.x), __float2half_rn(hb.y*inv2*gb4.y));
    ph2[1] = __halves2half2(__float2half_rn(hb.z*inv2*gb4.z), __float2half_rn(hb.w*inv2*gb4.w));
}

// ---------------- local window attention (fp16 smem, V transposed) ----------------
__global__ __launch_bounds__(256)
void latt_kernel(const __half* __restrict__ qkv, __half* __restrict__ out)
{
    extern __shared__ char smraw[];
    __half* Qh = (__half*)smraw;
    __half* Kh = Qh + 128*130;
    __half* VT = Kh + 128*130;
    float*  Ps = (float*)(VT + 128*130);
    __half2* Q2 = (__half2*)Qh;
    __half2* K2 = (__half2*)Kh;
    __half2* V2 = (__half2*)VT;

    int bid = blockIdx.x;
    int h = bid % Hn;
    int w = (bid / Hn) % nWn;
    int b = bid / (Hn * nWn);
    int tid = threadIdx.x, lane = tid & 31, wp = tid >> 5;

    size_t base = ((size_t)(b*Sn + w*WINn)) * (3*Dn) + (size_t)h * DHn;
    for (int i = tid; i < 128*64; i += 256){
        int r = i >> 6, dc = i & 63, d2 = dc*2;
        size_t gidx = base + (size_t)r * (3*Dn) + d2;
        __half2 q2 = *(const __half2*)(qkv + gidx);
        __half2 k2 = *(const __half2*)(qkv + gidx + Dn);
        __half2 v2 = *(const __half2*)(qkv + gidx + 2*Dn);
        Q2[r*65 + dc] = q2;
        K2[r*65 + dc] = k2;
        VT[d2*130 + r]     = __low2half(v2);
        VT[(d2+1)*130 + r] = __high2half(v2);
    }
    __syncthreads();

    for (int row = wp; row < 128; row += 8){
        float sc[4] = {0,0,0,0};
        for (int dd = 0; dd < 64; dd++){
            float2 q2 = __half22float2(Q2[row*65 + dd]);
            #pragma unroll
            for (int j=0;j<4;j++){
                float2 k2 = __half22float2(K2[(j*32+lane)*65 + dd]);
                sc[j] = fmaf(q2.x, k2.x, sc[j]);
                sc[j] = fmaf(q2.y, k2.y, sc[j]);
            }
        }
        #pragma unroll
        for (int j=0;j<4;j++) sc[j] *= SCALEn;
        float m = fmaxf(fmaxf(sc[0],sc[1]), fmaxf(sc[2],sc[3]));
        m = warpMax(m);
        float l = 0.f;
        #pragma unroll
        for (int j=0;j<4;j++){ sc[j] = expf(sc[j]-m); l += sc[j]; }
        l = warpSum(l);
        float inv = 1.f / l;
        #pragma unroll
        for (int j=0;j<4;j++) Ps[wp*128 + j*32 + lane] = sc[j]*inv;
        __syncwarp();
        float accv[4] = {0,0,0,0};
        for (int kk=0;kk<64;kk++){
            float p0 = Ps[wp*128 + 2*kk], p1 = Ps[wp*128 + 2*kk + 1];
            #pragma unroll
            for (int j=0;j<4;j++){
                float2 v2 = __half22float2(V2[(j*32+lane)*65 + kk]);
                accv[j] = fmaf(p0, v2.x, accv[j]);
                accv[j] = fmaf(p1, v2.y, accv[j]);
            }
        }
        size_t orow = ((size_t)(b*Sn + w*WINn + row)) * Dn + (size_t)h*DHn;
        #pragma unroll
        for (int j=0;j<4;j++) out[orow + j*32 + lane] = __float2half_rn(accv[j]);
        __syncwarp();
    }
}

// ---------------- global-memory read attention (fp16 smem, V transposed) ----------------
__global__ __launch_bounds__(256)
void gatt_kernel(const __half* __restrict__ qg, const __half* __restrict__ kg,
                 const __half* __restrict__ vg, __half* __restrict__ rd)
{
    extern __shared__ char smraw[];
    __half* Qh = (__half*)smraw;
    __half* Kh = Qh + 64*130;
    __half* VT = Kh + 64*130;
    float*  Ps = (float*)(VT + 128*66);
    __half2* Q2 = (__half2*)Qh;
    __half2* K2 = (__half2*)Kh;
    __half2* V2 = (__half2*)VT;

    int bid = blockIdx.x;
    int qt = bid % (Sn/64);
    int h  = (bid / (Sn/64)) % Hn;
    int b  = bid / ((Sn/64) * Hn);
    int tid = threadIdx.x, lane = tid & 31, wp = tid >> 5;
    int s0 = qt * 64;

    for (int i = tid; i < 64*64; i += 256){
        int r = i >> 6, dc = i & 63, d2 = dc*2;
        __half2 q2 = *(const __half2*)(qg + ((size_t)(b*Sn + s0 + r))*Dn + h*DHn + d2);
        size_t gidx = ((size_t)(b*Mn + r))*Dn + h*DHn + d2;
        __half2 k2 = *(const __half2*)(kg + gidx);
        __half2 v2 = *(const __half2*)(vg + gidx);
        Q2[r*65 + dc] = q2;
        K2[r*65 + dc] = k2;
        VT[d2*66 + r]     = __low2half(v2);
        VT[(d2+1)*66 + r] = __high2half(v2);
    }
    __syncthreads();

    for (int row = wp; row < 64; row += 8){
        float sc[2] = {0,0};
        for (int dd = 0; dd < 64; dd++){
            float2 q2 = __half22float2(Q2[row*65 + dd]);
            #pragma unroll
            for (int j=0;j<2;j++){
                float2 k2 = __half22float2(K2[(j*32+lane)*65 + dd]);
                sc[j] = fmaf(q2.x, k2.x, sc[j]);
                sc[j] = fmaf(q2.y, k2.y, sc[j]);
            }
        }
        sc[0] *= SCALEn; sc[1] *= SCALEn;
        float m = warpMax(fmaxf(sc[0], sc[1]));
        float l = 0.f;
        #pragma unroll
        for (int j=0;j<2;j++){ sc[j] = expf(sc[j]-m); l += sc[j]; }
        l = warpSum(l);
        float inv = 1.f/l;
        #pragma unroll
        for (int j=0;j<2;j++) Ps[wp*64 + j*32 + lane] = sc[j]*inv;
        __syncwarp();
        float accv[4] = {0,0,0,0};
        for (int kk=0;kk<32;kk++){
            float p0 = Ps[wp*64 + 2*kk], p1 = Ps[wp*64 + 2*kk + 1];
            #pragma unroll
            for (int j=0;j<4;j++){
                float2 v2 = __half22float2(V2[(j*32+lane)*33 + kk]);
                accv[j] = fmaf(p0, v2.x, accv[j]);
                accv[j] = fmaf(p1, v2.y, accv[j]);
            }
        }
        size_t orow = ((size_t)(b*Sn + s0 + row))*Dn + (size_t)h*DHn;
        #pragma unroll
        for (int j=0;j<4;j++) rd[orow + j*32 + lane] = __float2half_rn(accv[j]);
        __syncwarp();
    }
}

// ---------------- memory-write attention: split-K partials ----------------
__global__ __launch_bounds__(256)
void matt_part_kernel(const __half* __restrict__ qm, const __half* __restrict__ km,
                      const __half* __restrict__ vm,
                      float* __restrict__ pm, float* __restrict__ pl,
                      float* __restrict__ pacc)
{
    extern __shared__ char smraw[];
    __half* Qm = (__half*)smraw;
    __half* Kc = Qm + 64*130;
    __half* VT = Kc + 128*130;
    float*  Ps = (float*)(VT + 128*130);
    __half2* Q2 = (__half2*)Qm;
    __half2* K2 = (__half2*)Kc;
    __half2* V2 = (__half2*)VT;

    int bid = blockIdx.x;
    int ch = bid & (NCH-1);
    int hb = bid >> 3;
    int h = hb % Hn, b = hb / Hn;
    int tid = threadIdx.x, lane = tid & 31, wp = tid >> 5;

    for (int i = tid; i < 64*64; i += 256){
        int r = i >> 6, dc = i & 63;
        Q2[r*65 + dc] = *(const __half2*)(qm + ((size_t)(b*Mn + r))*Dn + h*DHn + dc*2);
    }

    float mrun[8], lrun[8], accv[8][4];
    #pragma unroll
    for (int rr=0;rr<8;rr++){
        mrun[rr] = -1e30f; lrun[rr] = 0.f;
        #pragma unroll
        for (int j=0;j<4;j++) accv[rr][j] = 0.f;
    }

    int cBeg = ch * (Sn / NCH);
    for (int c0 = cBeg; c0 < cBeg + Sn/NCH; c0 += 128){
        __syncthreads();
        for (int i = tid; i < 128*64; i += 256){
            int r = i >> 6, dc = i & 63, d2 = dc*2;
            size_t gidx = ((size_t)(b*Sn + c0 + r))*Dn + h*DHn + d2;
            __half2 k2 = *(const __half2*)(km + gidx);
            __half2 v2 = *(const __half2*)(vm + gidx);
            K2[r*65 + dc] = k2;
            VT[d2*130 + r]     = __low2half(v2);
            VT[(d2+1)*130 + r] = __high2half(v2);
        }
        __syncthreads();

        #pragma unroll 1
        for (int rr=0;rr<8;rr++){
            int row = wp*8 + rr;
            float sc[4] = {0,0,0,0};
            for (int dd = 0; dd < 64; dd++){
                float2 q2 = __half22float2(Q2[row*65 + dd]);
                #pragma unroll
                for (int j=0;j<4;j++){
                    float2 k2 = __half22float2(K2[(j*32+lane)*65 + dd]);
                    sc[j] = fmaf(q2.x, k2.x, sc[j]);
                    sc[j] = fmaf(q2.y, k2.y, sc[j]);
                }
            }
            #pragma unroll
            for (int j=0;j<4;j++) sc[j] *= SCALEn;
            float cm = fmaxf(fmaxf(sc[0],sc[1]), fmaxf(sc[2],sc[3]));
            cm = warpMax(cm);
            float mn = fmaxf(mrun[rr], cm);
            float corr = expf(mrun[rr] - mn);
            float ls = 0.f;
            #pragma unroll
            for (int j=0;j<4;j++){ sc[j] = expf(sc[j]-mn); ls += sc[j]; }
            ls = warpSum(ls);
            lrun[rr] = lrun[rr]*corr + ls;
            mrun[rr] = mn;
            #pragma unroll
            for (int j=0;j<4;j++) accv[rr][j] *= corr;
            #pragma unroll
            for (int j=0;j<4;j++) Ps[wp*128 + j*32 + lane] = sc[j];
            __syncwarp();
            for (int kk=0;kk<64;kk++){
                float p0 = Ps[wp*128 + 2*kk], p1 = Ps[wp*128 + 2*kk + 1];
                #pragma unroll
                for (int j=0;j<4;j++){
                    float2 v2 = __half22float2(V2[(j*32+lane)*65 + kk]);
                    accv[rr][j] = fmaf(p0, v2.x, accv[rr][j]);
                    accv[rr][j] = fmaf(p1, v2.y, accv[rr][j]);
                }
            }
            __syncwarp();
        }
    }

    #pragma unroll
    for (int rr=0;rr<8;rr++){
        int row = wp*8 + rr;
        size_t p = ((size_t)(b*Hn + h)*NCH + ch)*Mn + row;
        if (lane == 0){ pm[p] = mrun[rr]; pl[p] = lrun[rr]; }
        #pragma unroll
        for (int j=0;j<4;j++)
            pacc[p*DHn + j*32 + lane] = accv[rr][j];
    }
}

// ---------------- matt merge ----------------
__global__ __launch_bounds__(256)
void matt_merge_kernel(const float* __restrict__ pm, const float* __restrict__ pl,
                       const float* __restrict__ pacc, __half* __restrict__ wr)
{
    int b = blockIdx.x / Hn, h = blockIdx.x % Hn;
    int tid = threadIdx.x, lane = tid & 31, wp = tid >> 5;
    size_t pb = (size_t)(b*Hn + h)*NCH;

    #pragma unroll 1
    for (int rr=0;rr<8;rr++){
        int row = wp*8 + rr;
        float M = -1e30f;
        float mv[NCH], lv[NCH];
        #pragma unroll
        for (int ccc=0; ccc<NCH; ccc++){
            mv[ccc] = pm[(pb + ccc)*Mn + row];
            lv[ccc] = pl[(pb + ccc)*Mn + row];
            M = fmaxf(M, mv[ccc]);
        }
        float L = 0.f, w[NCH];
        #pragma unroll
        for (int ccc=0; ccc<NCH; ccc++){
            w[ccc] = expf(mv[ccc] - M);
            L += w[ccc]*lv[ccc];
        }
        float invL = 1.f/L;
        #pragma unroll
        for (int j=0;j<4;j++){
            int d = j*32 + lane;
            float s = 0.f;
            #pragma unroll
            for (int ccc=0; ccc<NCH; ccc++)
                s += w[ccc]*pacc[((pb + ccc)*Mn + row)*DHn + d];
            wr[((size_t)(b*Mn + row))*Dn + h*DHn + d] = __float2half_rn(s*invL);
        }
    }
}

// ---------------- pooled mean: two-phase ----------------
__global__ __launch_bounds__(256)
void pooled_part_kernel(const float* __restrict__ gmg, float* __restrict__ pp)
{
    int d = blockIdx.x*256 + threadIdx.x;
    int b = blockIdx.y;
    int z = blockIdx.z;
    const float* p = gmg + (size_t)b*Sn*Dn + (size_t)z*(Sn/PCH)*Dn + d;
    float s = 0.f;
    for (int i=0;i<Sn/PCH;i++) s += p[(size_t)i*Dn];
    pp[((size_t)z*Bn + b)*Dn + d] = s;
}
__global__ __launch_bounds__(256)
void pooled_final_kernel(const float* __restrict__ pp, float* __restrict__ pooled)
{
    int d = blockIdx.x*256 + threadIdx.x;
    int b = blockIdx.y;
    float s = 0.f;
    #pragma unroll
    for (int z=0;z<PCH;z++) s += pp[((size_t)z*Bn + b)*Dn + d];
    pooled[b*Dn + d] = s * (1.0f/Sn);
}

__global__ __launch_bounds__(256)
void state_kernel(const float* __restrict__ pooled, const float* __restrict__ w_cz,
                  const float* __restrict__ w_cg, const float* __restrict__ cs,
                  float* __restrict__ state, float* __restrict__ out_state)
{
    int b = blockIdx.x, c = threadIdx.x;
    const float* pr = pooled + (size_t)b*Dn;
    float z = 0.f, gs = 0.f;
    for (int k=0;k<Dn;k++){
        float p = pr[k];
        z  = fmaf(p, w_cz[(size_t)k*Cn + c], z);
        gs = fmaf(p, w_cg[(size_t)k*Cn + c], gs);
    }
    float zt = tanhf(z);
    float gc = 1.f / (1.f + expf(-gs));
    float ns = gc * cs[b*Cn + c] + (1.f - gc) * zt;
    state[b*Cn + c] = ns;
    out_state[b*Cn + c] = ns;
}

__global__ __launch_bounds__(256)
void sp_kernel(const float* __restrict__ state, const float* __restrict__ w_sp,
               float* __restrict__ sp)
{
    int d = blockIdx.x*256 + threadIdx.x;
    int b = blockIdx.y;
    float s = 0.f;
    for (int c=0;c<Cn;c++) s = fmaf(state[b*Cn+c], w_sp[(size_t)c*Dn + d], s);
    sp[b*Dn + d] = s;
}

__global__ __launch_bounds__(256)
void spbias_kernel(const float* __restrict__ sp, const float* __restrict__ wf2,
                   float* __restrict__ bias)
{
    int n = blockIdx.x*256 + threadIdx.x;
    int b = blockIdx.y;
    const float* sr = sp + (size_t)b*Dn;
    float s = 0.f;
    for (int k=0;k<Dn;k++) s = fmaf(sr[k], wf2[(size_t)k*Dn + n], s);
    bias[b*Dn + n] = s;
}

// ---------------- host orchestration ----------------
#define TG1_128_SMEM (3*(128*144 + TG_B_ARR))      // 110592
#define TG1_64_SMEM  (3*(64*144 + TG_B_ARR))       // 82944
#define TG2_128_SMEM (2*(128*144 + 2*TG_B_ARR))    // 110592

static void tg1(const __half* A, const __half* W,
                float* C, int Mr, int Nc, int ldC, int K,
                int epi, const float* R1, const float* R2, __half* Hout,
                int seg = 0, int ldH = 0)
{
    if (!ldH) ldH = ldC;
    tgemm_kernel<1,128><<<dim3(Nc/128, Mr/128), 256, TG1_128_SMEM>>>(A, W, nullptr, C, ldC, K, epi, R1, R2, Hout, seg, ldH);
}
static void tg1s(const __half* A, const __half* W,       // small-M variant (TM=64)
                 float* C, int Mr, int Nc, int ldC, int K,
                 int epi, const float* R1, const float* R2, __half* Hout,
                 int seg = 0, int ldH = 0)
{
    if (!ldH) ldH = ldC;
    tgemm_kernel<1,64><<<dim3(Nc/128, Mr/64), 256, TG1_64_SMEM>>>(A, W, nullptr, C, ldC, K, epi, R1, R2, Hout, seg, ldH);
}
static void tg2(const __half* A, const __half* Wh, const __half* Wl,
                float* C, int Mr, int Nc, int ldC, int K,
                int epi, const float* R1, const float* R2, __half* Hout,
                int seg = 0, int ldH = 0)
{
    if (!ldH) ldH = ldC;
    tgemm_kernel<2,128><<<dim3(Nc/128, Mr/128), 256, TG2_128_SMEM>>>(A, Wh, Wl, C, ldC, K, epi, R1, R2, Hout, seg, ldH);
}
static void conv(const float* in, __half* hi, size_t n){
    conv_kernel<<<(unsigned)((n+1023)/1024), 256>>>(in, hi, n);
}
static void wconv(const float* W, __half* hi, __half* lo, int K, int N, int ldo = 0){
    if (!ldo) ldo = K;
    wconv_kernel<<<dim3(N/32, K/32), 256>>>(W, hi, lo, K, N, ldo);
}

template <typename T>
static T* sym(const void* symbol){ void* p; cudaGetSymbolAddress(&p, symbol); return (T*)p; }

extern "C" void kernel_launch(void* const* d_in, const int* in_sizes, int n_in,
                              void* d_out, int out_size)
{
    (void)in_sizes; (void)n_in; (void)out_size;
    const float* x      = (const float*)d_in[0];
    const float* gmem   = (const float*)d_in[1];
    const float* cstate = (const float*)d_in[2];
    const float* g1     = (const float*)d_in[3];
    const float* g2     = (const float*)d_in[4];
    const float* g3     = (const float*)d_in[5];
    const float* g4     = (const float*)d_in[6];
    const float* w_qkv  = (const float*)d_in[7];
    const float* w_lo   = (const float*)d_in[8];
    const float* w_gq   = (const float*)d_in[9];
    const float* w_gk   = (const float*)d_in[10];
    const float* w_gv   = (const float*)d_in[11];
    const float* w_go   = (const float*)d_in[12];
    const float* w_gate = (const float*)d_in[13];
    const float* w_mq   = (const float*)d_in[14];
    const float* w_mk   = (const float*)d_in[15];
    const float* w_mv   = (const float*)d_in[16];
    const float* w_mo   = (const float*)d_in[17];
    const float* w_cz   = (const float*)d_in[18];
    const float* w_cg   = (const float*)d_in[19];
    const float* w_sp   = (const float*)d_in[20];
    const float* w_fuse = (const float*)d_in[21];
    const float* w_ff1  = (const float*)d_in[22];
    const float* w_ff2  = (const float*)d_in[23];
    float* out = (float*)d_out;

    float* lcp   = sym<float>(g_lcp);
    float* h2    = sym<float>(g_h2);
    float* gate  = sym<float>(g_gate);
    float* gmgv  = sym<float>(g_gmg);
    float* pool  = sym<float>(g_pool);
    float* pp    = sym<float>(g_pp);
    float* state = sym<float>(g_state);
    float* sp    = sym<float>(g_sp);
    float* bias  = sym<float>(g_bias);
    float* fused = sym<float>(g_fused);
    float* hv    = sym<float>(g_h);
    float* pm    = sym<float>(g_pm);
    float* pl    = sym<float>(g_pl);
    float* pacc  = sym<float>(g_pacc);

    __half* ch1  = sym<__half>(c_h1);
    __half* ch2  = sym<__half>(c_h2);
    __half* cgm  = sym<__half>(c_gm);
    __half* cqkv = sym<__half>(c_qkv);
    __half* cat  = sym<__half>(c_atto);
    __half* cqg  = sym<__half>(c_qg);
    __half* ckvq = sym<__half>(c_kvq);
    __half* ckm  = sym<__half>(c_km);
    __half* cvm  = sym<__half>(c_vm);
    __half* crd  = sym<__half>(c_rd);
    __half* cf01 = sym<__half>(c_f01);
    __half* ch4  = sym<__half>(c_h4);
    __half* cffa = sym<__half>(c_ffa);
    __half* cwr  = sym<__half>(c_wr);
    __half* tqkv = sym<__half>(t_qkv);
    __half* tgq  = sym<__half>(t_gq);
    __half* tmk  = sym<__half>(t_mk);
    __half* tlo  = sym<__half>(t_lo);
    __half* tgt  = sym<__half>(t_gate);
    __half* tgo  = sym<__half>(t_go);
    __half* tmv  = sym<__half>(t_mv);
    __half* tf01 = sym<__half>(t_f01);
    __half* tgm3 = sym<__half>(t_gm3);
    __half* tmo  = sym<__half>(t_mo);
    __half* tff1 = sym<__half>(t_ff1);
    __half* tff2 = sym<__half>(t_ff2);

    const size_t W1 = (size_t)Dn*Dn;
    const size_t WQ = (size_t)3*Dn*Dn;

    const int LATT_SMEM = 3*128*130*2 + 8*128*4;
    const int GATT_SMEM = 2*64*130*2 + 128*66*2 + 8*64*4;
    const int MATT_SMEM = 64*130*2 + 2*128*130*2 + 8*128*4;
    cudaFuncSetAttribute(latt_kernel, cudaFuncAttributeMaxDynamicSharedMemorySize, LATT_SMEM);
    cudaFuncSetAttribute(gatt_kernel, cudaFuncAttributeMaxDynamicSharedMemorySize, GATT_SMEM);
    cudaFuncSetAttribute(matt_part_kernel, cudaFuncAttributeMaxDynamicSharedMemorySize, MATT_SMEM);
    cudaFuncSetAttribute(tgemm_kernel<1,128>, cudaFuncAttributeMaxDynamicSharedMemorySize, TG1_128_SMEM);
    cudaFuncSetAttribute(tgemm_kernel<1,64>,  cudaFuncAttributeMaxDynamicSharedMemorySize, TG1_64_SMEM);
    cudaFuncSetAttribute(tgemm_kernel<2,128>, cudaFuncAttributeMaxDynamicSharedMemorySize, TG2_128_SMEM);

    // ---- front: qkv path first (launch #5 = P1 tgemm) ----
    wconv(w_qkv, tqkv, tqkv + WQ, Dn, 3*Dn);                        // 0
    rmsnorm_kernel<<<ROWS, 256>>>(x, g1, nullptr, ch1, 0);          // 1 (h1 fp32 store dropped)
    wconv(w_lo,  tlo,  nullptr, Dn, Dn);                            // 2
    tg2(ch1, tqkv, tqkv + WQ, nullptr, ROWS, 3*Dn, 3*Dn, Dn, 0, nullptr, nullptr, cqkv); // 3
    latt_kernel<<<Bn*nWn*Hn, 256, LATT_SMEM>>>(cqkv, cat);          // 4
    tg1(cat, tlo, lcp, ROWS, Dn, Dn, Dn, 1, x, nullptr, cf01, 0, 2*Dn); // 5 <- profiled

    // ---- remaining weight converts ----
    wconv(w_gq,   tgq,  tgq + W1, Dn, Dn);
    wconv(w_mk,   tmk,  tmk + W1, Dn, Dn);
    wconv(w_gate, tgt,  nullptr, Dn, Dn);
    wconv(w_go,   tgo,  nullptr, Dn, Dn);
    wconv(w_mv,   tmv,  nullptr, Dn, Dn);
    wconv(w_fuse,      tf01,      nullptr, Dn, Dn, 2*Dn);
    wconv(w_fuse + W1, tf01 + Dn, nullptr, Dn, Dn, 2*Dn);
    wconv(w_gk,   tgm3,          nullptr, Dn, Dn);
    wconv(w_gv,   tgm3 + W1,     nullptr, Dn, Dn);
    wconv(w_mq,   tgm3 + 2*W1,   nullptr, Dn, Dn);
    wconv(w_mo,   tmo,  nullptr, Dn, Dn);
    wconv(w_ff1,  tff1, nullptr, Dn, FFn);
    wconv(w_ff2,  tff2, nullptr, FFn, Dn);
    conv(gmem, cgm, GM_ELEMS);

    // 5) h2 = rmsnorm(lcp, g2)
    rmsnorm_kernel<<<ROWS, 256>>>(lcp, g2, h2, ch2, 0);
    // 6) qg ; batched kg|vg|qm (TM=64 tile: 192 CTAs instead of 48)
    tg2(ch2, tgq, tgq + W1, nullptr, ROWS, Dn, Dn, Dn, 0, nullptr, nullptr, cqg);
    tg1s(cgm, tgm3, nullptr, Bn*Mn, 3*Dn, Dn, Dn, 0, nullptr, nullptr, ckvq, 1);
    // 7) read attention
    gatt_kernel<<<Bn*Hn*(Sn/64), 256, GATT_SMEM>>>(cqg, ckvq, ckvq + GM_ELEMS, crd);
    // 8) gate / gmg (gmg fp16 goes into cf01 cols 2048..4095)
    tg1(ch2, tgt, gate, ROWS, Dn, Dn, Dn, 2, nullptr, nullptr, nullptr);
    tg1(crd, tgo, gmgv, ROWS, Dn, Dn, Dn, 3, h2, gate, cf01 + Dn, 0, 2*Dn);
    // 9) km / vm
    tg2(ch2, tmk, tmk + W1, nullptr, ROWS, Dn, Dn, Dn, 0, nullptr, nullptr, ckm);
    tg1(ch2, tmv, nullptr, ROWS, Dn, Dn, Dn, 0, nullptr, nullptr, cvm);
    // 10) memory-write attention: split-K + merge
    matt_part_kernel<<<Bn*Hn*NCH, 256, MATT_SMEM>>>(ckvq + 2*GM_ELEMS, ckm, cvm, pm, pl, pacc);
    matt_merge_kernel<<<Bn*Hn, 256>>>(pm, pl, pacc, cwr);
    // 11) new_memory (TM=64: 64 CTAs instead of 32)
    tg1s(cwr, tmo, out + OUT_ELEMS, Bn*Mn, Dn, Dn, Dn, 1, gmem, nullptr, nullptr);
    // 12) pooled (two-phase) / state / sp / bias
    pooled_part_kernel<<<dim3(Dn/256, Bn, PCH), 256>>>(gmgv, pp);
    pooled_final_kernel<<<dim3(Dn/256, Bn), 256>>>(pp, pool);
    state_kernel<<<Bn, Cn>>>(pool, w_cz, w_cg, cstate, state, out + OUT_ELEMS + MEM_ELEMS);
    sp_kernel<<<dim3(Dn/256, Bn), 256>>>(state, w_sp, sp);
    spbias_kernel<<<dim3(Dn/256, Bn), 256>>>(sp, w_fuse + (size_t)2*Dn*Dn, bias);
    // 13) fused = [lcp|gmg] @ [Wf0;Wf1] + bias[b]  (single K=4096 GEMM)
    tg1(cf01, tf01, fused, ROWS, Dn, Dn, 2*Dn, 6, bias, nullptr, nullptr);
    // 14) h / h4 fused: hv = fused + norm(fused)*g3 ; ch4 = fp16(norm(hv)*g4)
    rmsnorm2_kernel<<<ROWS, 256>>>(fused, g3, g4, hv, ch4);
    // 15) FFN
    tg1(ch4, tff1, nullptr, ROWS, FFn, FFn, Dn, 4, nullptr, nullptr, cffa);
    tg1(cffa, tff2, out, ROWS, Dn, Dn, FFn, 1, hv, nullptr, nullptr);
}